// round 1
// baseline (speedup 1.0000x reference)
#include <cuda_runtime.h>
#include <math.h>

#define BB 2
#define VV 6
#define CC 256
#define QQ 900
#define KP 4
#define H0 64
#define W0 176
#define H1 32
#define W1 88
#define NH 8
#define HD 32

// ---------------- scratch (device globals; no runtime allocation) ----------------
__device__ float  g_featT0[(size_t)BB*VV*H0*W0*CC];   // [B,V,H,W,C]
__device__ float  g_featT1[(size_t)BB*VV*H1*W1*CC];
__device__ float4 g_proj[BB*VV*QQ*KP];                // (u/z, v/z, valid, pad)
__device__ float  g_sampled[BB*QQ*CC];
__device__ float  g_qp[BB*QQ*CC];
__device__ float  g_kp[BB*QQ*CC];
__device__ float  g_vp[BB*QQ*CC];
__device__ float  g_scores[(size_t)BB*NH*QQ*QQ];
__device__ float  g_attno[BB*QQ*CC];

// ---------------- feature transpose: [bv, C, HW] -> [bv, HW, C] ----------------
__global__ void transpose_kernel(const float* __restrict__ in, float* __restrict__ out, int HW) {
    __shared__ float tile[32][33];
    int bv = blockIdx.z;
    int c0 = blockIdx.y * 32, p0 = blockIdx.x * 32;
    const float* src = in  + (size_t)bv * CC * HW;
    float*       dst = out + (size_t)bv * HW * CC;
    int tx = threadIdx.x, ty = threadIdx.y;
    #pragma unroll
    for (int i = 0; i < 32; i += 8) {
        int c = c0 + ty + i, p = p0 + tx;
        if (c < CC && p < HW) tile[ty + i][tx] = src[(size_t)c * HW + p];
    }
    __syncthreads();
    #pragma unroll
    for (int i = 0; i < 32; i += 8) {
        int p = p0 + ty + i, c = c0 + tx;
        if (p < HW && c < CC) dst[(size_t)p * CC + c] = tile[tx][ty + i];
    }
}

// ---------------- projection: per (b,v,q,k) compute (u/z, v/z, valid) ----------------
__global__ void proj_kernel(const float* __restrict__ refs,
                            const float* __restrict__ intr,
                            const float* __restrict__ extr) {
    int idx = blockIdx.x * 256 + threadIdx.x;
    if (idx >= BB * VV * QQ * KP) return;
    int k = idx & 3;
    int q = (idx >> 2) % QQ;
    int v = (idx / (KP * QQ)) % VV;
    int b = idx / (KP * QQ * VV);
    const float kpx[4] = {0.f, 2.f, 0.f, -2.f};
    const float kpy[4] = {0.f, 0.f, 2.f, 0.f};
    const float* r = refs + (b * QQ + q) * 3;
    float rx = r[0] + kpx[k], ry = r[1] + kpy[k], rz = r[2];
    const float* E = extr + (b * VV + v) * 16;
    float c0 = E[0]*rx + E[1]*ry + E[2]*rz + E[3];
    float c1 = E[4]*rx + E[5]*ry + E[6]*rz + E[7];
    float c2 = E[8]*rx + E[9]*ry + E[10]*rz + E[11];
    const float* I = intr + (b * VV + v) * 9;
    float u = I[0]*c0 + I[1]*c1 + I[2]*c2;
    float w = I[3]*c0 + I[4]*c1 + I[5]*c2;
    float z = I[6]*c0 + I[7]*c1 + I[8]*c2;
    float zs = (fabsf(z) > 1e-6f) ? z : 1e-6f;
    float4 o;
    o.x = u / zs;
    o.y = w / zs;
    o.z = (z > 0.f) ? 1.f : 0.f;
    o.w = 0.f;
    g_proj[idx] = o;
}

// ---------------- bilinear tap on transposed features ----------------
__device__ __forceinline__ float bilin(const float* __restrict__ feat, int bv,
                                       int H, int W, float uz, float vz, int c) {
    // replicate the reference's normalize->unnormalize round trip
    float gx = 2.f * uz / (float)(W - 1) - 1.f;
    float gy = 2.f * vz / (float)(H - 1) - 1.f;
    float x = (gx + 1.f) * 0.5f * (float)(W - 1);
    float y = (gy + 1.f) * 0.5f * (float)(H - 1);
    float x0 = floorf(x), y0 = floorf(y);
    float wx1 = x - x0, wx0 = 1.f - wx1;
    float wy1 = y - y0, wy0 = 1.f - wy1;
    float s = 0.f;
    #pragma unroll
    for (int dy = 0; dy < 2; dy++) {
        #pragma unroll
        for (int dx = 0; dx < 2; dx++) {
            float xf = x0 + (float)dx, yf = y0 + (float)dy;
            if (xf >= 0.f && xf <= (float)(W - 1) && yf >= 0.f && yf <= (float)(H - 1)) {
                int xi = (int)xf, yi = (int)yf;
                float val = feat[(((size_t)bv * H + yi) * W + xi) * CC + c];
                s += ((dx ? wx1 : wx0) * (dy ? wy1 : wy0)) * val;
            }
        }
    }
    return s;
}

// ---------------- sampling: one block per (b,q), threads = channels ----------------
__global__ void sample_kernel() {
    int bq = blockIdx.x;
    int b = bq / QQ, q = bq % QQ;
    int c = threadIdx.x;
    float cnt = 0.f;
    #pragma unroll
    for (int v = 0; v < VV; v++)
        #pragma unroll
        for (int k = 0; k < KP; k++)
            cnt += g_proj[((b * VV + v) * QQ + q) * KP + k].z;
    cnt = fmaxf(cnt, 1.f);
    float acc = 0.f;
    for (int v = 0; v < VV; v++) {
        int bv = b * VV + v;
        #pragma unroll
        for (int k = 0; k < KP; k++) {
            float4 pr = g_proj[((size_t)bv * QQ + q) * KP + k];
            if (pr.z == 0.f) continue;
            acc += bilin(g_featT0, bv, H0, W0, pr.x, pr.y, c);
            acc += bilin(g_featT1, bv, H1, W1, pr.x, pr.y, c);
        }
    }
    g_sampled[((size_t)b * QQ + q) * CC + c] = acc / (2.f * cnt);
}

// ---------------- generic tiled GEMMs ----------------
// C[M,N] = alpha * A[M,K] @ B^T (B is [N,K], K contiguous) + bias
__global__ void gemm_nt(const float* __restrict__ A, const float* __restrict__ B,
                        float* __restrict__ C, const float* __restrict__ bias,
                        int M, int N, int K, int lda, int ldb, int ldc,
                        int zdiv, long sAb, long sAh, long sBb, long sBh,
                        long sCb, long sCh, float alpha) {
    int z = blockIdx.z;
    int zb = z / zdiv, zh = z % zdiv;
    A += zb * sAb + zh * sAh;
    B += zb * sBb + zh * sBh;
    C += zb * sCb + zh * sCh;
    __shared__ float As[16][64];
    __shared__ float Bs[16][64];
    int tid = threadIdx.x;
    int tx = tid & 15, ty = tid >> 4;
    int m0 = blockIdx.y * 64, n0 = blockIdx.x * 64;
    float acc[4][4] = {};
    for (int k0 = 0; k0 < K; k0 += 16) {
        int r = tid >> 2;
        int cg = (tid & 3) * 4;
        #pragma unroll
        for (int j = 0; j < 4; j++) {
            int kk = cg + j;
            int gk = k0 + kk;
            int gm = m0 + r;
            As[kk][r] = (gm < M && gk < K) ? A[(size_t)gm * lda + gk] : 0.f;
            int gn = n0 + r;
            Bs[kk][r] = (gn < N && gk < K) ? B[(size_t)gn * ldb + gk] : 0.f;
        }
        __syncthreads();
        #pragma unroll
        for (int kk = 0; kk < 16; kk++) {
            float4 a4 = *(const float4*)&As[kk][ty * 4];
            float4 b4 = *(const float4*)&Bs[kk][tx * 4];
            float a[4] = {a4.x, a4.y, a4.z, a4.w};
            float bb[4] = {b4.x, b4.y, b4.z, b4.w};
            #pragma unroll
            for (int i = 0; i < 4; i++)
                #pragma unroll
                for (int j = 0; j < 4; j++)
                    acc[i][j] += a[i] * bb[j];
        }
        __syncthreads();
    }
    #pragma unroll
    for (int i = 0; i < 4; i++) {
        int gm = m0 + ty * 4 + i;
        if (gm >= M) continue;
        #pragma unroll
        for (int j = 0; j < 4; j++) {
            int gn = n0 + tx * 4 + j;
            if (gn >= N) continue;
            float val = acc[i][j] * alpha;
            if (bias) val += bias[gn];
            C[(size_t)gm * ldc + gn] = val;
        }
    }
}

// C[M,N] = alpha * A[M,K] @ B  (B is [K,N], N contiguous)
__global__ void gemm_nn(const float* __restrict__ A, const float* __restrict__ B,
                        float* __restrict__ C, const float* __restrict__ bias,
                        int M, int N, int K, int lda, int ldb, int ldc,
                        int zdiv, long sAb, long sAh, long sBb, long sBh,
                        long sCb, long sCh, float alpha) {
    int z = blockIdx.z;
    int zb = z / zdiv, zh = z % zdiv;
    A += zb * sAb + zh * sAh;
    B += zb * sBb + zh * sBh;
    C += zb * sCb + zh * sCh;
    __shared__ float As[16][64];
    __shared__ float Bs[16][64];
    int tid = threadIdx.x;
    int tx = tid & 15, ty = tid >> 4;
    int m0 = blockIdx.y * 64, n0 = blockIdx.x * 64;
    float acc[4][4] = {};
    for (int k0 = 0; k0 < K; k0 += 16) {
        {   // A tile: [64 rows][16 k], K contiguous
            int r = tid >> 2;
            int cg = (tid & 3) * 4;
            #pragma unroll
            for (int j = 0; j < 4; j++) {
                int kk = cg + j;
                int gk = k0 + kk;
                int gm = m0 + r;
                As[kk][r] = (gm < M && gk < K) ? A[(size_t)gm * lda + gk] : 0.f;
            }
        }
        {   // B tile: [16 k][64 n], N contiguous -> coalesced
            int col = tid & 63;
            int kr = tid >> 6;   // 0..3
            #pragma unroll
            for (int j = 0; j < 4; j++) {
                int kk = kr * 4 + j;
                int gk = k0 + kk;
                int gn = n0 + col;
                Bs[kk][col] = (gk < K && gn < N) ? B[(size_t)gk * ldb + gn] : 0.f;
            }
        }
        __syncthreads();
        #pragma unroll
        for (int kk = 0; kk < 16; kk++) {
            float4 a4 = *(const float4*)&As[kk][ty * 4];
            float4 b4 = *(const float4*)&Bs[kk][tx * 4];
            float a[4] = {a4.x, a4.y, a4.z, a4.w};
            float bb[4] = {b4.x, b4.y, b4.z, b4.w};
            #pragma unroll
            for (int i = 0; i < 4; i++)
                #pragma unroll
                for (int j = 0; j < 4; j++)
                    acc[i][j] += a[i] * bb[j];
        }
        __syncthreads();
    }
    #pragma unroll
    for (int i = 0; i < 4; i++) {
        int gm = m0 + ty * 4 + i;
        if (gm >= M) continue;
        #pragma unroll
        for (int j = 0; j < 4; j++) {
            int gn = n0 + tx * 4 + j;
            if (gn >= N) continue;
            float val = acc[i][j] * alpha;
            if (bias) val += bias[gn];
            C[(size_t)gm * ldc + gn] = val;
        }
    }
}

// ---------------- row softmax over 900 elems, one block per row ----------------
__global__ void softmax_kernel(float* __restrict__ S) {
    float* p = S + (size_t)blockIdx.x * QQ;
    int tid = threadIdx.x;
    __shared__ float red[256];
    float m = -1e30f;
    for (int j = tid; j < QQ; j += 256) m = fmaxf(m, p[j]);
    red[tid] = m; __syncthreads();
    for (int s = 128; s > 0; s >>= 1) { if (tid < s) red[tid] = fmaxf(red[tid], red[tid + s]); __syncthreads(); }
    m = red[0]; __syncthreads();
    float sum = 0.f;
    for (int j = tid; j < QQ; j += 256) { float e = expf(p[j] - m); p[j] = e; sum += e; }
    red[tid] = sum; __syncthreads();
    for (int s = 128; s > 0; s >>= 1) { if (tid < s) red[tid] += red[tid + s]; __syncthreads(); }
    float inv = 1.f / red[0];
    for (int j = tid; j < QQ; j += 256) p[j] *= inv;
}

// ---------------- host launcher ----------------
extern "C" void kernel_launch(void* const* d_in, const int* in_sizes, int n_in,
                              void* d_out, int out_size) {
    const float* f0   = (const float*)d_in[0];
    const float* f1   = (const float*)d_in[1];
    const float* refs = (const float*)d_in[2];
    const float* intr = (const float*)d_in[3];
    const float* extr = (const float*)d_in[4];
    const float* qry  = (const float*)d_in[5];
    const float* Wq   = (const float*)d_in[6];
    const float* bq   = (const float*)d_in[7];
    const float* Wk   = (const float*)d_in[8];
    const float* bk   = (const float*)d_in[9];
    const float* Wv   = (const float*)d_in[10];
    const float* bv   = (const float*)d_in[11];
    const float* Wo   = (const float*)d_in[12];
    const float* bo   = (const float*)d_in[13];
    float* out = (float*)d_out;

    float *featT0, *featT1, *sampled, *qp, *kp, *vp, *scores, *attno;
    cudaGetSymbolAddress((void**)&featT0, g_featT0);
    cudaGetSymbolAddress((void**)&featT1, g_featT1);
    cudaGetSymbolAddress((void**)&sampled, g_sampled);
    cudaGetSymbolAddress((void**)&qp, g_qp);
    cudaGetSymbolAddress((void**)&kp, g_kp);
    cudaGetSymbolAddress((void**)&vp, g_vp);
    cudaGetSymbolAddress((void**)&scores, g_scores);
    cudaGetSymbolAddress((void**)&attno, g_attno);

    dim3 tt(32, 8);
    transpose_kernel<<<dim3((H0 * W0) / 32, CC / 32, BB * VV), tt>>>(f0, featT0, H0 * W0);
    transpose_kernel<<<dim3((H1 * W1) / 32, CC / 32, BB * VV), tt>>>(f1, featT1, H1 * W1);
    proj_kernel<<<(BB * VV * QQ * KP + 255) / 256, 256>>>(refs, intr, extr);
    sample_kernel<<<BB * QQ, CC>>>();

    const int M = BB * QQ;  // 1800
    dim3 gproj((CC + 63) / 64, (M + 63) / 64, 1);
    gemm_nt<<<gproj, 256>>>(qry, Wq, qp, bq, M, CC, CC, CC, CC, CC,
                            1, 0, 0, 0, 0, 0, 0, 1.f);
    gemm_nt<<<gproj, 256>>>(sampled, Wk, kp, bk, M, CC, CC, CC, CC, CC,
                            1, 0, 0, 0, 0, 0, 0, 1.f);
    gemm_nt<<<gproj, 256>>>(sampled, Wv, vp, bv, M, CC, CC, CC, CC, CC,
                            1, 0, 0, 0, 0, 0, 0, 1.f);

    // scores[b,h] = (Qh @ Kh^T) / sqrt(HD)
    dim3 gsc((QQ + 63) / 64, (QQ + 63) / 64, BB * NH);
    gemm_nt<<<gsc, 256>>>(qp, kp, scores, nullptr, QQ, QQ, HD, CC, CC, QQ,
                          NH, (long)QQ * CC, HD, (long)QQ * CC, HD,
                          (long)NH * QQ * QQ, (long)QQ * QQ, 0.1767766952966369f);

    softmax_kernel<<<BB * NH * QQ, 256>>>(scores);

    // O[b,h] = P @ Vh  -> written into [B,Q,C] interleaved per head
    dim3 gpv((HD + 63) / 64, (QQ + 63) / 64, BB * NH);
    gemm_nn<<<gpv, 256>>>(scores, vp, attno, nullptr, QQ, HD, QQ, QQ, CC, CC,
                          NH, (long)NH * QQ * QQ, (long)QQ * QQ,
                          (long)QQ * CC, HD, (long)QQ * CC, HD, 1.f);

    // final projection -> d_out
    gemm_nt<<<gproj, 256>>>(attno, Wo, out, bo, M, CC, CC, CC, CC, CC,
                            1, 0, 0, 0, 0, 0, 0, 1.f);
}

// round 2
// speedup vs baseline: 1.2591x; 1.2591x over previous
#include <cuda_runtime.h>
#include <math.h>
#include <stdint.h>

#define BB 2
#define VV 6
#define CC 256
#define QQ 900
#define KP 4
#define H0 64
#define W0 176
#define H1 32
#define W1 88
#define NH 8
#define HD 32

// ---------------- scratch (device globals; no runtime allocation) ----------------
__device__ float  g_featT0[(size_t)BB*VV*H0*W0*CC];   // [B,V,H,W,C]
__device__ float  g_featT1[(size_t)BB*VV*H1*W1*CC];
__device__ float4 g_proj[BB*VV*QQ*KP];                // (u/z, v/z, valid, pad)
__device__ float  g_sampled[BB*QQ*CC];
__device__ float  g_qp[BB*QQ*CC];
__device__ float  g_kp[BB*QQ*CC];
__device__ float  g_vp[BB*QQ*CC];
__device__ float  g_scores[(size_t)BB*NH*QQ*QQ];
__device__ float  g_attno[BB*QQ*CC];

// ---------------- feature transpose: [bv, C, HW] -> [bv, HW, C] ----------------
__global__ void transpose_kernel(const float* __restrict__ in, float* __restrict__ out, int HW) {
    __shared__ float tile[32][33];
    int bv = blockIdx.z;
    int c0 = blockIdx.y * 32, p0 = blockIdx.x * 32;
    const float* src = in  + (size_t)bv * CC * HW;
    float*       dst = out + (size_t)bv * HW * CC;
    int tx = threadIdx.x, ty = threadIdx.y;
    #pragma unroll
    for (int i = 0; i < 32; i += 8) {
        int c = c0 + ty + i, p = p0 + tx;
        if (c < CC && p < HW) tile[ty + i][tx] = src[(size_t)c * HW + p];
    }
    __syncthreads();
    #pragma unroll
    for (int i = 0; i < 32; i += 8) {
        int p = p0 + ty + i, c = c0 + tx;
        if (p < HW && c < CC) dst[(size_t)p * CC + c] = tile[tx][ty + i];
    }
}

// ---------------- projection: per (b,v,q,k) compute (u/z, v/z, valid) ----------------
__global__ void proj_kernel(const float* __restrict__ refs,
                            const float* __restrict__ intr,
                            const float* __restrict__ extr) {
    int idx = blockIdx.x * 256 + threadIdx.x;
    if (idx >= BB * VV * QQ * KP) return;
    int k = idx & 3;
    int q = (idx >> 2) % QQ;
    int v = (idx / (KP * QQ)) % VV;
    int b = idx / (KP * QQ * VV);
    const float kpx[4] = {0.f, 2.f, 0.f, -2.f};
    const float kpy[4] = {0.f, 0.f, 2.f, 0.f};
    const float* r = refs + (b * QQ + q) * 3;
    float rx = r[0] + kpx[k], ry = r[1] + kpy[k], rz = r[2];
    const float* E = extr + (b * VV + v) * 16;
    float c0 = E[0]*rx + E[1]*ry + E[2]*rz + E[3];
    float c1 = E[4]*rx + E[5]*ry + E[6]*rz + E[7];
    float c2 = E[8]*rx + E[9]*ry + E[10]*rz + E[11];
    const float* I = intr + (b * VV + v) * 9;
    float u = I[0]*c0 + I[1]*c1 + I[2]*c2;
    float w = I[3]*c0 + I[4]*c1 + I[5]*c2;
    float z = I[6]*c0 + I[7]*c1 + I[8]*c2;
    float zs = (fabsf(z) > 1e-6f) ? z : 1e-6f;
    float4 o;
    o.x = u / zs;
    o.y = w / zs;
    o.z = (z > 0.f) ? 1.f : 0.f;
    o.w = 0.f;
    g_proj[idx] = o;
}

// ---------------- sampling: tap geometry precomputed once per (b,q) block ----------------
__global__ void sample_kernel() {
    __shared__ float        s_w[48][4];
    __shared__ const float* s_p[48][4];
    __shared__ int          s_valid[48];
    __shared__ float        s_cnt;
    int bq = blockIdx.x;
    int b = bq / QQ, q = bq % QQ;
    int tid = threadIdx.x;

    if (tid < 48) {
        int level = tid / 24, r = tid % 24, v = r >> 2, k = r & 3;
        int bv = b * VV + v;
        float4 pr = g_proj[((size_t)(b * VV + v) * QQ + q) * KP + k];
        int H = level ? H1 : H0, W = level ? W1 : W0;
        const float* base = level ? g_featT1 : g_featT0;
        s_valid[tid] = (pr.z != 0.f);
        // replicate reference's normalize -> unnormalize round trip exactly
        float gx = 2.f * pr.x / (float)(W - 1) - 1.f;
        float gy = 2.f * pr.y / (float)(H - 1) - 1.f;
        float x = (gx + 1.f) * 0.5f * (float)(W - 1);
        float y = (gy + 1.f) * 0.5f * (float)(H - 1);
        float x0f = floorf(x), y0f = floorf(y);
        float wx1 = x - x0f, wx0 = 1.f - wx1;
        float wy1 = y - y0f, wy0 = 1.f - wy1;
        #pragma unroll
        for (int c4 = 0; c4 < 4; c4++) {
            int dx = c4 & 1, dy = c4 >> 1;
            float xf = x0f + (float)dx, yf = y0f + (float)dy;
            bool inb = (xf >= 0.f) && (xf <= (float)(W - 1)) && (yf >= 0.f) && (yf <= (float)(H - 1));
            int xi = min(max((int)xf, 0), W - 1);
            int yi = min(max((int)yf, 0), H - 1);
            s_w[tid][c4] = inb ? (dx ? wx1 : wx0) * (dy ? wy1 : wy0) : 0.f;
            s_p[tid][c4] = base + (((size_t)bv * H + yi) * W + xi) * CC;
        }
    }
    __syncthreads();
    if (tid == 0) {
        float c = 0.f;
        for (int t = 0; t < 24; t++) c += s_valid[t] ? 1.f : 0.f;
        s_cnt = fmaxf(c, 1.f);
    }
    __syncthreads();

    int c = tid;
    float acc = 0.f;
    #pragma unroll 4
    for (int t = 0; t < 48; t++) {
        if (!s_valid[t]) continue;
        acc = fmaf(s_w[t][0], s_p[t][0][c], acc);
        acc = fmaf(s_w[t][1], s_p[t][1][c], acc);
        acc = fmaf(s_w[t][2], s_p[t][2][c], acc);
        acc = fmaf(s_w[t][3], s_p[t][3][c], acc);
    }
    g_sampled[((size_t)b * QQ + q) * CC + c] = acc / (2.f * s_cnt);
}

// ---------------- TF32 mma.sync GEMM core ----------------
__device__ __forceinline__ uint32_t f2tf(float x) {
    uint32_t r;
    asm("cvt.rna.tf32.f32 %0, %1;" : "=r"(r) : "f"(x));
    return r;
}

__device__ __forceinline__ void mma8(float* c, const uint32_t* a, const uint32_t* b) {
    asm volatile(
        "mma.sync.aligned.m16n8k8.row.col.f32.tf32.tf32.f32 "
        "{%0,%1,%2,%3},{%4,%5,%6,%7},{%8,%9},{%0,%1,%2,%3};\n"
        : "+f"(c[0]), "+f"(c[1]), "+f"(c[2]), "+f"(c[3])
        : "r"(a[0]), "r"(a[1]), "r"(a[2]), "r"(a[3]), "r"(b[0]), "r"(b[1]));
}

// C[M,N] = alpha * A[M,K] @ op(B) + bias.
// TRANSB=1: B is [N,K] row-major (element (k,n) at B[n*ldb+k]).
// TRANSB=0: B is [K,N] row-major (element (k,n) at B[k*ldb+n]).
// Block tile 128x64, BK=32, 256 threads (8 warps, each 32x32).
template<bool TRANSB>
__device__ __forceinline__ void gemm_body(
    const float* __restrict__ A, const float* __restrict__ B,
    float* __restrict__ C, const float* __restrict__ bias,
    int M, int N, int K, int lda, int ldb, int ldc, float alpha)
{
    __shared__ uint32_t As[128][36];
    __shared__ uint32_t Bs[32][72];
    int tid = threadIdx.x;
    int warp = tid >> 5, lane = tid & 31;
    int g = lane >> 2, tg = lane & 3;
    int wm0 = (warp >> 1) * 32, wn0 = (warp & 1) * 32;
    int m0 = blockIdx.y * 128, n0 = blockIdx.x * 64;
    float acc[2][4][4] = {};

    for (int k0 = 0; k0 < K; k0 += 32) {
        #pragma unroll
        for (int i = 0; i < 4; i++) {
            int lin = tid + i * 256;
            int row = lin >> 3, c4 = lin & 7;
            int gm = m0 + row, gk = k0 + c4 * 4;
            float4 v = make_float4(0.f, 0.f, 0.f, 0.f);
            if (gm < M && gk + 4 <= K)
                v = *(const float4*)(A + (size_t)gm * lda + gk);
            As[row][c4 * 4 + 0] = f2tf(v.x);
            As[row][c4 * 4 + 1] = f2tf(v.y);
            As[row][c4 * 4 + 2] = f2tf(v.z);
            As[row][c4 * 4 + 3] = f2tf(v.w);
        }
        #pragma unroll
        for (int i = 0; i < 2; i++) {
            int lin = tid + i * 256;
            if (TRANSB) {
                int n = lin >> 3, c4 = lin & 7;
                int gn = n0 + n, gk = k0 + c4 * 4;
                float4 v = make_float4(0.f, 0.f, 0.f, 0.f);
                if (gn < N && gk + 4 <= K)
                    v = *(const float4*)(B + (size_t)gn * ldb + gk);
                Bs[c4 * 4 + 0][n] = f2tf(v.x);
                Bs[c4 * 4 + 1][n] = f2tf(v.y);
                Bs[c4 * 4 + 2][n] = f2tf(v.z);
                Bs[c4 * 4 + 3][n] = f2tf(v.w);
            } else {
                int kk = lin >> 4, c4 = lin & 15;
                int gk = k0 + kk, gn = n0 + c4 * 4;
                float4 v = make_float4(0.f, 0.f, 0.f, 0.f);
                if (gk < K && gn + 4 <= N)
                    v = *(const float4*)(B + (size_t)gk * ldb + gn);
                Bs[kk][c4 * 4 + 0] = f2tf(v.x);
                Bs[kk][c4 * 4 + 1] = f2tf(v.y);
                Bs[kk][c4 * 4 + 2] = f2tf(v.z);
                Bs[kk][c4 * 4 + 3] = f2tf(v.w);
            }
        }
        __syncthreads();
        #pragma unroll
        for (int kk = 0; kk < 32; kk += 8) {
            uint32_t a[2][4], bfr[4][2];
            #pragma unroll
            for (int mi = 0; mi < 2; mi++) {
                int r = wm0 + mi * 16 + g;
                a[mi][0] = As[r][kk + tg];
                a[mi][1] = As[r + 8][kk + tg];
                a[mi][2] = As[r][kk + tg + 4];
                a[mi][3] = As[r + 8][kk + tg + 4];
            }
            #pragma unroll
            for (int ni = 0; ni < 4; ni++) {
                int cn = wn0 + ni * 8 + g;
                bfr[ni][0] = Bs[kk + tg][cn];
                bfr[ni][1] = Bs[kk + tg + 4][cn];
            }
            #pragma unroll
            for (int mi = 0; mi < 2; mi++)
                #pragma unroll
                for (int ni = 0; ni < 4; ni++)
                    mma8(acc[mi][ni], a[mi], bfr[ni]);
        }
        __syncthreads();
    }

    #pragma unroll
    for (int mi = 0; mi < 2; mi++) {
        #pragma unroll
        for (int ni = 0; ni < 4; ni++) {
            int r0 = m0 + wm0 + mi * 16 + g;
            int cc0 = n0 + wn0 + ni * 8 + tg * 2;
            #pragma unroll
            for (int e = 0; e < 4; e++) {
                int r = r0 + (e >> 1) * 8;
                int cn = cc0 + (e & 1);
                if (r < M && cn < N) {
                    float val = acc[mi][ni][e] * alpha;
                    if (bias) val += bias[cn];
                    C[(size_t)r * ldc + cn] = val;
                }
            }
        }
    }
}

template<bool TRANSB>
__global__ void gemm_k(const float* __restrict__ A, const float* __restrict__ B,
                       float* __restrict__ C, const float* __restrict__ bias,
                       int M, int N, int K, int lda, int ldb, int ldc,
                       int zdiv, long sAb, long sAh, long sBb, long sBh,
                       long sCb, long sCh, float alpha) {
    int z = blockIdx.z;
    int zb = z / zdiv, zh = z % zdiv;
    gemm_body<TRANSB>(A + zb * sAb + zh * sAh, B + zb * sBb + zh * sBh,
                      C + zb * sCb + zh * sCh, bias,
                      M, N, K, lda, ldb, ldc, alpha);
}

// batched q/k/v projections in one launch (z selects which)
__global__ void gemm_qkv(const float* __restrict__ qry, const float* __restrict__ sampled,
                         const float* __restrict__ Wq, const float* __restrict__ Wk,
                         const float* __restrict__ Wv,
                         const float* __restrict__ bq, const float* __restrict__ bk,
                         const float* __restrict__ bv,
                         float* __restrict__ qp, float* __restrict__ kp, float* __restrict__ vp) {
    int z = blockIdx.z;
    const float* A = (z == 0) ? qry : sampled;
    const float* B = (z == 0) ? Wq : ((z == 1) ? Wk : Wv);
    const float* bi = (z == 0) ? bq : ((z == 1) ? bk : bv);
    float* C = (z == 0) ? qp : ((z == 1) ? kp : vp);
    gemm_body<true>(A, B, C, bi, BB * QQ, CC, CC, CC, CC, CC, 1.f);
}

// ---------------- row softmax over 900 elems, one block per row ----------------
__global__ void softmax_kernel(float* __restrict__ S) {
    float* p = S + (size_t)blockIdx.x * QQ;
    int tid = threadIdx.x;
    __shared__ float red[256];
    float m = -1e30f;
    for (int j = tid; j < QQ; j += 256) m = fmaxf(m, p[j]);
    red[tid] = m; __syncthreads();
    for (int s = 128; s > 0; s >>= 1) { if (tid < s) red[tid] = fmaxf(red[tid], red[tid + s]); __syncthreads(); }
    m = red[0]; __syncthreads();
    float sum = 0.f;
    for (int j = tid; j < QQ; j += 256) { float e = expf(p[j] - m); p[j] = e; sum += e; }
    red[tid] = sum; __syncthreads();
    for (int s = 128; s > 0; s >>= 1) { if (tid < s) red[tid] += red[tid + s]; __syncthreads(); }
    float inv = 1.f / red[0];
    for (int j = tid; j < QQ; j += 256) p[j] *= inv;
}

// ---------------- host launcher ----------------
extern "C" void kernel_launch(void* const* d_in, const int* in_sizes, int n_in,
                              void* d_out, int out_size) {
    const float* f0   = (const float*)d_in[0];
    const float* f1   = (const float*)d_in[1];
    const float* refs = (const float*)d_in[2];
    const float* intr = (const float*)d_in[3];
    const float* extr = (const float*)d_in[4];
    const float* qry  = (const float*)d_in[5];
    const float* Wq   = (const float*)d_in[6];
    const float* bq   = (const float*)d_in[7];
    const float* Wk   = (const float*)d_in[8];
    const float* bk   = (const float*)d_in[9];
    const float* Wv   = (const float*)d_in[10];
    const float* bv   = (const float*)d_in[11];
    const float* Wo   = (const float*)d_in[12];
    const float* bo   = (const float*)d_in[13];
    float* out = (float*)d_out;

    float *featT0, *featT1, *sampled, *qp, *kp, *vp, *scores, *attno;
    cudaGetSymbolAddress((void**)&featT0, g_featT0);
    cudaGetSymbolAddress((void**)&featT1, g_featT1);
    cudaGetSymbolAddress((void**)&sampled, g_sampled);
    cudaGetSymbolAddress((void**)&qp, g_qp);
    cudaGetSymbolAddress((void**)&kp, g_kp);
    cudaGetSymbolAddress((void**)&vp, g_vp);
    cudaGetSymbolAddress((void**)&scores, g_scores);
    cudaGetSymbolAddress((void**)&attno, g_attno);

    dim3 tt(32, 8);
    transpose_kernel<<<dim3((H0 * W0) / 32, CC / 32, BB * VV), tt>>>(f0, featT0, H0 * W0);
    transpose_kernel<<<dim3((H1 * W1) / 32, CC / 32, BB * VV), tt>>>(f1, featT1, H1 * W1);
    proj_kernel<<<(BB * VV * QQ * KP + 255) / 256, 256>>>(refs, intr, extr);
    sample_kernel<<<BB * QQ, CC>>>();

    const int M = BB * QQ;  // 1800
    // q/k/v projections batched: grid (N/64, ceil(M/128), 3)
    gemm_qkv<<<dim3(CC / 64, (M + 127) / 128, 3), 256>>>(
        qry, sampled, Wq, Wk, Wv, bq, bk, bv, qp, kp, vp);

    // scores[b,h] = (Qh @ Kh^T) / sqrt(HD)
    gemm_k<true><<<dim3((QQ + 63) / 64, (QQ + 127) / 128, BB * NH), 256>>>(
        qp, kp, scores, nullptr, QQ, QQ, HD, CC, CC, QQ,
        NH, (long)QQ * CC, HD, (long)QQ * CC, HD,
        (long)NH * QQ * QQ, (long)QQ * QQ, 0.1767766952966369f);

    softmax_kernel<<<BB * NH * QQ, 256>>>(scores);

    // O[b,h] = P @ Vh  (nn)
    gemm_k<false><<<dim3(1, (QQ + 127) / 128, BB * NH), 256>>>(
        scores, vp, attno, nullptr, QQ, HD, QQ, QQ, CC, CC,
        NH, (long)NH * QQ * QQ, (long)QQ * QQ,
        (long)QQ * CC, HD, (long)QQ * CC, HD, 1.f);

    // final projection -> d_out
    gemm_k<true><<<dim3(CC / 64, (M + 127) / 128, 1), 256>>>(
        attno, Wo, out, bo, M, CC, CC, CC, CC, CC,
        1, 0, 0, 0, 0, 0, 0, 1.f);
}

// round 4
// speedup vs baseline: 2.1351x; 1.6958x over previous
#include <cuda_runtime.h>
#include <math.h>
#include <stdint.h>

#define BB 2
#define VV 6
#define CC 256
#define QQ 900
#define KP 4
#define H0 64
#define W0 176
#define H1 32
#define W1 88
#define NH 8
#define HD 32
#define ATT_SCALE 0.17677669529663689f

// ---------------- scratch (device globals; no runtime allocation) ----------------
__device__ float  g_featT0[(size_t)BB*VV*H0*W0*CC];   // [B,V,H,W,C]
__device__ float  g_featT1[(size_t)BB*VV*H1*W1*CC];
__device__ float4 g_proj[BB*VV*QQ*KP];                // (u/z, v/z, valid, pad)
__device__ float  g_sampled[BB*QQ*CC];
__device__ float  g_qp[BB*QQ*CC];
__device__ float  g_kp[BB*QQ*CC];
__device__ float  g_vp[BB*QQ*CC];
__device__ float  g_attno[BB*QQ*CC];

// ---------------- feature transpose: [bv, C, HW] -> [bv, HW, C] ----------------
__global__ void transpose_kernel(const float* __restrict__ in, float* __restrict__ out, int HW) {
    __shared__ float tile[32][33];
    int bv = blockIdx.z;
    int c0 = blockIdx.y * 32, p0 = blockIdx.x * 32;
    const float* src = in  + (size_t)bv * CC * HW;
    float*       dst = out + (size_t)bv * HW * CC;
    int tx = threadIdx.x, ty = threadIdx.y;
    #pragma unroll
    for (int i = 0; i < 32; i += 8) {
        int c = c0 + ty + i, p = p0 + tx;
        if (c < CC && p < HW) tile[ty + i][tx] = src[(size_t)c * HW + p];
    }
    __syncthreads();
    #pragma unroll
    for (int i = 0; i < 32; i += 8) {
        int p = p0 + ty + i, c = c0 + tx;
        if (p < HW && c < CC) dst[(size_t)p * CC + c] = tile[tx][ty + i];
    }
}

// ---------------- projection ----------------
__global__ void proj_kernel(const float* __restrict__ refs,
                            const float* __restrict__ intr,
                            const float* __restrict__ extr) {
    int idx = blockIdx.x * 256 + threadIdx.x;
    if (idx >= BB * VV * QQ * KP) return;
    int k = idx & 3;
    int q = (idx >> 2) % QQ;
    int v = (idx / (KP * QQ)) % VV;
    int b = idx / (KP * QQ * VV);
    const float kpx[4] = {0.f, 2.f, 0.f, -2.f};
    const float kpy[4] = {0.f, 0.f, 2.f, 0.f};
    const float* r = refs + (b * QQ + q) * 3;
    float rx = r[0] + kpx[k], ry = r[1] + kpy[k], rz = r[2];
    const float* E = extr + (b * VV + v) * 16;
    float c0 = E[0]*rx + E[1]*ry + E[2]*rz + E[3];
    float c1 = E[4]*rx + E[5]*ry + E[6]*rz + E[7];
    float c2 = E[8]*rx + E[9]*ry + E[10]*rz + E[11];
    const float* I = intr + (b * VV + v) * 9;
    float u = I[0]*c0 + I[1]*c1 + I[2]*c2;
    float w = I[3]*c0 + I[4]*c1 + I[5]*c2;
    float z = I[6]*c0 + I[7]*c1 + I[8]*c2;
    float zs = (fabsf(z) > 1e-6f) ? z : 1e-6f;
    float4 o;
    o.x = u / zs;
    o.y = w / zs;
    o.z = (z > 0.f) ? 1.f : 0.f;
    o.w = 0.f;
    g_proj[idx] = o;
}

// ---------------- sampling: 4 queries/block, float4 channels ----------------
__global__ void sample_kernel() {
    __shared__ float        s_w[4][48][4];
    __shared__ const float* s_p[4][48][4];
    __shared__ int          s_valid[4][48];
    __shared__ float        s_cnt[4];
    int tid = threadIdx.y * 64 + threadIdx.x;
    int bq0 = blockIdx.x * 4;

    if (tid < 192) {
        int qy = tid / 48, t = tid % 48;
        int bq = bq0 + qy;
        int b = bq / QQ, q = bq % QQ;
        int level = t / 24, r = t % 24, v = r >> 2, k = r & 3;
        int bv = b * VV + v;
        float4 pr = g_proj[((size_t)bv * QQ + q) * KP + k];
        int H = level ? H1 : H0, W = level ? W1 : W0;
        const float* base = level ? g_featT1 : g_featT0;
        s_valid[qy][t] = (pr.z != 0.f);
        float gx = 2.f * pr.x / (float)(W - 1) - 1.f;
        float gy = 2.f * pr.y / (float)(H - 1) - 1.f;
        float x = (gx + 1.f) * 0.5f * (float)(W - 1);
        float y = (gy + 1.f) * 0.5f * (float)(H - 1);
        float x0f = floorf(x), y0f = floorf(y);
        float wx1 = x - x0f, wx0 = 1.f - wx1;
        float wy1 = y - y0f, wy0 = 1.f - wy1;
        #pragma unroll
        for (int c4 = 0; c4 < 4; c4++) {
            int dx = c4 & 1, dy = c4 >> 1;
            float xf = x0f + (float)dx, yf = y0f + (float)dy;
            bool inb = (xf >= 0.f) && (xf <= (float)(W - 1)) && (yf >= 0.f) && (yf <= (float)(H - 1));
            int xi = min(max((int)xf, 0), W - 1);
            int yi = min(max((int)yf, 0), H - 1);
            s_w[qy][t][c4] = inb ? (dx ? wx1 : wx0) * (dy ? wy1 : wy0) : 0.f;
            s_p[qy][t][c4] = base + (((size_t)bv * H + yi) * W + xi) * CC;
        }
    }
    __syncthreads();
    if (tid < 4) {
        float c = 0.f;
        for (int t = 0; t < 24; t++) c += s_valid[tid][t] ? 1.f : 0.f;
        s_cnt[tid] = 0.5f / fmaxf(c, 1.f);
    }
    __syncthreads();

    int qy = threadIdx.y, c = threadIdx.x * 4;
    float4 acc = make_float4(0.f, 0.f, 0.f, 0.f);
    #pragma unroll 4
    for (int t = 0; t < 48; t++) {
        if (!s_valid[qy][t]) continue;
        #pragma unroll
        for (int j = 0; j < 4; j++) {
            float w = s_w[qy][t][j];
            float4 v = *(const float4*)(s_p[qy][t][j] + c);
            acc.x = fmaf(w, v.x, acc.x);
            acc.y = fmaf(w, v.y, acc.y);
            acc.z = fmaf(w, v.z, acc.z);
            acc.w = fmaf(w, v.w, acc.w);
        }
    }
    float sc = s_cnt[qy];
    int bq = bq0 + qy;
    *(float4*)(g_sampled + (size_t)bq * CC + c) =
        make_float4(acc.x * sc, acc.y * sc, acc.z * sc, acc.w * sc);
}

// ---------------- TF32 mma helpers ----------------
__device__ __forceinline__ uint32_t f2tf(float x) {
    uint32_t r;
    asm("cvt.rna.tf32.f32 %0, %1;" : "=r"(r) : "f"(x));
    return r;
}

__device__ __forceinline__ void mma8(float* c, const uint32_t* a, const uint32_t* b) {
    asm volatile(
        "mma.sync.aligned.m16n8k8.row.col.f32.tf32.tf32.f32 "
        "{%0,%1,%2,%3},{%4,%5,%6,%7},{%8,%9},{%0,%1,%2,%3};\n"
        : "+f"(c[0]), "+f"(c[1]), "+f"(c[2]), "+f"(c[3])
        : "r"(a[0]), "r"(a[1]), "r"(a[2]), "r"(a[3]), "r"(b[0]), "r"(b[1]));
}

// ---------------- dense projection GEMM (128x64 tile, B [N,K]) ----------------
__device__ __forceinline__ void gemm_body(
    const float* __restrict__ A, const float* __restrict__ B,
    float* __restrict__ C, const float* __restrict__ bias,
    int M, int N, int K, int lda, int ldb, int ldc, float alpha)
{
    __shared__ uint32_t As[128][36];
    __shared__ uint32_t Bs[32][72];
    int tid = threadIdx.x;
    int warp = tid >> 5, lane = tid & 31;
    int g = lane >> 2, tg = lane & 3;
    int wm0 = (warp >> 1) * 32, wn0 = (warp & 1) * 32;
    int m0 = blockIdx.y * 128, n0 = blockIdx.x * 64;
    float acc[2][4][4] = {};

    for (int k0 = 0; k0 < K; k0 += 32) {
        #pragma unroll
        for (int i = 0; i < 4; i++) {
            int lin = tid + i * 256;
            int row = lin >> 3, c4 = lin & 7;
            int gm = m0 + row, gk = k0 + c4 * 4;
            float4 v = make_float4(0.f, 0.f, 0.f, 0.f);
            if (gm < M && gk + 4 <= K)
                v = *(const float4*)(A + (size_t)gm * lda + gk);
            As[row][c4 * 4 + 0] = f2tf(v.x);
            As[row][c4 * 4 + 1] = f2tf(v.y);
            As[row][c4 * 4 + 2] = f2tf(v.z);
            As[row][c4 * 4 + 3] = f2tf(v.w);
        }
        #pragma unroll
        for (int i = 0; i < 2; i++) {
            int lin = tid + i * 256;
            int n = lin >> 3, c4 = lin & 7;
            int gn = n0 + n, gk = k0 + c4 * 4;
            float4 v = make_float4(0.f, 0.f, 0.f, 0.f);
            if (gn < N && gk + 4 <= K)
                v = *(const float4*)(B + (size_t)gn * ldb + gk);
            Bs[c4 * 4 + 0][n] = f2tf(v.x);
            Bs[c4 * 4 + 1][n] = f2tf(v.y);
            Bs[c4 * 4 + 2][n] = f2tf(v.z);
            Bs[c4 * 4 + 3][n] = f2tf(v.w);
        }
        __syncthreads();
        #pragma unroll
        for (int kk = 0; kk < 32; kk += 8) {
            uint32_t a[2][4], bfr[4][2];
            #pragma unroll
            for (int mi = 0; mi < 2; mi++) {
                int r = wm0 + mi * 16 + g;
                a[mi][0] = As[r][kk + tg];
                a[mi][1] = As[r + 8][kk + tg];
                a[mi][2] = As[r][kk + tg + 4];
                a[mi][3] = As[r + 8][kk + tg + 4];
            }
            #pragma unroll
            for (int ni = 0; ni < 4; ni++) {
                int cn = wn0 + ni * 8 + g;
                bfr[ni][0] = Bs[kk + tg][cn];
                bfr[ni][1] = Bs[kk + tg + 4][cn];
            }
            #pragma unroll
            for (int mi = 0; mi < 2; mi++)
                #pragma unroll
                for (int ni = 0; ni < 4; ni++)
                    mma8(acc[mi][ni], a[mi], bfr[ni]);
        }
        __syncthreads();
    }

    #pragma unroll
    for (int mi = 0; mi < 2; mi++) {
        #pragma unroll
        for (int ni = 0; ni < 4; ni++) {
            int r0 = m0 + wm0 + mi * 16 + g;
            int cc0 = n0 + wn0 + ni * 8 + tg * 2;
            #pragma unroll
            for (int e = 0; e < 4; e++) {
                int r = r0 + (e >> 1) * 8;
                int cn = cc0 + (e & 1);
                if (r < M && cn < N) {
                    float val = acc[mi][ni][e] * alpha;
                    if (bias) val += bias[cn];
                    C[(size_t)r * ldc + cn] = val;
                }
            }
        }
    }
}

__global__ void gemm_proj(const float* __restrict__ A, const float* __restrict__ B,
                          float* __restrict__ C, const float* __restrict__ bias) {
    gemm_body(A, B, C, bias, BB * QQ, CC, CC, CC, CC, CC, 1.f);
}

// batched q/k/v projections in one launch (z selects which)
__global__ void gemm_qkv(const float* __restrict__ qry, const float* __restrict__ sampled,
                         const float* __restrict__ Wq, const float* __restrict__ Wk,
                         const float* __restrict__ Wv,
                         const float* __restrict__ bq, const float* __restrict__ bk,
                         const float* __restrict__ bv,
                         float* __restrict__ qp, float* __restrict__ kp, float* __restrict__ vp) {
    int z = blockIdx.z;
    const float* A = (z == 0) ? qry : sampled;
    const float* B = (z == 0) ? Wq : ((z == 1) ? Wk : Wv);
    const float* bi = (z == 0) ? bq : ((z == 1) ? bk : bv);
    float* C = (z == 0) ? qp : ((z == 1) ? kp : vp);
    gemm_body(A, B, C, bi, BB * QQ, CC, CC, CC, CC, CC, 1.f);
}

// ---------------- fused flash attention ----------------
// grid: (ceil(QQ/64), BB*NH); 256 threads (8 warps).
// Q tile 64x32, K/V tiles 64x32, P tile 64x64, online softmax, TF32 mma.
__global__ void flash_kernel(const float* __restrict__ qp, const float* __restrict__ kp,
                             const float* __restrict__ vp, float* __restrict__ attno) {
    __shared__ uint32_t Qs[64][36];
    __shared__ uint32_t Ks[32][72];
    __shared__ uint32_t Vs[64][40];
    __shared__ uint32_t Ps[64][68];
    __shared__ float part[2][64];
    __shared__ float m_s[64], l_s[64], sc_s[64];

    int z = blockIdx.y;
    int b = z / NH, h = z % NH;
    int q0 = blockIdx.x * 64;
    int tid = threadIdx.x;
    int warp = tid >> 5, lane = tid & 31;
    int g = lane >> 2, tg = lane & 3;
    int wm0 = (warp >> 1) * 16;
    int wn0 = (warp & 1) * 32;     // S col band
    int wn0p = (warp & 1) * 16;    // O col band
    int wn = warp & 1;

    const float* qbase = qp + (size_t)b * QQ * CC + h * HD;
    const float* kbase = kp + (size_t)b * QQ * CC + h * HD;
    const float* vbase = vp + (size_t)b * QQ * CC + h * HD;

    // load Q tile
    {
        int r = tid >> 2, cg = (tid & 3) * 8;
        float4 v0 = make_float4(0.f,0.f,0.f,0.f), v1 = v0;
        if (q0 + r < QQ) {
            v0 = *(const float4*)(qbase + (size_t)(q0 + r) * CC + cg);
            v1 = *(const float4*)(qbase + (size_t)(q0 + r) * CC + cg + 4);
        }
        Qs[r][cg+0]=f2tf(v0.x); Qs[r][cg+1]=f2tf(v0.y); Qs[r][cg+2]=f2tf(v0.z); Qs[r][cg+3]=f2tf(v0.w);
        Qs[r][cg+4]=f2tf(v1.x); Qs[r][cg+5]=f2tf(v1.y); Qs[r][cg+6]=f2tf(v1.z); Qs[r][cg+7]=f2tf(v1.w);
    }
    if (tid < 64) { m_s[tid] = -1e30f; l_s[tid] = 0.f; }
    float oacc[2][4] = {};
    __syncthreads();

    for (int k0 = 0; k0 < QQ; k0 += 64) {
        // load K (transposed into [k][n]) and V (direct [k][n])
        {
            int kv = tid >> 2, cg = (tid & 3) * 8;
            float4 a0 = make_float4(0.f,0.f,0.f,0.f), a1 = a0, b0 = a0, b1 = a0;
            if (k0 + kv < QQ) {
                a0 = *(const float4*)(kbase + (size_t)(k0 + kv) * CC + cg);
                a1 = *(const float4*)(kbase + (size_t)(k0 + kv) * CC + cg + 4);
                b0 = *(const float4*)(vbase + (size_t)(k0 + kv) * CC + cg);
                b1 = *(const float4*)(vbase + (size_t)(k0 + kv) * CC + cg + 4);
            }
            Ks[cg+0][kv]=f2tf(a0.x); Ks[cg+1][kv]=f2tf(a0.y); Ks[cg+2][kv]=f2tf(a0.z); Ks[cg+3][kv]=f2tf(a0.w);
            Ks[cg+4][kv]=f2tf(a1.x); Ks[cg+5][kv]=f2tf(a1.y); Ks[cg+6][kv]=f2tf(a1.z); Ks[cg+7][kv]=f2tf(a1.w);
            Vs[kv][cg+0]=f2tf(b0.x); Vs[kv][cg+1]=f2tf(b0.y); Vs[kv][cg+2]=f2tf(b0.z); Vs[kv][cg+3]=f2tf(b0.w);
            Vs[kv][cg+4]=f2tf(b1.x); Vs[kv][cg+5]=f2tf(b1.y); Vs[kv][cg+6]=f2tf(b1.z); Vs[kv][cg+7]=f2tf(b1.w);
        }
        __syncthreads();

        // S = Q @ K^T (per warp: 16 rows x 32 cols)
        float sacc[4][4] = {};
        #pragma unroll
        for (int kk = 0; kk < 32; kk += 8) {
            uint32_t a[4];
            a[0] = Qs[wm0 + g][kk + tg];
            a[1] = Qs[wm0 + g + 8][kk + tg];
            a[2] = Qs[wm0 + g][kk + tg + 4];
            a[3] = Qs[wm0 + g + 8][kk + tg + 4];
            #pragma unroll
            for (int ni = 0; ni < 4; ni++) {
                uint32_t bf[2];
                int cn = wn0 + ni * 8 + g;
                bf[0] = Ks[kk + tg][cn];
                bf[1] = Ks[kk + tg + 4][cn];
                mma8(sacc[ni], a, bf);
            }
        }

        // scale + mask + per-thread rowmax
        float r0 = -1e30f, r1 = -1e30f;
        #pragma unroll
        for (int ni = 0; ni < 4; ni++) {
            #pragma unroll
            for (int e = 0; e < 4; e++) {
                int gk = k0 + wn0 + ni * 8 + tg * 2 + (e & 1);
                float s = sacc[ni][e] * ATT_SCALE;
                if (gk >= QQ) s = -1e30f;
                sacc[ni][e] = s;
                if (e < 2) r0 = fmaxf(r0, s); else r1 = fmaxf(r1, s);
            }
        }
        r0 = fmaxf(r0, __shfl_xor_sync(0xffffffffu, r0, 1));
        r0 = fmaxf(r0, __shfl_xor_sync(0xffffffffu, r0, 2));
        r1 = fmaxf(r1, __shfl_xor_sync(0xffffffffu, r1, 1));
        r1 = fmaxf(r1, __shfl_xor_sync(0xffffffffu, r1, 2));
        if (tg == 0) { part[wn][wm0 + g] = r0; part[wn][wm0 + g + 8] = r1; }
        __syncthreads();

        if (tid < 64) {
            float nm = fmaxf(m_s[tid], fmaxf(part[0][tid], part[1][tid]));
            float sc = __expf(m_s[tid] - nm);
            sc_s[tid] = sc;
            m_s[tid] = nm;
            l_s[tid] *= sc;
        }
        __syncthreads();

        // P = exp(S - m), write to smem, partial row sums
        float m0r = m_s[wm0 + g], m1r = m_s[wm0 + g + 8];
        float s0 = 0.f, s1 = 0.f;
        #pragma unroll
        for (int ni = 0; ni < 4; ni++) {
            #pragma unroll
            for (int e = 0; e < 4; e++) {
                float mr = (e < 2) ? m0r : m1r;
                float p = __expf(sacc[ni][e] - mr);
                int col = wn0 + ni * 8 + tg * 2 + (e & 1);
                Ps[wm0 + g + ((e >> 1) << 3)][col] = f2tf(p);
                if (e < 2) s0 += p; else s1 += p;
            }
        }
        s0 += __shfl_xor_sync(0xffffffffu, s0, 1);
        s0 += __shfl_xor_sync(0xffffffffu, s0, 2);
        s1 += __shfl_xor_sync(0xffffffffu, s1, 1);
        s1 += __shfl_xor_sync(0xffffffffu, s1, 2);
        if (tg == 0) { part[wn][wm0 + g] = s0; part[wn][wm0 + g + 8] = s1; }
        __syncthreads();

        if (tid < 64) l_s[tid] += part[0][tid] + part[1][tid];

        // rescale O accumulator
        float sc0 = sc_s[wm0 + g], sc1 = sc_s[wm0 + g + 8];
        #pragma unroll
        for (int ni = 0; ni < 2; ni++) {
            oacc[ni][0] *= sc0; oacc[ni][1] *= sc0;
            oacc[ni][2] *= sc1; oacc[ni][3] *= sc1;
        }

        // O += P @ V (per warp: 16 rows x 16 cols, k=64)
        #pragma unroll
        for (int kk = 0; kk < 64; kk += 8) {
            uint32_t a[4];
            a[0] = Ps[wm0 + g][kk + tg];
            a[1] = Ps[wm0 + g + 8][kk + tg];
            a[2] = Ps[wm0 + g][kk + tg + 4];
            a[3] = Ps[wm0 + g + 8][kk + tg + 4];
            #pragma unroll
            for (int ni = 0; ni < 2; ni++) {
                uint32_t bf[2];
                int cn = wn0p + ni * 8 + g;
                bf[0] = Vs[kk + tg][cn];
                bf[1] = Vs[kk + tg + 4][cn];
                mma8(oacc[ni], a, bf);
            }
        }
        __syncthreads();
    }

    // epilogue: divide by l, write [B,Q,C] head-interleaved
    float li0 = 1.f / l_s[wm0 + g];
    float li1 = 1.f / l_s[wm0 + g + 8];
    #pragma unroll
    for (int ni = 0; ni < 2; ni++) {
        #pragma unroll
        for (int e = 0; e < 4; e++) {
            int row = wm0 + g + ((e >> 1) << 3);
            int col = wn0p + ni * 8 + tg * 2 + (e & 1);
            int q = q0 + row;
            if (q < QQ)
                attno[((size_t)b * QQ + q) * CC + h * HD + col] =
                    oacc[ni][e] * ((e < 2) ? li0 : li1);
        }
    }
}

// ---------------- host launcher ----------------
extern "C" void kernel_launch(void* const* d_in, const int* in_sizes, int n_in,
                              void* d_out, int out_size) {
    const float* f0   = (const float*)d_in[0];
    const float* f1   = (const float*)d_in[1];
    const float* refs = (const float*)d_in[2];
    const float* intr = (const float*)d_in[3];
    const float* extr = (const float*)d_in[4];
    const float* qry  = (const float*)d_in[5];
    const float* Wq   = (const float*)d_in[6];
    const float* bq   = (const float*)d_in[7];
    const float* Wk   = (const float*)d_in[8];
    const float* bk   = (const float*)d_in[9];
    const float* Wv   = (const float*)d_in[10];
    const float* bv   = (const float*)d_in[11];
    const float* Wo   = (const float*)d_in[12];
    const float* bo   = (const float*)d_in[13];
    float* out = (float*)d_out;

    float *featT0, *featT1, *sampled, *qp, *kp, *vp, *attno;
    cudaGetSymbolAddress((void**)&featT0, g_featT0);
    cudaGetSymbolAddress((void**)&featT1, g_featT1);
    cudaGetSymbolAddress((void**)&sampled, g_sampled);
    cudaGetSymbolAddress((void**)&qp, g_qp);
    cudaGetSymbolAddress((void**)&kp, g_kp);
    cudaGetSymbolAddress((void**)&vp, g_vp);
    cudaGetSymbolAddress((void**)&attno, g_attno);

    dim3 tt(32, 8);
    transpose_kernel<<<dim3((H0 * W0) / 32, CC / 32, BB * VV), tt>>>(f0, featT0, H0 * W0);
    transpose_kernel<<<dim3((H1 * W1) / 32, CC / 32, BB * VV), tt>>>(f1, featT1, H1 * W1);
    proj_kernel<<<(BB * VV * QQ * KP + 255) / 256, 256>>>(refs, intr, extr);
    sample_kernel<<<(BB * QQ) / 4, dim3(64, 4)>>>();

    const int M = BB * QQ;  // 1800
    gemm_qkv<<<dim3(CC / 64, (M + 127) / 128, 3), 256>>>(
        qry, sampled, Wq, Wk, Wv, bq, bk, bv, qp, kp, vp);

    flash_kernel<<<dim3((QQ + 63) / 64, BB * NH), 256>>>(qp, kp, vp, attno);

    gemm_proj<<<dim3(CC / 64, (M + 127) / 128), 256>>>(attno, Wo, out, bo);
}

// round 5
// speedup vs baseline: 2.5535x; 1.1960x over previous
#include <cuda_runtime.h>
#include <math.h>
#include <stdint.h>

#define BB 2
#define VV 6
#define CC 256
#define QQ 900
#define KP 4
#define H0 64
#define W0 176
#define H1 32
#define W1 88
#define NH 8
#define HD 32
#define ATT_SCALE 0.17677669529663689f

// ---------------- scratch (device globals; no runtime allocation) ----------------
__device__ float  g_featT0[(size_t)BB*VV*H0*W0*CC];   // [B,V,H,W,C]
__device__ float  g_featT1[(size_t)BB*VV*H1*W1*CC];
__device__ float4 g_proj[BB*VV*QQ*KP];                // (u/z, v/z, valid, pad)
__device__ float  g_sampled[BB*QQ*CC];
__device__ float  g_qp[BB*QQ*CC];
__device__ float  g_kp[BB*QQ*CC];
__device__ float  g_vp[BB*QQ*CC];
__device__ float  g_attno[BB*QQ*CC];

// ---------------- feature transpose: [bv, C, HW] -> [bv, HW, C] ----------------
__global__ void transpose_kernel(const float* __restrict__ in, float* __restrict__ out, int HW) {
    __shared__ float tile[32][33];
    int bv = blockIdx.z;
    int c0 = blockIdx.y * 32, p0 = blockIdx.x * 32;
    const float* src = in  + (size_t)bv * CC * HW;
    float*       dst = out + (size_t)bv * HW * CC;
    int tx = threadIdx.x, ty = threadIdx.y;
    #pragma unroll
    for (int i = 0; i < 32; i += 8) {
        int c = c0 + ty + i, p = p0 + tx;
        if (c < CC && p < HW) tile[ty + i][tx] = src[(size_t)c * HW + p];
    }
    __syncthreads();
    #pragma unroll
    for (int i = 0; i < 32; i += 8) {
        int p = p0 + ty + i, c = c0 + tx;
        if (p < HW && c < CC) dst[(size_t)p * CC + c] = tile[tx][ty + i];
    }
}

// ---------------- projection ----------------
__global__ void proj_kernel(const float* __restrict__ refs,
                            const float* __restrict__ intr,
                            const float* __restrict__ extr) {
    int idx = blockIdx.x * 256 + threadIdx.x;
    if (idx >= BB * VV * QQ * KP) return;
    int k = idx & 3;
    int q = (idx >> 2) % QQ;
    int v = (idx / (KP * QQ)) % VV;
    int b = idx / (KP * QQ * VV);
    const float kpx[4] = {0.f, 2.f, 0.f, -2.f};
    const float kpy[4] = {0.f, 0.f, 2.f, 0.f};
    const float* r = refs + (b * QQ + q) * 3;
    float rx = r[0] + kpx[k], ry = r[1] + kpy[k], rz = r[2];
    const float* E = extr + (b * VV + v) * 16;
    float c0 = E[0]*rx + E[1]*ry + E[2]*rz + E[3];
    float c1 = E[4]*rx + E[5]*ry + E[6]*rz + E[7];
    float c2 = E[8]*rx + E[9]*ry + E[10]*rz + E[11];
    const float* I = intr + (b * VV + v) * 9;
    float u = I[0]*c0 + I[1]*c1 + I[2]*c2;
    float w = I[3]*c0 + I[4]*c1 + I[5]*c2;
    float z = I[6]*c0 + I[7]*c1 + I[8]*c2;
    float zs = (fabsf(z) > 1e-6f) ? z : 1e-6f;
    float4 o;
    o.x = u / zs;
    o.y = w / zs;
    o.z = (z > 0.f) ? 1.f : 0.f;
    o.w = 0.f;
    g_proj[idx] = o;
}

// ---------------- sampling: 4 queries/block, float4 channels ----------------
__global__ void sample_kernel() {
    __shared__ float        s_w[4][48][4];
    __shared__ const float* s_p[4][48][4];
    __shared__ int          s_valid[4][48];
    __shared__ float        s_cnt[4];
    int tid = threadIdx.y * 64 + threadIdx.x;
    int bq0 = blockIdx.x * 4;

    if (tid < 192) {
        int qy = tid / 48, t = tid % 48;
        int bq = bq0 + qy;
        int b = bq / QQ, q = bq % QQ;
        int level = t / 24, r = t % 24, v = r >> 2, k = r & 3;
        int bv = b * VV + v;
        float4 pr = g_proj[((size_t)bv * QQ + q) * KP + k];
        int H = level ? H1 : H0, W = level ? W1 : W0;
        const float* base = level ? g_featT1 : g_featT0;
        s_valid[qy][t] = (pr.z != 0.f);
        float gx = 2.f * pr.x / (float)(W - 1) - 1.f;
        float gy = 2.f * pr.y / (float)(H - 1) - 1.f;
        float x = (gx + 1.f) * 0.5f * (float)(W - 1);
        float y = (gy + 1.f) * 0.5f * (float)(H - 1);
        float x0f = floorf(x), y0f = floorf(y);
        float wx1 = x - x0f, wx0 = 1.f - wx1;
        float wy1 = y - y0f, wy0 = 1.f - wy1;
        #pragma unroll
        for (int c4 = 0; c4 < 4; c4++) {
            int dx = c4 & 1, dy = c4 >> 1;
            float xf = x0f + (float)dx, yf = y0f + (float)dy;
            bool inb = (xf >= 0.f) && (xf <= (float)(W - 1)) && (yf >= 0.f) && (yf <= (float)(H - 1));
            int xi = min(max((int)xf, 0), W - 1);
            int yi = min(max((int)yf, 0), H - 1);
            s_w[qy][t][c4] = inb ? (dx ? wx1 : wx0) * (dy ? wy1 : wy0) : 0.f;
            s_p[qy][t][c4] = base + (((size_t)bv * H + yi) * W + xi) * CC;
        }
    }
    __syncthreads();
    if (tid < 4) {
        float c = 0.f;
        for (int t = 0; t < 24; t++) c += s_valid[tid][t] ? 1.f : 0.f;
        s_cnt[tid] = 0.5f / fmaxf(c, 1.f);
    }
    __syncthreads();

    int qy = threadIdx.y, c = threadIdx.x * 4;
    float4 acc = make_float4(0.f, 0.f, 0.f, 0.f);
    #pragma unroll 4
    for (int t = 0; t < 48; t++) {
        if (!s_valid[qy][t]) continue;
        #pragma unroll
        for (int j = 0; j < 4; j++) {
            float w = s_w[qy][t][j];
            float4 v = *(const float4*)(s_p[qy][t][j] + c);
            acc.x = fmaf(w, v.x, acc.x);
            acc.y = fmaf(w, v.y, acc.y);
            acc.z = fmaf(w, v.z, acc.z);
            acc.w = fmaf(w, v.w, acc.w);
        }
    }
    float sc = s_cnt[qy];
    int bq = bq0 + qy;
    *(float4*)(g_sampled + (size_t)bq * CC + c) =
        make_float4(acc.x * sc, acc.y * sc, acc.z * sc, acc.w * sc);
}

// ---------------- TF32 mma helpers ----------------
__device__ __forceinline__ uint32_t f2tf(float x) {
    uint32_t r;
    asm("cvt.rna.tf32.f32 %0, %1;" : "=r"(r) : "f"(x));
    return r;
}

__device__ __forceinline__ void mma8(float* c, const uint32_t* a, const uint32_t* b) {
    asm volatile(
        "mma.sync.aligned.m16n8k8.row.col.f32.tf32.tf32.f32 "
        "{%0,%1,%2,%3},{%4,%5,%6,%7},{%8,%9},{%0,%1,%2,%3};\n"
        : "+f"(c[0]), "+f"(c[1]), "+f"(c[2]), "+f"(c[3])
        : "r"(a[0]), "r"(a[1]), "r"(a[2]), "r"(a[3]), "r"(b[0]), "r"(b[1]));
}

// ---------------- pipelined projection GEMM (128x64 tile, B [N,K] row-major) ----------------
// dynamic smem: As[2][128][36], Bs[2][32][72]  (55296 bytes)
#define GEMM_SMEM (2*128*36*4 + 2*32*72*4)
__device__ __forceinline__ void gemm_body(
    const float* __restrict__ A, const float* __restrict__ B,
    float* __restrict__ C, const float* __restrict__ bias,
    int M, int N, int K, int lda, int ldb, int ldc, float alpha)
{
    extern __shared__ uint32_t gsm[];
    uint32_t (*As)[128][36] = (uint32_t(*)[128][36])gsm;
    uint32_t (*Bs)[32][72]  = (uint32_t(*)[32][72])(gsm + 2*128*36);
    int tid = threadIdx.x;
    int warp = tid >> 5, lane = tid & 31;
    int g = lane >> 2, tg = lane & 3;
    int wm0 = (warp >> 1) * 32, wn0 = (warp & 1) * 32;
    int m0 = blockIdx.y * 128, n0 = blockIdx.x * 64;
    float acc[2][4][4] = {};

    int arow = tid >> 3, ac4 = (tid & 7) * 4;      // A stage addressing (x4 over i)
    int brow = tid >> 3, bc4 = (tid & 7) * 4;      // B stage addressing (x2 over i)

    float4 aR[4], bR[2];
    auto loadA = [&](int k0) {
        #pragma unroll
        for (int i = 0; i < 4; i++) {
            int row = arow + i * 32;
            int gm = m0 + row, gk = k0 + ac4;
            aR[i] = (gm < M) ? *(const float4*)(A + (size_t)gm * lda + gk)
                             : make_float4(0.f, 0.f, 0.f, 0.f);
        }
    };
    auto loadB = [&](int k0) {
        #pragma unroll
        for (int i = 0; i < 2; i++) {
            int n = brow + i * 32;
            int gn = n0 + n, gk = k0 + bc4;
            bR[i] = (gn < N) ? *(const float4*)(B + (size_t)gn * ldb + gk)
                             : make_float4(0.f, 0.f, 0.f, 0.f);
        }
    };
    auto stage = [&](int buf) {
        #pragma unroll
        for (int i = 0; i < 4; i++) {
            int row = arow + i * 32;
            As[buf][row][ac4+0] = f2tf(aR[i].x);
            As[buf][row][ac4+1] = f2tf(aR[i].y);
            As[buf][row][ac4+2] = f2tf(aR[i].z);
            As[buf][row][ac4+3] = f2tf(aR[i].w);
        }
        #pragma unroll
        for (int i = 0; i < 2; i++) {
            int n = brow + i * 32;
            Bs[buf][bc4+0][n] = f2tf(bR[i].x);
            Bs[buf][bc4+1][n] = f2tf(bR[i].y);
            Bs[buf][bc4+2][n] = f2tf(bR[i].z);
            Bs[buf][bc4+3][n] = f2tf(bR[i].w);
        }
    };

    loadA(0); loadB(0);
    int nk = K >> 5;
    int buf = 0;
    for (int kt = 0; kt < nk; kt++) {
        stage(buf);
        __syncthreads();
        if (kt + 1 < nk) { loadA((kt + 1) * 32); loadB((kt + 1) * 32); }
        #pragma unroll
        for (int kk = 0; kk < 32; kk += 8) {
            uint32_t a[2][4], bfr[4][2];
            #pragma unroll
            for (int mi = 0; mi < 2; mi++) {
                int r = wm0 + mi * 16 + g;
                a[mi][0] = As[buf][r][kk + tg];
                a[mi][1] = As[buf][r + 8][kk + tg];
                a[mi][2] = As[buf][r][kk + tg + 4];
                a[mi][3] = As[buf][r + 8][kk + tg + 4];
            }
            #pragma unroll
            for (int ni = 0; ni < 4; ni++) {
                int cn = wn0 + ni * 8 + g;
                bfr[ni][0] = Bs[buf][kk + tg][cn];
                bfr[ni][1] = Bs[buf][kk + tg + 4][cn];
            }
            #pragma unroll
            for (int mi = 0; mi < 2; mi++)
                #pragma unroll
                for (int ni = 0; ni < 4; ni++)
                    mma8(acc[mi][ni], a[mi], bfr[ni]);
        }
        buf ^= 1;
    }

    #pragma unroll
    for (int mi = 0; mi < 2; mi++) {
        #pragma unroll
        for (int ni = 0; ni < 4; ni++) {
            int r0 = m0 + wm0 + mi * 16 + g;
            int cc0 = n0 + wn0 + ni * 8 + tg * 2;
            #pragma unroll
            for (int e = 0; e < 4; e++) {
                int r = r0 + (e >> 1) * 8;
                int cn = cc0 + (e & 1);
                if (r < M && cn < N) {
                    float val = acc[mi][ni][e] * alpha;
                    if (bias) val += bias[cn];
                    C[(size_t)r * ldc + cn] = val;
                }
            }
        }
    }
}

__global__ void gemm_proj(const float* __restrict__ A, const float* __restrict__ B,
                          float* __restrict__ C, const float* __restrict__ bias) {
    gemm_body(A, B, C, bias, BB * QQ, CC, CC, CC, CC, CC, 1.f);
}

__global__ void gemm_qkv(const float* __restrict__ qry, const float* __restrict__ sampled,
                         const float* __restrict__ Wq, const float* __restrict__ Wk,
                         const float* __restrict__ Wv,
                         const float* __restrict__ bq, const float* __restrict__ bk,
                         const float* __restrict__ bv,
                         float* __restrict__ qp, float* __restrict__ kp, float* __restrict__ vp) {
    int z = blockIdx.z;
    const float* A = (z == 0) ? qry : sampled;
    const float* B = (z == 0) ? Wq : ((z == 1) ? Wk : Wv);
    const float* bi = (z == 0) ? bq : ((z == 1) ? bk : bv);
    float* C = (z == 0) ? qp : ((z == 1) ? kp : vp);
    gemm_body(A, B, C, bi, BB * QQ, CC, CC, CC, CC, CC, 1.f);
}

// ---------------- fused flash attention v2 ----------------
// Q tile 128 rows, each of 8 warps owns 16 COMPLETE rows (all 64 S cols)
// -> softmax stats fully in registers, P warp-private, 1 __syncthreads per KV tile.
// dynamic smem: Qs[128][36] | Ks[2][32][72] | Vs[2][64][40] | Ps[128][68] = 92160 B
#define FLASH_SMEM ((128*36 + 2*32*72 + 2*64*40 + 128*68) * 4)
#define NIT ((QQ + 63) / 64)

__global__ void flash_kernel(const float* __restrict__ qp, const float* __restrict__ kp,
                             const float* __restrict__ vp, float* __restrict__ attno) {
    extern __shared__ uint32_t fsm[];
    uint32_t (*Qs)[36]     = (uint32_t(*)[36])fsm;
    uint32_t (*Ks)[32][72] = (uint32_t(*)[32][72])(fsm + 128*36);
    uint32_t (*Vs)[64][40] = (uint32_t(*)[64][40])(fsm + 128*36 + 2*32*72);
    uint32_t (*Ps)[68]     = (uint32_t(*)[68])(fsm + 128*36 + 2*32*72 + 2*64*40);

    int z = blockIdx.y;
    int b = z / NH, h = z % NH;
    int q0 = blockIdx.x * 128;
    int tid = threadIdx.x;
    int warp = tid >> 5, lane = tid & 31;
    int g = lane >> 2, tg = lane & 3;
    int wr0 = warp * 16;

    const float* qbase = qp + (size_t)b * QQ * CC + h * HD;
    const float* kbase = kp + (size_t)b * QQ * CC + h * HD;
    const float* vbase = vp + (size_t)b * QQ * CC + h * HD;

    // load Q tile (scale folded in): 128 rows x 32 cols = 1024 float4 / 256 thr = 4 each
    #pragma unroll
    for (int i = 0; i < 4; i++) {
        int lin = tid + i * 256;
        int row = lin >> 3, c4 = (lin & 7) * 4;
        float4 v = make_float4(0.f, 0.f, 0.f, 0.f);
        if (q0 + row < QQ) v = *(const float4*)(qbase + (size_t)(q0 + row) * CC + c4);
        Qs[row][c4+0] = f2tf(v.x * ATT_SCALE);
        Qs[row][c4+1] = f2tf(v.y * ATT_SCALE);
        Qs[row][c4+2] = f2tf(v.z * ATT_SCALE);
        Qs[row][c4+3] = f2tf(v.w * ATT_SCALE);
    }

    // KV register staging: 64 rows x 32 cols = 512 float4 each / 256 thr = 2 each
    int kvrow0 = tid >> 3, kvc4 = (tid & 7) * 4;
    float4 kr[2], vr[2];
    auto loadKV = [&](int k0) {
        #pragma unroll
        for (int j = 0; j < 2; j++) {
            int row = kvrow0 + j * 32;
            int gk = k0 + row;
            if (gk < QQ) {
                kr[j] = *(const float4*)(kbase + (size_t)gk * CC + kvc4);
                vr[j] = *(const float4*)(vbase + (size_t)gk * CC + kvc4);
            } else {
                kr[j] = make_float4(0.f, 0.f, 0.f, 0.f);
                vr[j] = kr[j];
            }
        }
    };
    auto stageKV = [&](int buf) {
        #pragma unroll
        for (int j = 0; j < 2; j++) {
            int row = kvrow0 + j * 32;
            Ks[buf][kvc4+0][row] = f2tf(kr[j].x);
            Ks[buf][kvc4+1][row] = f2tf(kr[j].y);
            Ks[buf][kvc4+2][row] = f2tf(kr[j].z);
            Ks[buf][kvc4+3][row] = f2tf(kr[j].w);
            Vs[buf][row][kvc4+0] = f2tf(vr[j].x);
            Vs[buf][row][kvc4+1] = f2tf(vr[j].y);
            Vs[buf][row][kvc4+2] = f2tf(vr[j].z);
            Vs[buf][row][kvc4+3] = f2tf(vr[j].w);
        }
    };

    float m0r = -1e30f, m1r = -1e30f;   // running max, rows (wr0+g), (wr0+g+8)
    float l0 = 0.f, l1 = 0.f;           // running denom
    float oacc[4][4] = {};

    loadKV(0);
    int buf = 0;
    for (int it = 0; it < NIT; it++) {
        stageKV(buf);
        __syncthreads();
        if (it + 1 < NIT) loadKV((it + 1) * 64);

        // S = Qscaled @ K^T : 16 rows x 64 cols per warp
        float sacc[8][4] = {};
        #pragma unroll
        for (int kk = 0; kk < 32; kk += 8) {
            uint32_t a[4];
            a[0] = Qs[wr0 + g][kk + tg];
            a[1] = Qs[wr0 + g + 8][kk + tg];
            a[2] = Qs[wr0 + g][kk + tg + 4];
            a[3] = Qs[wr0 + g + 8][kk + tg + 4];
            #pragma unroll
            for (int ni = 0; ni < 8; ni++) {
                uint32_t bf[2];
                int cn = ni * 8 + g;
                bf[0] = Ks[buf][kk + tg][cn];
                bf[1] = Ks[buf][kk + tg + 4][cn];
                mma8(sacc[ni], a, bf);
            }
        }

        // mask + per-thread rowmax
        int cbase = it * 64;
        float r0 = -1e30f, r1 = -1e30f;
        #pragma unroll
        for (int ni = 0; ni < 8; ni++) {
            #pragma unroll
            for (int e = 0; e < 4; e++) {
                int gk = cbase + ni * 8 + tg * 2 + (e & 1);
                float s = sacc[ni][e];
                if (gk >= QQ) s = -1e30f;
                sacc[ni][e] = s;
                if (e < 2) r0 = fmaxf(r0, s); else r1 = fmaxf(r1, s);
            }
        }
        r0 = fmaxf(r0, __shfl_xor_sync(0xffffffffu, r0, 1));
        r0 = fmaxf(r0, __shfl_xor_sync(0xffffffffu, r0, 2));
        r1 = fmaxf(r1, __shfl_xor_sync(0xffffffffu, r1, 1));
        r1 = fmaxf(r1, __shfl_xor_sync(0xffffffffu, r1, 2));

        float nm0 = fmaxf(m0r, r0), nm1 = fmaxf(m1r, r1);
        float sc0 = __expf(m0r - nm0), sc1 = __expf(m1r - nm1);
        m0r = nm0; m1r = nm1;

        // P = exp(S - m) -> warp-private smem, partial row sums
        float s0 = 0.f, s1 = 0.f;
        #pragma unroll
        for (int ni = 0; ni < 8; ni++) {
            #pragma unroll
            for (int e = 0; e < 4; e++) {
                float mr = (e < 2) ? m0r : m1r;
                float p = __expf(sacc[ni][e] - mr);
                Ps[wr0 + g + ((e >> 1) << 3)][ni * 8 + tg * 2 + (e & 1)] = f2tf(p);
                if (e < 2) s0 += p; else s1 += p;
            }
        }
        s0 += __shfl_xor_sync(0xffffffffu, s0, 1);
        s0 += __shfl_xor_sync(0xffffffffu, s0, 2);
        s1 += __shfl_xor_sync(0xffffffffu, s1, 1);
        s1 += __shfl_xor_sync(0xffffffffu, s1, 2);
        l0 = l0 * sc0 + s0;
        l1 = l1 * sc1 + s1;

        // rescale O accumulator
        #pragma unroll
        for (int ni = 0; ni < 4; ni++) {
            oacc[ni][0] *= sc0; oacc[ni][1] *= sc0;
            oacc[ni][2] *= sc1; oacc[ni][3] *= sc1;
        }
        __syncwarp();

        // O += P @ V : 16 rows x 32 cols per warp, k=64
        #pragma unroll
        for (int kk = 0; kk < 64; kk += 8) {
            uint32_t a[4];
            a[0] = Ps[wr0 + g][kk + tg];
            a[1] = Ps[wr0 + g + 8][kk + tg];
            a[2] = Ps[wr0 + g][kk + tg + 4];
            a[3] = Ps[wr0 + g + 8][kk + tg + 4];
            #pragma unroll
            for (int ni = 0; ni < 4; ni++) {
                uint32_t bf[2];
                int cn = ni * 8 + g;
                bf[0] = Vs[buf][kk + tg][cn];
                bf[1] = Vs[buf][kk + tg + 4][cn];
                mma8(oacc[ni], a, bf);
            }
        }
        buf ^= 1;
    }

    // epilogue
    float li0 = 1.f / l0, li1 = 1.f / l1;
    #pragma unroll
    for (int ni = 0; ni < 4; ni++) {
        #pragma unroll
        for (int e = 0; e < 4; e++) {
            int row = wr0 + g + ((e >> 1) << 3);
            int col = ni * 8 + tg * 2 + (e & 1);
            int q = q0 + row;
            if (q < QQ)
                attno[((size_t)b * QQ + q) * CC + h * HD + col] =
                    oacc[ni][e] * ((e < 2) ? li0 : li1);
        }
    }
}

// ---------------- host launcher ----------------
extern "C" void kernel_launch(void* const* d_in, const int* in_sizes, int n_in,
                              void* d_out, int out_size) {
    const float* f0   = (const float*)d_in[0];
    const float* f1   = (const float*)d_in[1];
    const float* refs = (const float*)d_in[2];
    const float* intr = (const float*)d_in[3];
    const float* extr = (const float*)d_in[4];
    const float* qry  = (const float*)d_in[5];
    const float* Wq   = (const float*)d_in[6];
    const float* bq   = (const float*)d_in[7];
    const float* Wk   = (const float*)d_in[8];
    const float* bk   = (const float*)d_in[9];
    const float* Wv   = (const float*)d_in[10];
    const float* bv   = (const float*)d_in[11];
    const float* Wo   = (const float*)d_in[12];
    const float* bo   = (const float*)d_in[13];
    float* out = (float*)d_out;

    float *featT0, *featT1, *sampled, *qp, *kp, *vp, *attno;
    cudaGetSymbolAddress((void**)&featT0, g_featT0);
    cudaGetSymbolAddress((void**)&featT1, g_featT1);
    cudaGetSymbolAddress((void**)&sampled, g_sampled);
    cudaGetSymbolAddress((void**)&qp, g_qp);
    cudaGetSymbolAddress((void**)&kp, g_kp);
    cudaGetSymbolAddress((void**)&vp, g_vp);
    cudaGetSymbolAddress((void**)&attno, g_attno);

    cudaFuncSetAttribute(gemm_qkv, cudaFuncAttributeMaxDynamicSharedMemorySize, GEMM_SMEM);
    cudaFuncSetAttribute(gemm_proj, cudaFuncAttributeMaxDynamicSharedMemorySize, GEMM_SMEM);
    cudaFuncSetAttribute(flash_kernel, cudaFuncAttributeMaxDynamicSharedMemorySize, FLASH_SMEM);

    dim3 tt(32, 8);
    transpose_kernel<<<dim3((H0 * W0) / 32, CC / 32, BB * VV), tt>>>(f0, featT0, H0 * W0);
    transpose_kernel<<<dim3((H1 * W1) / 32, CC / 32, BB * VV), tt>>>(f1, featT1, H1 * W1);
    proj_kernel<<<(BB * VV * QQ * KP + 255) / 256, 256>>>(refs, intr, extr);
    sample_kernel<<<(BB * QQ) / 4, dim3(64, 4)>>>();

    const int M = BB * QQ;  // 1800
    gemm_qkv<<<dim3(CC / 64, (M + 127) / 128, 3), 256, GEMM_SMEM>>>(
        qry, sampled, Wq, Wk, Wv, bq, bk, bv, qp, kp, vp);

    flash_kernel<<<dim3((QQ + 127) / 128, BB * NH), 256, FLASH_SMEM>>>(qp, kp, vp, attno);

    gemm_proj<<<dim3(CC / 64, (M + 127) / 128), 256, GEMM_SMEM>>>(attno, Wo, out, bo);
}

// round 6
// speedup vs baseline: 2.7964x; 1.0951x over previous
#include <cuda_runtime.h>
#include <cuda_fp16.h>
#include <math.h>
#include <stdint.h>

#define BB 2
#define VV 6
#define CC 256
#define QQ 900
#define KP 4
#define H0 64
#define W0 176
#define H1 32
#define W1 88
#define NH 8
#define HD 32
#define ATT_SCALE 0.17677669529663689f

// ---------------- scratch (device globals; no runtime allocation) ----------------
__device__ __half g_featT0[(size_t)BB*VV*H0*W0*CC];   // [B,V,H,W,C] fp16
__device__ __half g_featT1[(size_t)BB*VV*H1*W1*CC];
__device__ float  g_sampled[BB*QQ*CC];
__device__ float  g_qp[BB*QQ*CC];
__device__ float  g_kp[BB*QQ*CC];
__device__ float  g_vp[BB*QQ*CC];
__device__ float  g_attno[BB*QQ*CC];

// ---------------- feature transpose: [bv, C, HW] -> [bv, HW, C] fp32 -> fp16 ----------------
__global__ void transpose_kernel(const float* __restrict__ in, __half* __restrict__ out, int HW) {
    __shared__ float tile[32][33];
    int bv = blockIdx.z;
    int c0 = blockIdx.y * 32, p0 = blockIdx.x * 32;
    const float* src = in  + (size_t)bv * CC * HW;
    __half*      dst = out + (size_t)bv * HW * CC;
    int tx = threadIdx.x, ty = threadIdx.y;
    #pragma unroll
    for (int i = 0; i < 32; i += 8) {
        int c = c0 + ty + i, p = p0 + tx;
        if (c < CC && p < HW) tile[ty + i][tx] = src[(size_t)c * HW + p];
    }
    __syncthreads();
    #pragma unroll
    for (int i = 0; i < 32; i += 8) {
        int p = p0 + ty + i, c = c0 + tx;
        if (p < HW && c < CC) dst[(size_t)p * CC + c] = __float2half(tile[tx][ty + i]);
    }
}

// ---------------- sampling: proj fused into setup; 4 queries/block, fp16 features ----------------
__global__ void sample_kernel(const float* __restrict__ refs,
                              const float* __restrict__ intr,
                              const float* __restrict__ extr) {
    __shared__ float         s_w[4][48][4];
    __shared__ const __half* s_p[4][48][4];
    __shared__ int           s_valid[4][48];
    __shared__ float         s_cnt[4];
    int tid = threadIdx.y * 64 + threadIdx.x;
    int bq0 = blockIdx.x * 4;

    if (tid < 192) {
        int qy = tid / 48, t = tid % 48;
        int bq = bq0 + qy;
        int b = bq / QQ, q = bq % QQ;
        int level = t / 24, r = t % 24, v = r >> 2, k = r & 3;
        int bv = b * VV + v;
        // ---- projection (computed in-place; replicates reference math) ----
        const float kpx[4] = {0.f, 2.f, 0.f, -2.f};
        const float kpy[4] = {0.f, 0.f, 2.f, 0.f};
        const float* rp = refs + (b * QQ + q) * 3;
        float rx = rp[0] + kpx[k], ry = rp[1] + kpy[k], rz = rp[2];
        const float* E = extr + bv * 16;
        float c0 = E[0]*rx + E[1]*ry + E[2]*rz + E[3];
        float c1 = E[4]*rx + E[5]*ry + E[6]*rz + E[7];
        float c2 = E[8]*rx + E[9]*ry + E[10]*rz + E[11];
        const float* I = intr + bv * 9;
        float u  = I[0]*c0 + I[1]*c1 + I[2]*c2;
        float w_ = I[3]*c0 + I[4]*c1 + I[5]*c2;
        float z  = I[6]*c0 + I[7]*c1 + I[8]*c2;
        float zs = (fabsf(z) > 1e-6f) ? z : 1e-6f;
        float uz = u / zs, vz = w_ / zs;
        s_valid[qy][t] = (z > 0.f);
        // ---- bilinear geometry (replicates normalize->unnormalize round trip) ----
        int H = level ? H1 : H0, W = level ? W1 : W0;
        const __half* base = level ? g_featT1 : g_featT0;
        float gx = 2.f * uz / (float)(W - 1) - 1.f;
        float gy = 2.f * vz / (float)(H - 1) - 1.f;
        float x = (gx + 1.f) * 0.5f * (float)(W - 1);
        float y = (gy + 1.f) * 0.5f * (float)(H - 1);
        float x0f = floorf(x), y0f = floorf(y);
        float wx1 = x - x0f, wx0 = 1.f - wx1;
        float wy1 = y - y0f, wy0 = 1.f - wy1;
        #pragma unroll
        for (int c4 = 0; c4 < 4; c4++) {
            int dx = c4 & 1, dy = c4 >> 1;
            float xf = x0f + (float)dx, yf = y0f + (float)dy;
            bool inb = (xf >= 0.f) && (xf <= (float)(W - 1)) && (yf >= 0.f) && (yf <= (float)(H - 1));
            int xi = min(max((int)xf, 0), W - 1);
            int yi = min(max((int)yf, 0), H - 1);
            s_w[qy][t][c4] = inb ? (dx ? wx1 : wx0) * (dy ? wy1 : wy0) : 0.f;
            s_p[qy][t][c4] = base + (((size_t)bv * H + yi) * W + xi) * CC;
        }
    }
    __syncthreads();
    if (tid < 4) {
        float c = 0.f;
        for (int t = 0; t < 24; t++) c += s_valid[tid][t] ? 1.f : 0.f;
        s_cnt[tid] = 0.5f / fmaxf(c, 1.f);
    }
    __syncthreads();

    int qy = threadIdx.y, c = threadIdx.x * 4;
    float4 acc = make_float4(0.f, 0.f, 0.f, 0.f);
    #pragma unroll 4
    for (int t = 0; t < 48; t++) {
        if (!s_valid[qy][t]) continue;
        #pragma unroll
        for (int j = 0; j < 4; j++) {
            float w = s_w[qy][t][j];
            uint2 raw = *(const uint2*)(s_p[qy][t][j] + c);
            __half2 h0 = *reinterpret_cast<__half2*>(&raw.x);
            __half2 h1 = *reinterpret_cast<__half2*>(&raw.y);
            float2 f0 = __half22float2(h0);
            float2 f1 = __half22float2(h1);
            acc.x = fmaf(w, f0.x, acc.x);
            acc.y = fmaf(w, f0.y, acc.y);
            acc.z = fmaf(w, f1.x, acc.z);
            acc.w = fmaf(w, f1.y, acc.w);
        }
    }
    float sc = s_cnt[qy];
    int bq = bq0 + qy;
    *(float4*)(g_sampled + (size_t)bq * CC + c) =
        make_float4(acc.x * sc, acc.y * sc, acc.z * sc, acc.w * sc);
}

// ---------------- TF32 mma helpers ----------------
__device__ __forceinline__ uint32_t f2tf(float x) {
    uint32_t r;
    asm("cvt.rna.tf32.f32 %0, %1;" : "=r"(r) : "f"(x));
    return r;
}

__device__ __forceinline__ void mma8(float* c, const uint32_t* a, const uint32_t* b) {
    asm volatile(
        "mma.sync.aligned.m16n8k8.row.col.f32.tf32.tf32.f32 "
        "{%0,%1,%2,%3},{%4,%5,%6,%7},{%8,%9},{%0,%1,%2,%3};\n"
        : "+f"(c[0]), "+f"(c[1]), "+f"(c[2]), "+f"(c[3])
        : "r"(a[0]), "r"(a[1]), "r"(a[2]), "r"(a[3]), "r"(b[0]), "r"(b[1]));
}

// ---------------- pipelined projection GEMM (128x64 tile, B [N,K] row-major) ----------------
#define GEMM_SMEM (2*128*36*4 + 2*32*72*4)
__device__ __forceinline__ void gemm_body(
    const float* __restrict__ A, const float* __restrict__ B,
    float* __restrict__ C, const float* __restrict__ bias,
    int M, int N, int K, int lda, int ldb, int ldc, float alpha)
{
    extern __shared__ uint32_t gsm[];
    uint32_t (*As)[128][36] = (uint32_t(*)[128][36])gsm;
    uint32_t (*Bs)[32][72]  = (uint32_t(*)[32][72])(gsm + 2*128*36);
    int tid = threadIdx.x;
    int warp = tid >> 5, lane = tid & 31;
    int g = lane >> 2, tg = lane & 3;
    int wm0 = (warp >> 1) * 32, wn0 = (warp & 1) * 32;
    int m0 = blockIdx.y * 128, n0 = blockIdx.x * 64;
    float acc[2][4][4] = {};

    int arow = tid >> 3, ac4 = (tid & 7) * 4;
    int brow = tid >> 3, bc4 = (tid & 7) * 4;

    float4 aR[4], bR[2];
    auto loadA = [&](int k0) {
        #pragma unroll
        for (int i = 0; i < 4; i++) {
            int row = arow + i * 32;
            int gm = m0 + row, gk = k0 + ac4;
            aR[i] = (gm < M) ? *(const float4*)(A + (size_t)gm * lda + gk)
                             : make_float4(0.f, 0.f, 0.f, 0.f);
        }
    };
    auto loadB = [&](int k0) {
        #pragma unroll
        for (int i = 0; i < 2; i++) {
            int n = brow + i * 32;
            int gn = n0 + n, gk = k0 + bc4;
            bR[i] = (gn < N) ? *(const float4*)(B + (size_t)gn * ldb + gk)
                             : make_float4(0.f, 0.f, 0.f, 0.f);
        }
    };
    auto stage = [&](int buf) {
        #pragma unroll
        for (int i = 0; i < 4; i++) {
            int row = arow + i * 32;
            As[buf][row][ac4+0] = f2tf(aR[i].x);
            As[buf][row][ac4+1] = f2tf(aR[i].y);
            As[buf][row][ac4+2] = f2tf(aR[i].z);
            As[buf][row][ac4+3] = f2tf(aR[i].w);
        }
        #pragma unroll
        for (int i = 0; i < 2; i++) {
            int n = brow + i * 32;
            Bs[buf][bc4+0][n] = f2tf(bR[i].x);
            Bs[buf][bc4+1][n] = f2tf(bR[i].y);
            Bs[buf][bc4+2][n] = f2tf(bR[i].z);
            Bs[buf][bc4+3][n] = f2tf(bR[i].w);
        }
    };

    loadA(0); loadB(0);
    int nk = K >> 5;
    int buf = 0;
    for (int kt = 0; kt < nk; kt++) {
        stage(buf);
        __syncthreads();
        if (kt + 1 < nk) { loadA((kt + 1) * 32); loadB((kt + 1) * 32); }
        #pragma unroll
        for (int kk = 0; kk < 32; kk += 8) {
            uint32_t a[2][4], bfr[4][2];
            #pragma unroll
            for (int mi = 0; mi < 2; mi++) {
                int r = wm0 + mi * 16 + g;
                a[mi][0] = As[buf][r][kk + tg];
                a[mi][1] = As[buf][r + 8][kk + tg];
                a[mi][2] = As[buf][r][kk + tg + 4];
                a[mi][3] = As[buf][r + 8][kk + tg + 4];
            }
            #pragma unroll
            for (int ni = 0; ni < 4; ni++) {
                int cn = wn0 + ni * 8 + g;
                bfr[ni][0] = Bs[buf][kk + tg][cn];
                bfr[ni][1] = Bs[buf][kk + tg + 4][cn];
            }
            #pragma unroll
            for (int mi = 0; mi < 2; mi++)
                #pragma unroll
                for (int ni = 0; ni < 4; ni++)
                    mma8(acc[mi][ni], a[mi], bfr[ni]);
        }
        buf ^= 1;
    }

    #pragma unroll
    for (int mi = 0; mi < 2; mi++) {
        #pragma unroll
        for (int ni = 0; ni < 4; ni++) {
            int r0 = m0 + wm0 + mi * 16 + g;
            int cc0 = n0 + wn0 + ni * 8 + tg * 2;
            #pragma unroll
            for (int e = 0; e < 4; e++) {
                int r = r0 + (e >> 1) * 8;
                int cn = cc0 + (e & 1);
                if (r < M && cn < N) {
                    float val = acc[mi][ni][e] * alpha;
                    if (bias) val += bias[cn];
                    C[(size_t)r * ldc + cn] = val;
                }
            }
        }
    }
}

__global__ void gemm_proj(const float* __restrict__ A, const float* __restrict__ B,
                          float* __restrict__ C, const float* __restrict__ bias) {
    gemm_body(A, B, C, bias, BB * QQ, CC, CC, CC, CC, CC, 1.f);
}

__global__ void gemm_qkv(const float* __restrict__ qry, const float* __restrict__ sampled,
                         const float* __restrict__ Wq, const float* __restrict__ Wk,
                         const float* __restrict__ Wv,
                         const float* __restrict__ bq, const float* __restrict__ bk,
                         const float* __restrict__ bv,
                         float* __restrict__ qp, float* __restrict__ kp, float* __restrict__ vp) {
    int z = blockIdx.z;
    const float* A = (z == 0) ? qry : sampled;
    const float* B = (z == 0) ? Wq : ((z == 1) ? Wk : Wv);
    const float* bi = (z == 0) ? bq : ((z == 1) ? bk : bv);
    float* C = (z == 0) ? qp : ((z == 1) ? kp : vp);
    gemm_body(A, B, C, bi, BB * QQ, CC, CC, CC, CC, CC, 1.f);
}

// ---------------- fused flash attention v2 ----------------
#define FLASH_SMEM ((128*36 + 2*32*72 + 2*64*40 + 128*68) * 4)
#define NIT ((QQ + 63) / 64)

__global__ void flash_kernel(const float* __restrict__ qp, const float* __restrict__ kp,
                             const float* __restrict__ vp, float* __restrict__ attno) {
    extern __shared__ uint32_t fsm[];
    uint32_t (*Qs)[36]     = (uint32_t(*)[36])fsm;
    uint32_t (*Ks)[32][72] = (uint32_t(*)[32][72])(fsm + 128*36);
    uint32_t (*Vs)[64][40] = (uint32_t(*)[64][40])(fsm + 128*36 + 2*32*72);
    uint32_t (*Ps)[68]     = (uint32_t(*)[68])(fsm + 128*36 + 2*32*72 + 2*64*40);

    int z = blockIdx.y;
    int b = z / NH, h = z % NH;
    int q0 = blockIdx.x * 128;
    int tid = threadIdx.x;
    int warp = tid >> 5, lane = tid & 31;
    int g = lane >> 2, tg = lane & 3;
    int wr0 = warp * 16;

    const float* qbase = qp + (size_t)b * QQ * CC + h * HD;
    const float* kbase = kp + (size_t)b * QQ * CC + h * HD;
    const float* vbase = vp + (size_t)b * QQ * CC + h * HD;

    #pragma unroll
    for (int i = 0; i < 4; i++) {
        int lin = tid + i * 256;
        int row = lin >> 3, c4 = (lin & 7) * 4;
        float4 v = make_float4(0.f, 0.f, 0.f, 0.f);
        if (q0 + row < QQ) v = *(const float4*)(qbase + (size_t)(q0 + row) * CC + c4);
        Qs[row][c4+0] = f2tf(v.x * ATT_SCALE);
        Qs[row][c4+1] = f2tf(v.y * ATT_SCALE);
        Qs[row][c4+2] = f2tf(v.z * ATT_SCALE);
        Qs[row][c4+3] = f2tf(v.w * ATT_SCALE);
    }

    int kvrow0 = tid >> 3, kvc4 = (tid & 7) * 4;
    float4 kr[2], vr[2];
    auto loadKV = [&](int k0) {
        #pragma unroll
        for (int j = 0; j < 2; j++) {
            int row = kvrow0 + j * 32;
            int gk = k0 + row;
            if (gk < QQ) {
                kr[j] = *(const float4*)(kbase + (size_t)gk * CC + kvc4);
                vr[j] = *(const float4*)(vbase + (size_t)gk * CC + kvc4);
            } else {
                kr[j] = make_float4(0.f, 0.f, 0.f, 0.f);
                vr[j] = kr[j];
            }
        }
    };
    auto stageKV = [&](int buf) {
        #pragma unroll
        for (int j = 0; j < 2; j++) {
            int row = kvrow0 + j * 32;
            Ks[buf][kvc4+0][row] = f2tf(kr[j].x);
            Ks[buf][kvc4+1][row] = f2tf(kr[j].y);
            Ks[buf][kvc4+2][row] = f2tf(kr[j].z);
            Ks[buf][kvc4+3][row] = f2tf(kr[j].w);
            Vs[buf][row][kvc4+0] = f2tf(vr[j].x);
            Vs[buf][row][kvc4+1] = f2tf(vr[j].y);
            Vs[buf][row][kvc4+2] = f2tf(vr[j].z);
            Vs[buf][row][kvc4+3] = f2tf(vr[j].w);
        }
    };

    float m0r = -1e30f, m1r = -1e30f;
    float l0 = 0.f, l1 = 0.f;
    float oacc[4][4] = {};

    loadKV(0);
    int buf = 0;
    for (int it = 0; it < NIT; it++) {
        stageKV(buf);
        __syncthreads();
        if (it + 1 < NIT) loadKV((it + 1) * 64);

        float sacc[8][4] = {};
        #pragma unroll
        for (int kk = 0; kk < 32; kk += 8) {
            uint32_t a[4];
            a[0] = Qs[wr0 + g][kk + tg];
            a[1] = Qs[wr0 + g + 8][kk + tg];
            a[2] = Qs[wr0 + g][kk + tg + 4];
            a[3] = Qs[wr0 + g + 8][kk + tg + 4];
            #pragma unroll
            for (int ni = 0; ni < 8; ni++) {
                uint32_t bf[2];
                int cn = ni * 8 + g;
                bf[0] = Ks[buf][kk + tg][cn];
                bf[1] = Ks[buf][kk + tg + 4][cn];
                mma8(sacc[ni], a, bf);
            }
        }

        int cbase = it * 64;
        float r0 = -1e30f, r1 = -1e30f;
        #pragma unroll
        for (int ni = 0; ni < 8; ni++) {
            #pragma unroll
            for (int e = 0; e < 4; e++) {
                int gk = cbase + ni * 8 + tg * 2 + (e & 1);
                float s = sacc[ni][e];
                if (gk >= QQ) s = -1e30f;
                sacc[ni][e] = s;
                if (e < 2) r0 = fmaxf(r0, s); else r1 = fmaxf(r1, s);
            }
        }
        r0 = fmaxf(r0, __shfl_xor_sync(0xffffffffu, r0, 1));
        r0 = fmaxf(r0, __shfl_xor_sync(0xffffffffu, r0, 2));
        r1 = fmaxf(r1, __shfl_xor_sync(0xffffffffu, r1, 1));
        r1 = fmaxf(r1, __shfl_xor_sync(0xffffffffu, r1, 2));

        float nm0 = fmaxf(m0r, r0), nm1 = fmaxf(m1r, r1);
        float sc0 = __expf(m0r - nm0), sc1 = __expf(m1r - nm1);
        m0r = nm0; m1r = nm1;

        float s0 = 0.f, s1 = 0.f;
        #pragma unroll
        for (int ni = 0; ni < 8; ni++) {
            #pragma unroll
            for (int e = 0; e < 4; e++) {
                float mr = (e < 2) ? m0r : m1r;
                float p = __expf(sacc[ni][e] - mr);
                Ps[wr0 + g + ((e >> 1) << 3)][ni * 8 + tg * 2 + (e & 1)] = f2tf(p);
                if (e < 2) s0 += p; else s1 += p;
            }
        }
        s0 += __shfl_xor_sync(0xffffffffu, s0, 1);
        s0 += __shfl_xor_sync(0xffffffffu, s0, 2);
        s1 += __shfl_xor_sync(0xffffffffu, s1, 1);
        s1 += __shfl_xor_sync(0xffffffffu, s1, 2);
        l0 = l0 * sc0 + s0;
        l1 = l1 * sc1 + s1;

        #pragma unroll
        for (int ni = 0; ni < 4; ni++) {
            oacc[ni][0] *= sc0; oacc[ni][1] *= sc0;
            oacc[ni][2] *= sc1; oacc[ni][3] *= sc1;
        }
        __syncwarp();

        #pragma unroll
        for (int kk = 0; kk < 64; kk += 8) {
            uint32_t a[4];
            a[0] = Ps[wr0 + g][kk + tg];
            a[1] = Ps[wr0 + g + 8][kk + tg];
            a[2] = Ps[wr0 + g][kk + tg + 4];
            a[3] = Ps[wr0 + g + 8][kk + tg + 4];
            #pragma unroll
            for (int ni = 0; ni < 4; ni++) {
                uint32_t bf[2];
                int cn = ni * 8 + g;
                bf[0] = Vs[buf][kk + tg][cn];
                bf[1] = Vs[buf][kk + tg + 4][cn];
                mma8(oacc[ni], a, bf);
            }
        }
        buf ^= 1;
    }

    float li0 = 1.f / l0, li1 = 1.f / l1;
    #pragma unroll
    for (int ni = 0; ni < 4; ni++) {
        #pragma unroll
        for (int e = 0; e < 4; e++) {
            int row = wr0 + g + ((e >> 1) << 3);
            int col = ni * 8 + tg * 2 + (e & 1);
            int q = q0 + row;
            if (q < QQ)
                attno[((size_t)b * QQ + q) * CC + h * HD + col] =
                    oacc[ni][e] * ((e < 2) ? li0 : li1);
        }
    }
}

// ---------------- host launcher ----------------
extern "C" void kernel_launch(void* const* d_in, const int* in_sizes, int n_in,
                              void* d_out, int out_size) {
    const float* f0   = (const float*)d_in[0];
    const float* f1   = (const float*)d_in[1];
    const float* refs = (const float*)d_in[2];
    const float* intr = (const float*)d_in[3];
    const float* extr = (const float*)d_in[4];
    const float* qry  = (const float*)d_in[5];
    const float* Wq   = (const float*)d_in[6];
    const float* bq   = (const float*)d_in[7];
    const float* Wk   = (const float*)d_in[8];
    const float* bk   = (const float*)d_in[9];
    const float* Wv   = (const float*)d_in[10];
    const float* bv   = (const float*)d_in[11];
    const float* Wo   = (const float*)d_in[12];
    const float* bo   = (const float*)d_in[13];
    float* out = (float*)d_out;

    __half *featT0, *featT1;
    float *sampled, *qp, *kp, *vp, *attno;
    cudaGetSymbolAddress((void**)&featT0, g_featT0);
    cudaGetSymbolAddress((void**)&featT1, g_featT1);
    cudaGetSymbolAddress((void**)&sampled, g_sampled);
    cudaGetSymbolAddress((void**)&qp, g_qp);
    cudaGetSymbolAddress((void**)&kp, g_kp);
    cudaGetSymbolAddress((void**)&vp, g_vp);
    cudaGetSymbolAddress((void**)&attno, g_attno);

    cudaFuncSetAttribute(gemm_qkv, cudaFuncAttributeMaxDynamicSharedMemorySize, GEMM_SMEM);
    cudaFuncSetAttribute(gemm_proj, cudaFuncAttributeMaxDynamicSharedMemorySize, GEMM_SMEM);
    cudaFuncSetAttribute(flash_kernel, cudaFuncAttributeMaxDynamicSharedMemorySize, FLASH_SMEM);

    dim3 tt(32, 8);
    transpose_kernel<<<dim3((H0 * W0) / 32, CC / 32, BB * VV), tt>>>(f0, featT0, H0 * W0);
    transpose_kernel<<<dim3((H1 * W1) / 32, CC / 32, BB * VV), tt>>>(f1, featT1, H1 * W1);
    sample_kernel<<<(BB * QQ) / 4, dim3(64, 4)>>>(refs, intr, extr);

    const int M = BB * QQ;  // 1800
    gemm_qkv<<<dim3(CC / 64, (M + 127) / 128, 3), 256, GEMM_SMEM>>>(
        qry, sampled, Wq, Wk, Wv, bq, bk, bv, qp, kp, vp);

    flash_kernel<<<dim3((QQ + 127) / 128, BB * NH), 256, FLASH_SMEM>>>(qp, kp, vp, attno);

    gemm_proj<<<dim3(CC / 64, (M + 127) / 128), 256, GEMM_SMEM>>>(attno, Wo, out, bo);
}

// round 8
// speedup vs baseline: 3.0184x; 1.0794x over previous
#include <cuda_runtime.h>
#include <cuda_fp16.h>
#include <math.h>
#include <stdint.h>

#define BB 2
#define VV 6
#define CC 256
#define QQ 900
#define KP 4
#define H0 64
#define W0 176
#define H1 32
#define W1 88
#define NH 8
#define HD 32
#define ATT_SCALE 0.17677669529663689f

// ---------------- scratch (device globals; no runtime allocation) ----------------
__device__ __half g_featT0[(size_t)BB*VV*H0*W0*CC];   // [B,V,H,W,C] fp16
__device__ __half g_featT1[(size_t)BB*VV*H1*W1*CC];
__device__ float  g_sampled[BB*QQ*CC];
__device__ float  g_qp[BB*QQ*CC];
__device__ float  g_kp[BB*QQ*CC];
__device__ float  g_vp[BB*QQ*CC];
__device__ float  g_attno[BB*QQ*CC];

// ---------------- feature transpose: [bv, C, HW] -> [bv, HW, C] fp32 -> fp16 ----------------
__global__ void transpose_kernel(const float* __restrict__ in, __half* __restrict__ out, int HW) {
    __shared__ float tile[32][33];
    int bv = blockIdx.z;
    int c0 = blockIdx.y * 32, p0 = blockIdx.x * 32;
    const float* src = in  + (size_t)bv * CC * HW;
    __half*      dst = out + (size_t)bv * HW * CC;
    int tx = threadIdx.x, ty = threadIdx.y;
    #pragma unroll
    for (int i = 0; i < 32; i += 8) {
        int c = c0 + ty + i, p = p0 + tx;
        if (c < CC && p < HW) tile[ty + i][tx] = src[(size_t)c * HW + p];
    }
    __syncthreads();
    #pragma unroll
    for (int i = 0; i < 32; i += 8) {
        int p = p0 + ty + i, c = c0 + tx;
        if (p < HW && c < CC) dst[(size_t)p * CC + c] = __float2half(tile[tx][ty + i]);
    }
}

// ---------------- sampling: proj fused into setup; 4 queries/block, fp16 features ----------------
__global__ void sample_kernel(const float* __restrict__ refs,
                              const float* __restrict__ intr,
                              const float* __restrict__ extr) {
    __shared__ float         s_w[4][48][4];
    __shared__ const __half* s_p[4][48][4];
    __shared__ int           s_valid[4][48];
    __shared__ float         s_cnt[4];
    int tid = threadIdx.y * 64 + threadIdx.x;
    int bq0 = blockIdx.x * 4;

    if (tid < 192) {
        int qy = tid / 48, t = tid % 48;
        int bq = bq0 + qy;
        int b = bq / QQ, q = bq % QQ;
        int level = t / 24, r = t % 24, v = r >> 2, k = r & 3;
        int bv = b * VV + v;
        const float kpx[4] = {0.f, 2.f, 0.f, -2.f};
        const float kpy[4] = {0.f, 0.f, 2.f, 0.f};
        const float* rp = refs + (b * QQ + q) * 3;
        float rx = rp[0] + kpx[k], ry = rp[1] + kpy[k], rz = rp[2];
        const float* E = extr + bv * 16;
        float c0 = E[0]*rx + E[1]*ry + E[2]*rz + E[3];
        float c1 = E[4]*rx + E[5]*ry + E[6]*rz + E[7];
        float c2 = E[8]*rx + E[9]*ry + E[10]*rz + E[11];
        const float* I = intr + bv * 9;
        float u  = I[0]*c0 + I[1]*c1 + I[2]*c2;
        float w_ = I[3]*c0 + I[4]*c1 + I[5]*c2;
        float z  = I[6]*c0 + I[7]*c1 + I[8]*c2;
        float zs = (fabsf(z) > 1e-6f) ? z : 1e-6f;
        float uz = u / zs, vz = w_ / zs;
        s_valid[qy][t] = (z > 0.f);
        int H = level ? H1 : H0, W = level ? W1 : W0;
        const __half* base = level ? g_featT1 : g_featT0;
        float gx = 2.f * uz / (float)(W - 1) - 1.f;
        float gy = 2.f * vz / (float)(H - 1) - 1.f;
        float x = (gx + 1.f) * 0.5f * (float)(W - 1);
        float y = (gy + 1.f) * 0.5f * (float)(H - 1);
        float x0f = floorf(x), y0f = floorf(y);
        float wx1 = x - x0f, wx0 = 1.f - wx1;
        float wy1 = y - y0f, wy0 = 1.f - wy1;
        #pragma unroll
        for (int c4 = 0; c4 < 4; c4++) {
            int dx = c4 & 1, dy = c4 >> 1;
            float xf = x0f + (float)dx, yf = y0f + (float)dy;
            bool inb = (xf >= 0.f) && (xf <= (float)(W - 1)) && (yf >= 0.f) && (yf <= (float)(H - 1));
            int xi = min(max((int)xf, 0), W - 1);
            int yi = min(max((int)yf, 0), H - 1);
            s_w[qy][t][c4] = inb ? (dx ? wx1 : wx0) * (dy ? wy1 : wy0) : 0.f;
            s_p[qy][t][c4] = base + (((size_t)bv * H + yi) * W + xi) * CC;
        }
    }
    __syncthreads();
    if (tid < 4) {
        float c = 0.f;
        for (int t = 0; t < 24; t++) c += s_valid[tid][t] ? 1.f : 0.f;
        s_cnt[tid] = 0.5f / fmaxf(c, 1.f);
    }
    __syncthreads();

    int qy = threadIdx.y, c = threadIdx.x * 4;
    float4 acc = make_float4(0.f, 0.f, 0.f, 0.f);
    #pragma unroll 4
    for (int t = 0; t < 48; t++) {
        if (!s_valid[qy][t]) continue;
        #pragma unroll
        for (int j = 0; j < 4; j++) {
            float w = s_w[qy][t][j];
            uint2 raw = *(const uint2*)(s_p[qy][t][j] + c);
            __half2 h0 = *reinterpret_cast<__half2*>(&raw.x);
            __half2 h1 = *reinterpret_cast<__half2*>(&raw.y);
            float2 f0 = __half22float2(h0);
            float2 f1 = __half22float2(h1);
            acc.x = fmaf(w, f0.x, acc.x);
            acc.y = fmaf(w, f0.y, acc.y);
            acc.z = fmaf(w, f1.x, acc.z);
            acc.w = fmaf(w, f1.y, acc.w);
        }
    }
    float sc = s_cnt[qy];
    int bq = bq0 + qy;
    *(float4*)(g_sampled + (size_t)bq * CC + c) =
        make_float4(acc.x * sc, acc.y * sc, acc.z * sc, acc.w * sc);
}

// ---------------- mma helpers ----------------
__device__ __forceinline__ uint32_t f2tf(float x) {
    uint32_t r;
    asm("cvt.rna.tf32.f32 %0, %1;" : "=r"(r) : "f"(x));
    return r;
}

__device__ __forceinline__ uint32_t f22h(float x, float y) {
    __half2 h = __floats2half2_rn(x, y);
    return *reinterpret_cast<uint32_t*>(&h);
}

__device__ __forceinline__ void mma8(float* c, const uint32_t* a, const uint32_t* b) {
    asm volatile(
        "mma.sync.aligned.m16n8k8.row.col.f32.tf32.tf32.f32 "
        "{%0,%1,%2,%3},{%4,%5,%6,%7},{%8,%9},{%0,%1,%2,%3};\n"
        : "+f"(c[0]), "+f"(c[1]), "+f"(c[2]), "+f"(c[3])
        : "r"(a[0]), "r"(a[1]), "r"(a[2]), "r"(a[3]), "r"(b[0]), "r"(b[1]));
}

__device__ __forceinline__ void mma16(float* c, const uint32_t* a, const uint32_t* b) {
    asm volatile(
        "mma.sync.aligned.m16n8k16.row.col.f32.f16.f16.f32 "
        "{%0,%1,%2,%3},{%4,%5,%6,%7},{%8,%9},{%0,%1,%2,%3};\n"
        : "+f"(c[0]), "+f"(c[1]), "+f"(c[2]), "+f"(c[3])
        : "r"(a[0]), "r"(a[1]), "r"(a[2]), "r"(a[3]), "r"(b[0]), "r"(b[1]));
}

// ---------------- pipelined projection GEMM (64x64 tile, B [N,K] row-major) ----------------
#define GEMM_SMEM ((2*64*36 + 2*32*72) * 4)
__device__ __forceinline__ void gemm_body(
    const float* __restrict__ A, const float* __restrict__ B,
    float* __restrict__ C, const float* __restrict__ bias,
    int M, int N, int K, int lda, int ldb, int ldc, float alpha)
{
    extern __shared__ uint32_t gsm[];
    uint32_t (*As)[64][36] = (uint32_t(*)[64][36])gsm;
    uint32_t (*Bs)[32][72] = (uint32_t(*)[32][72])(gsm + 2*64*36);
    int tid = threadIdx.x;
    int warp = tid >> 5, lane = tid & 31;
    int g = lane >> 2, tg = lane & 3;
    int wm0 = (warp >> 1) * 16, wn0 = (warp & 1) * 32;
    int m0 = blockIdx.y * 64, n0 = blockIdx.x * 64;
    float acc[4][4] = {};

    int arow = tid >> 3, ac4 = (tid & 7) * 4;

    float4 aR[2], bR[2];
    auto loadA = [&](int k0) {
        #pragma unroll
        for (int i = 0; i < 2; i++) {
            int row = arow + i * 32;
            int gm = m0 + row, gk = k0 + ac4;
            aR[i] = (gm < M) ? *(const float4*)(A + (size_t)gm * lda + gk)
                             : make_float4(0.f, 0.f, 0.f, 0.f);
        }
    };
    auto loadB = [&](int k0) {
        #pragma unroll
        for (int i = 0; i < 2; i++) {
            int n = arow + i * 32;
            int gn = n0 + n, gk = k0 + ac4;
            bR[i] = (gn < N) ? *(const float4*)(B + (size_t)gn * ldb + gk)
                             : make_float4(0.f, 0.f, 0.f, 0.f);
        }
    };
    auto stage = [&](int buf) {
        #pragma unroll
        for (int i = 0; i < 2; i++) {
            int row = arow + i * 32;
            As[buf][row][ac4+0] = f2tf(aR[i].x);
            As[buf][row][ac4+1] = f2tf(aR[i].y);
            As[buf][row][ac4+2] = f2tf(aR[i].z);
            As[buf][row][ac4+3] = f2tf(aR[i].w);
        }
        #pragma unroll
        for (int i = 0; i < 2; i++) {
            int n = arow + i * 32;
            Bs[buf][ac4+0][n] = f2tf(bR[i].x);
            Bs[buf][ac4+1][n] = f2tf(bR[i].y);
            Bs[buf][ac4+2][n] = f2tf(bR[i].z);
            Bs[buf][ac4+3][n] = f2tf(bR[i].w);
        }
    };

    loadA(0); loadB(0);
    int nk = K >> 5;
    int buf = 0;
    for (int kt = 0; kt < nk; kt++) {
        stage(buf);
        __syncthreads();
        if (kt + 1 < nk) { loadA((kt + 1) * 32); loadB((kt + 1) * 32); }
        #pragma unroll
        for (int kk = 0; kk < 32; kk += 8) {
            uint32_t a[4], bfr[4][2];
            a[0] = As[buf][wm0 + g][kk + tg];
            a[1] = As[buf][wm0 + g + 8][kk + tg];
            a[2] = As[buf][wm0 + g][kk + tg + 4];
            a[3] = As[buf][wm0 + g + 8][kk + tg + 4];
            #pragma unroll
            for (int ni = 0; ni < 4; ni++) {
                int cn = wn0 + ni * 8 + g;
                bfr[ni][0] = Bs[buf][kk + tg][cn];
                bfr[ni][1] = Bs[buf][kk + tg + 4][cn];
            }
            #pragma unroll
            for (int ni = 0; ni < 4; ni++)
                mma8(acc[ni], a, bfr[ni]);
        }
        buf ^= 1;
    }

    #pragma unroll
    for (int ni = 0; ni < 4; ni++) {
        int r0 = m0 + wm0 + g;
        int cc0 = n0 + wn0 + ni * 8 + tg * 2;
        #pragma unroll
        for (int e = 0; e < 4; e++) {
            int r = r0 + (e >> 1) * 8;
            int cn = cc0 + (e & 1);
            if (r < M && cn < N) {
                float val = acc[ni][e] * alpha;
                if (bias) val += bias[cn];
                C[(size_t)r * ldc + cn] = val;
            }
        }
    }
}

__global__ void gemm_proj(const float* __restrict__ A, const float* __restrict__ B,
                          float* __restrict__ C, const float* __restrict__ bias) {
    gemm_body(A, B, C, bias, BB * QQ, CC, CC, CC, CC, CC, 1.f);
}

__global__ void gemm_qkv(const float* __restrict__ qry, const float* __restrict__ sampled,
                         const float* __restrict__ Wq, const float* __restrict__ Wk,
                         const float* __restrict__ Wv,
                         const float* __restrict__ bq, const float* __restrict__ bk,
                         const float* __restrict__ bv,
                         float* __restrict__ qp, float* __restrict__ kp, float* __restrict__ vp) {
    int z = blockIdx.z;
    const float* A = (z == 0) ? qry : sampled;
    const float* B = (z == 0) ? Wq : ((z == 1) ? Wk : Wv);
    const float* bi = (z == 0) ? bq : ((z == 1) ? bk : bv);
    float* C = (z == 0) ? qp : ((z == 1) ? kp : vp);
    gemm_body(A, B, C, bi, BB * QQ, CC, CC, CC, CC, CC, 1.f);
}

// ---------------- fused flash attention v3 (fp16 m16n8k16) ----------------
// smem words: Qs[128][18] | Ks[2][16][68] | Vs[2][32][36] | Ps[128][34]
#define FLASH_SMEM ((128*18 + 2*16*68 + 2*32*36 + 128*34) * 4)
#define NIT ((QQ + 63) / 64)

__global__ void flash_kernel(const float* __restrict__ qp, const float* __restrict__ kp,
                             const float* __restrict__ vp, float* __restrict__ attno) {
    extern __shared__ uint32_t fsm[];
    uint32_t (*Qs)[18]     = (uint32_t(*)[18])fsm;                         // [row][ch2]
    uint32_t (*Ks)[16][68] = (uint32_t(*)[16][68])(fsm + 128*18);          // [ch2][key]
    uint32_t (*Vs)[32][36] = (uint32_t(*)[32][36])(fsm + 128*18 + 2*16*68);// [key2][ch]
    uint32_t (*Ps)[34]     = (uint32_t(*)[34])(fsm + 128*18 + 2*16*68 + 2*32*36); // [row][key2]

    int z = blockIdx.y;
    int b = z / NH, h = z % NH;
    int q0 = blockIdx.x * 128;
    int tid = threadIdx.x;
    int warp = tid >> 5, lane = tid & 31;
    int g = lane >> 2, tg = lane & 3;
    int wr0 = warp * 16;

    const float* qbase = qp + (size_t)b * QQ * CC + h * HD;
    const float* kbase = kp + (size_t)b * QQ * CC + h * HD;
    const float* vbase = vp + (size_t)b * QQ * CC + h * HD;

    // stage Q (scale folded): 128 rows x 32 ch -> half2 [row][ch2]
    #pragma unroll
    for (int i = 0; i < 4; i++) {
        int lin = tid + i * 256;
        int row = lin >> 3, ch2 = (lin & 7) * 2, c4 = (lin & 7) * 4;
        float4 v = make_float4(0.f, 0.f, 0.f, 0.f);
        if (q0 + row < QQ) v = *(const float4*)(qbase + (size_t)(q0 + row) * CC + c4);
        Qs[row][ch2]     = f22h(v.x * ATT_SCALE, v.y * ATT_SCALE);
        Qs[row][ch2 + 1] = f22h(v.z * ATT_SCALE, v.w * ATT_SCALE);
    }

    // K: thread covers keys (tid>>3, +32) at 4 ch; V: key pair (2*(tid>>3), +1) at 4 ch
    int krow = tid >> 3, kch2 = (tid & 7) * 2, kc4 = (tid & 7) * 4;
    float4 kr[2], va, vb;
    auto loadKV = [&](int k0) {
        #pragma unroll
        for (int j = 0; j < 2; j++) {
            int gk = k0 + krow + j * 32;
            kr[j] = (gk < QQ) ? *(const float4*)(kbase + (size_t)gk * CC + kc4)
                              : make_float4(0.f, 0.f, 0.f, 0.f);
        }
        int gva = k0 + 2 * krow, gvb = gva + 1;
        va = (gva < QQ) ? *(const float4*)(vbase + (size_t)gva * CC + kc4)
                        : make_float4(0.f, 0.f, 0.f, 0.f);
        vb = (gvb < QQ) ? *(const float4*)(vbase + (size_t)gvb * CC + kc4)
                        : make_float4(0.f, 0.f, 0.f, 0.f);
    };
    auto stageKV = [&](int buf) {
        #pragma unroll
        for (int j = 0; j < 2; j++) {
            int key = krow + j * 32;
            Ks[buf][kch2][key]     = f22h(kr[j].x, kr[j].y);
            Ks[buf][kch2 + 1][key] = f22h(kr[j].z, kr[j].w);
        }
        Vs[buf][krow][kc4 + 0] = f22h(va.x, vb.x);
        Vs[buf][krow][kc4 + 1] = f22h(va.y, vb.y);
        Vs[buf][krow][kc4 + 2] = f22h(va.z, vb.z);
        Vs[buf][krow][kc4 + 3] = f22h(va.w, vb.w);
    };

    float m0r = -1e30f, m1r = -1e30f;
    float l0 = 0.f, l1 = 0.f;
    float oacc[4][4] = {};

    loadKV(0);
    int buf = 0;
    for (int it = 0; it < NIT; it++) {
        stageKV(buf);
        __syncthreads();
        if (it + 1 < NIT) loadKV((it + 1) * 64);

        // S = Qs @ K^T : 16 rows x 64 cols per warp, k=32ch in 2 fp16 mma steps
        float sacc[8][4] = {};
        #pragma unroll
        for (int ko = 0; ko < 2; ko++) {
            int koff = ko * 8;
            uint32_t a[4];
            a[0] = Qs[wr0 + g][koff + tg];
            a[1] = Qs[wr0 + g + 8][koff + tg];
            a[2] = Qs[wr0 + g][koff + tg + 4];
            a[3] = Qs[wr0 + g + 8][koff + tg + 4];
            #pragma unroll
            for (int ni = 0; ni < 8; ni++) {
                uint32_t bf[2];
                int cn = ni * 8 + g;
                bf[0] = Ks[buf][koff + tg][cn];
                bf[1] = Ks[buf][koff + tg + 4][cn];
                mma16(sacc[ni], a, bf);
            }
        }

        // mask + rowmax
        int cbase = it * 64;
        float r0 = -1e30f, r1 = -1e30f;
        #pragma unroll
        for (int ni = 0; ni < 8; ni++) {
            #pragma unroll
            for (int e = 0; e < 4; e++) {
                int gk = cbase + ni * 8 + tg * 2 + (e & 1);
                float s = sacc[ni][e];
                if (gk >= QQ) s = -1e30f;
                sacc[ni][e] = s;
                if (e < 2) r0 = fmaxf(r0, s); else r1 = fmaxf(r1, s);
            }
        }
        r0 = fmaxf(r0, __shfl_xor_sync(0xffffffffu, r0, 1));
        r0 = fmaxf(r0, __shfl_xor_sync(0xffffffffu, r0, 2));
        r1 = fmaxf(r1, __shfl_xor_sync(0xffffffffu, r1, 1));
        r1 = fmaxf(r1, __shfl_xor_sync(0xffffffffu, r1, 2));

        float nm0 = fmaxf(m0r, r0), nm1 = fmaxf(m1r, r1);
        float sc0 = __expf(m0r - nm0), sc1 = __expf(m1r - nm1);
        m0r = nm0; m1r = nm1;

        // P = exp(S - m) -> half2 packed [row][key2], warp-private
        float s0 = 0.f, s1 = 0.f;
        #pragma unroll
        for (int ni = 0; ni < 8; ni++) {
            float p0 = __expf(sacc[ni][0] - m0r);
            float p1 = __expf(sacc[ni][1] - m0r);
            float p2 = __expf(sacc[ni][2] - m1r);
            float p3 = __expf(sacc[ni][3] - m1r);
            Ps[wr0 + g][ni * 4 + tg]     = f22h(p0, p1);
            Ps[wr0 + g + 8][ni * 4 + tg] = f22h(p2, p3);
            s0 += p0 + p1;
            s1 += p2 + p3;
        }
        s0 += __shfl_xor_sync(0xffffffffu, s0, 1);
        s0 += __shfl_xor_sync(0xffffffffu, s0, 2);
        s1 += __shfl_xor_sync(0xffffffffu, s1, 1);
        s1 += __shfl_xor_sync(0xffffffffu, s1, 2);
        l0 = l0 * sc0 + s0;
        l1 = l1 * sc1 + s1;

        #pragma unroll
        for (int ni = 0; ni < 4; ni++) {
            oacc[ni][0] *= sc0; oacc[ni][1] *= sc0;
            oacc[ni][2] *= sc1; oacc[ni][3] *= sc1;
        }
        __syncwarp();

        // O += P @ V : k=64 keys in 4 fp16 mma steps
        #pragma unroll
        for (int kk2 = 0; kk2 < 32; kk2 += 8) {
            uint32_t a[4];
            a[0] = Ps[wr0 + g][kk2 + tg];
            a[1] = Ps[wr0 + g + 8][kk2 + tg];
            a[2] = Ps[wr0 + g][kk2 + tg + 4];
            a[3] = Ps[wr0 + g + 8][kk2 + tg + 4];
            #pragma unroll
            for (int ni = 0; ni < 4; ni++) {
                uint32_t bf[2];
                int cn = ni * 8 + g;
                bf[0] = Vs[buf][kk2 + tg][cn];
                bf[1] = Vs[buf][kk2 + tg + 4][cn];
                mma16(oacc[ni], a, bf);
            }
        }
        buf ^= 1;
    }

    float li0 = 1.f / l0, li1 = 1.f / l1;
    #pragma unroll
    for (int ni = 0; ni < 4; ni++) {
        #pragma unroll
        for (int e = 0; e < 4; e++) {
            int row = wr0 + g + ((e >> 1) << 3);
            int col = ni * 8 + tg * 2 + (e & 1);
            int q = q0 + row;
            if (q < QQ)
                attno[((size_t)b * QQ + q) * CC + h * HD + col] =
                    oacc[ni][e] * ((e < 2) ? li0 : li1);
        }
    }
}

// ---------------- host launcher ----------------
extern "C" void kernel_launch(void* const* d_in, const int* in_sizes, int n_in,
                              void* d_out, int out_size) {
    const float* f0   = (const float*)d_in[0];
    const float* f1   = (const float*)d_in[1];
    const float* refs = (const float*)d_in[2];
    const float* intr = (const float*)d_in[3];
    const float* extr = (const float*)d_in[4];
    const float* qry  = (const float*)d_in[5];
    const float* Wq   = (const float*)d_in[6];
    const float* bq   = (const float*)d_in[7];
    const float* Wk   = (const float*)d_in[8];
    const float* bk   = (const float*)d_in[9];
    const float* Wv   = (const float*)d_in[10];
    const float* bv   = (const float*)d_in[11];
    const float* Wo   = (const float*)d_in[12];
    const float* bo   = (const float*)d_in[13];
    float* out = (float*)d_out;

    __half *featT0, *featT1;
    float *sampled, *qp, *kp, *vp, *attno;
    cudaGetSymbolAddress((void**)&featT0, g_featT0);
    cudaGetSymbolAddress((void**)&featT1, g_featT1);
    cudaGetSymbolAddress((void**)&sampled, g_sampled);
    cudaGetSymbolAddress((void**)&qp, g_qp);
    cudaGetSymbolAddress((void**)&kp, g_kp);
    cudaGetSymbolAddress((void**)&vp, g_vp);
    cudaGetSymbolAddress((void**)&attno, g_attno);

    cudaFuncSetAttribute(gemm_qkv, cudaFuncAttributeMaxDynamicSharedMemorySize, GEMM_SMEM);
    cudaFuncSetAttribute(gemm_proj, cudaFuncAttributeMaxDynamicSharedMemorySize, GEMM_SMEM);
    cudaFuncSetAttribute(flash_kernel, cudaFuncAttributeMaxDynamicSharedMemorySize, FLASH_SMEM);

    dim3 tt(32, 8);
    transpose_kernel<<<dim3((H0 * W0) / 32, CC / 32, BB * VV), tt>>>(f0, featT0, H0 * W0);
    transpose_kernel<<<dim3((H1 * W1) / 32, CC / 32, BB * VV), tt>>>(f1, featT1, H1 * W1);
    sample_kernel<<<(BB * QQ) / 4, dim3(64, 4)>>>(refs, intr, extr);

    const int M = BB * QQ;  // 1800
    gemm_qkv<<<dim3(CC / 64, (M + 63) / 64, 3), 256, GEMM_SMEM>>>(
        qry, sampled, Wq, Wk, Wv, bq, bk, bv, qp, kp, vp);

    flash_kernel<<<dim3((QQ + 127) / 128, BB * NH), 256, FLASH_SMEM>>>(qp, kp, vp, attno);

    gemm_proj<<<dim3(CC / 64, (M + 63) / 64), 256, GEMM_SMEM>>>(attno, Wo, out, bo);
}

// round 9
// speedup vs baseline: 3.2786x; 1.0862x over previous
#include <cuda_runtime.h>
#include <cuda_fp16.h>
#include <math.h>
#include <stdint.h>

#define BB 2
#define VV 6
#define CC 256
#define QQ 900
#define KP 4
#define H0 64
#define W0 176
#define H1 32
#define W1 88
#define NH 8
#define HD 32
#define ATT_SCALE 0.17677669529663689f

// ---------------- scratch (device globals; no runtime allocation) ----------------
__device__ __half g_featT0[(size_t)BB*VV*H0*W0*CC];   // [B,V,H,W,C] fp16
__device__ __half g_featT1[(size_t)BB*VV*H1*W1*CC];
__device__ float  g_sampled[BB*QQ*CC];
__device__ float  g_qp[BB*QQ*CC];
__device__ float  g_kp[BB*QQ*CC];
__device__ float  g_vp[BB*QQ*CC];
__device__ float  g_attno[BB*QQ*CC];

// ---------------- feature transpose: [bv, C, HW] -> [bv, HW, C] fp32 -> fp16 ----------------
__global__ void transpose_kernel(const float* __restrict__ in, __half* __restrict__ out, int HW) {
    __shared__ float tile[32][33];
    int bv = blockIdx.z;
    int c0 = blockIdx.y * 32, p0 = blockIdx.x * 32;
    const float* src = in  + (size_t)bv * CC * HW;
    __half*      dst = out + (size_t)bv * HW * CC;
    int tx = threadIdx.x, ty = threadIdx.y;
    #pragma unroll
    for (int i = 0; i < 32; i += 8) {
        int c = c0 + ty + i, p = p0 + tx;
        if (c < CC && p < HW) tile[ty + i][tx] = src[(size_t)c * HW + p];
    }
    __syncthreads();
    #pragma unroll
    for (int i = 0; i < 32; i += 8) {
        int p = p0 + ty + i, c = c0 + tx;
        if (p < HW && c < CC) dst[(size_t)p * CC + c] = __float2half(tile[tx][ty + i]);
    }
}

// ---------------- sampling: proj fused into setup; 4 queries/block, fp16 features ----------------
__global__ void sample_kernel(const float* __restrict__ refs,
                              const float* __restrict__ intr,
                              const float* __restrict__ extr) {
    __shared__ float         s_w[4][48][4];
    __shared__ const __half* s_p[4][48][4];
    __shared__ int           s_valid[4][48];
    __shared__ float         s_cnt[4];
    int tid = threadIdx.y * 64 + threadIdx.x;
    int bq0 = blockIdx.x * 4;

    if (tid < 192) {
        int qy = tid / 48, t = tid % 48;
        int bq = bq0 + qy;
        int b = bq / QQ, q = bq % QQ;
        int level = t / 24, r = t % 24, v = r >> 2, k = r & 3;
        int bv = b * VV + v;
        const float kpx[4] = {0.f, 2.f, 0.f, -2.f};
        const float kpy[4] = {0.f, 0.f, 2.f, 0.f};
        const float* rp = refs + (b * QQ + q) * 3;
        float rx = rp[0] + kpx[k], ry = rp[1] + kpy[k], rz = rp[2];
        const float* E = extr + bv * 16;
        float c0 = E[0]*rx + E[1]*ry + E[2]*rz + E[3];
        float c1 = E[4]*rx + E[5]*ry + E[6]*rz + E[7];
        float c2 = E[8]*rx + E[9]*ry + E[10]*rz + E[11];
        const float* I = intr + bv * 9;
        float u  = I[0]*c0 + I[1]*c1 + I[2]*c2;
        float w_ = I[3]*c0 + I[4]*c1 + I[5]*c2;
        float z  = I[6]*c0 + I[7]*c1 + I[8]*c2;
        float zs = (fabsf(z) > 1e-6f) ? z : 1e-6f;
        float uz = u / zs, vz = w_ / zs;
        s_valid[qy][t] = (z > 0.f);
        int H = level ? H1 : H0, W = level ? W1 : W0;
        const __half* base = level ? g_featT1 : g_featT0;
        float gx = 2.f * uz / (float)(W - 1) - 1.f;
        float gy = 2.f * vz / (float)(H - 1) - 1.f;
        float x = (gx + 1.f) * 0.5f * (float)(W - 1);
        float y = (gy + 1.f) * 0.5f * (float)(H - 1);
        float x0f = floorf(x), y0f = floorf(y);
        float wx1 = x - x0f, wx0 = 1.f - wx1;
        float wy1 = y - y0f, wy0 = 1.f - wy1;
        #pragma unroll
        for (int c4 = 0; c4 < 4; c4++) {
            int dx = c4 & 1, dy = c4 >> 1;
            float xf = x0f + (float)dx, yf = y0f + (float)dy;
            bool inb = (xf >= 0.f) && (xf <= (float)(W - 1)) && (yf >= 0.f) && (yf <= (float)(H - 1));
            int xi = min(max((int)xf, 0), W - 1);
            int yi = min(max((int)yf, 0), H - 1);
            s_w[qy][t][c4] = inb ? (dx ? wx1 : wx0) * (dy ? wy1 : wy0) : 0.f;
            s_p[qy][t][c4] = base + (((size_t)bv * H + yi) * W + xi) * CC;
        }
    }
    __syncthreads();
    if (tid < 4) {
        float c = 0.f;
        for (int t = 0; t < 24; t++) c += s_valid[tid][t] ? 1.f : 0.f;
        s_cnt[tid] = 0.5f / fmaxf(c, 1.f);
    }
    __syncthreads();

    int qy = threadIdx.y, c = threadIdx.x * 4;
    float4 acc = make_float4(0.f, 0.f, 0.f, 0.f);
    #pragma unroll 4
    for (int t = 0; t < 48; t++) {
        if (!s_valid[qy][t]) continue;
        #pragma unroll
        for (int j = 0; j < 4; j++) {
            float w = s_w[qy][t][j];
            uint2 raw = *(const uint2*)(s_p[qy][t][j] + c);
            __half2 h0 = *reinterpret_cast<__half2*>(&raw.x);
            __half2 h1 = *reinterpret_cast<__half2*>(&raw.y);
            float2 f0 = __half22float2(h0);
            float2 f1 = __half22float2(h1);
            acc.x = fmaf(w, f0.x, acc.x);
            acc.y = fmaf(w, f0.y, acc.y);
            acc.z = fmaf(w, f1.x, acc.z);
            acc.w = fmaf(w, f1.y, acc.w);
        }
    }
    float sc = s_cnt[qy];
    int bq = bq0 + qy;
    *(float4*)(g_sampled + (size_t)bq * CC + c) =
        make_float4(acc.x * sc, acc.y * sc, acc.z * sc, acc.w * sc);
}

// ---------------- mma helpers ----------------
__device__ __forceinline__ uint32_t f22h(float x, float y) {
    __half2 h = __floats2half2_rn(x, y);
    return *reinterpret_cast<uint32_t*>(&h);
}

__device__ __forceinline__ void mma16(float* c, const uint32_t* a, const uint32_t* b) {
    asm volatile(
        "mma.sync.aligned.m16n8k16.row.col.f32.f16.f16.f32 "
        "{%0,%1,%2,%3},{%4,%5,%6,%7},{%8,%9},{%0,%1,%2,%3};\n"
        : "+f"(c[0]), "+f"(c[1]), "+f"(c[2]), "+f"(c[3])
        : "r"(a[0]), "r"(a[1]), "r"(a[2]), "r"(a[3]), "r"(b[0]), "r"(b[1]));
}

// ---------------- pipelined fp16 projection GEMM (64x64 tile, B [N,K] row-major) ----------------
// smem words: As[2][64][18] + Bs[2][16][72]   (k packed as half2: word w = k 2w (lo), 2w+1 (hi))
#define GEMM_SMEM ((2*64*18 + 2*16*72) * 4)
__device__ __forceinline__ void gemm_body(
    const float* __restrict__ A, const float* __restrict__ B,
    float* __restrict__ C, const float* __restrict__ bias,
    int M, int N, int K, int lda, int ldb, int ldc, float alpha)
{
    extern __shared__ uint32_t gsm[];
    uint32_t (*As)[64][18] = (uint32_t(*)[64][18])gsm;
    uint32_t (*Bs)[16][72] = (uint32_t(*)[16][72])(gsm + 2*64*18);
    int tid = threadIdx.x;
    int warp = tid >> 5, lane = tid & 31;
    int g = lane >> 2, tg = lane & 3;
    int wm0 = (warp >> 1) * 16, wn0 = (warp & 1) * 32;
    int m0 = blockIdx.y * 64, n0 = blockIdx.x * 64;
    float acc[4][4] = {};

    int arow = tid >> 3, ac4 = (tid & 7) * 4, ac2 = (tid & 7) * 2;

    float4 aR[2], bR[2];
    auto loadA = [&](int k0) {
        #pragma unroll
        for (int i = 0; i < 2; i++) {
            int row = arow + i * 32;
            int gm = m0 + row, gk = k0 + ac4;
            aR[i] = (gm < M) ? *(const float4*)(A + (size_t)gm * lda + gk)
                             : make_float4(0.f, 0.f, 0.f, 0.f);
        }
    };
    auto loadB = [&](int k0) {
        #pragma unroll
        for (int i = 0; i < 2; i++) {
            int n = arow + i * 32;
            int gn = n0 + n, gk = k0 + ac4;
            bR[i] = (gn < N) ? *(const float4*)(B + (size_t)gn * ldb + gk)
                             : make_float4(0.f, 0.f, 0.f, 0.f);
        }
    };
    auto stage = [&](int buf) {
        #pragma unroll
        for (int i = 0; i < 2; i++) {
            int row = arow + i * 32;
            As[buf][row][ac2+0] = f22h(aR[i].x, aR[i].y);
            As[buf][row][ac2+1] = f22h(aR[i].z, aR[i].w);
        }
        #pragma unroll
        for (int i = 0; i < 2; i++) {
            int n = arow + i * 32;
            Bs[buf][ac2+0][n] = f22h(bR[i].x, bR[i].y);
            Bs[buf][ac2+1][n] = f22h(bR[i].z, bR[i].w);
        }
    };

    loadA(0); loadB(0);
    int nk = K >> 5;
    int buf = 0;
    for (int kt = 0; kt < nk; kt++) {
        stage(buf);
        __syncthreads();
        if (kt + 1 < nk) { loadA((kt + 1) * 32); loadB((kt + 1) * 32); }
        #pragma unroll
        for (int ko = 0; ko < 2; ko++) {
            int koff = ko * 8;   // word offset: k elements koff*2 .. koff*2+15
            uint32_t a[4], bfr[4][2];
            a[0] = As[buf][wm0 + g][koff + tg];
            a[1] = As[buf][wm0 + g + 8][koff + tg];
            a[2] = As[buf][wm0 + g][koff + tg + 4];
            a[3] = As[buf][wm0 + g + 8][koff + tg + 4];
            #pragma unroll
            for (int ni = 0; ni < 4; ni++) {
                int cn = wn0 + ni * 8 + g;
                bfr[ni][0] = Bs[buf][koff + tg][cn];
                bfr[ni][1] = Bs[buf][koff + tg + 4][cn];
            }
            #pragma unroll
            for (int ni = 0; ni < 4; ni++)
                mma16(acc[ni], a, bfr[ni]);
        }
        buf ^= 1;
    }

    #pragma unroll
    for (int ni = 0; ni < 4; ni++) {
        int r0 = m0 + wm0 + g;
        int cc0 = n0 + wn0 + ni * 8 + tg * 2;
        #pragma unroll
        for (int e = 0; e < 4; e++) {
            int r = r0 + (e >> 1) * 8;
            int cn = cc0 + (e & 1);
            if (r < M && cn < N) {
                float val = acc[ni][e] * alpha;
                if (bias) val += bias[cn];
                C[(size_t)r * ldc + cn] = val;
            }
        }
    }
}

__global__ void gemm_proj(const float* __restrict__ A, const float* __restrict__ B,
                          float* __restrict__ C, const float* __restrict__ bias) {
    gemm_body(A, B, C, bias, BB * QQ, CC, CC, CC, CC, CC, 1.f);
}

__global__ void gemm_qkv(const float* __restrict__ qry, const float* __restrict__ sampled,
                         const float* __restrict__ Wq, const float* __restrict__ Wk,
                         const float* __restrict__ Wv,
                         const float* __restrict__ bq, const float* __restrict__ bk,
                         const float* __restrict__ bv,
                         float* __restrict__ qp, float* __restrict__ kp, float* __restrict__ vp) {
    int z = blockIdx.z;
    const float* A = (z == 0) ? qry : sampled;
    const float* B = (z == 0) ? Wq : ((z == 1) ? Wk : Wv);
    const float* bi = (z == 0) ? bq : ((z == 1) ? bk : bv);
    float* C = (z == 0) ? qp : ((z == 1) ? kp : vp);
    gemm_body(A, B, C, bi, BB * QQ, CC, CC, CC, CC, CC, 1.f);
}

// ---------------- fused flash attention v3 (fp16 m16n8k16) ----------------
// smem words: Qs[128][18] | Ks[2][16][68] | Vs[2][32][36] | Ps[128][34]
#define FLASH_SMEM ((128*18 + 2*16*68 + 2*32*36 + 128*34) * 4)
#define NIT ((QQ + 63) / 64)

__global__ void flash_kernel(const float* __restrict__ qp, const float* __restrict__ kp,
                             const float* __restrict__ vp, float* __restrict__ attno) {
    extern __shared__ uint32_t fsm[];
    uint32_t (*Qs)[18]     = (uint32_t(*)[18])fsm;                         // [row][ch2]
    uint32_t (*Ks)[16][68] = (uint32_t(*)[16][68])(fsm + 128*18);          // [ch2][key]
    uint32_t (*Vs)[32][36] = (uint32_t(*)[32][36])(fsm + 128*18 + 2*16*68);// [key2][ch]
    uint32_t (*Ps)[34]     = (uint32_t(*)[34])(fsm + 128*18 + 2*16*68 + 2*32*36); // [row][key2]

    int z = blockIdx.y;
    int b = z / NH, h = z % NH;
    int q0 = blockIdx.x * 128;
    int tid = threadIdx.x;
    int warp = tid >> 5, lane = tid & 31;
    int g = lane >> 2, tg = lane & 3;
    int wr0 = warp * 16;

    const float* qbase = qp + (size_t)b * QQ * CC + h * HD;
    const float* kbase = kp + (size_t)b * QQ * CC + h * HD;
    const float* vbase = vp + (size_t)b * QQ * CC + h * HD;

    #pragma unroll
    for (int i = 0; i < 4; i++) {
        int lin = tid + i * 256;
        int row = lin >> 3, ch2 = (lin & 7) * 2, c4 = (lin & 7) * 4;
        float4 v = make_float4(0.f, 0.f, 0.f, 0.f);
        if (q0 + row < QQ) v = *(const float4*)(qbase + (size_t)(q0 + row) * CC + c4);
        Qs[row][ch2]     = f22h(v.x * ATT_SCALE, v.y * ATT_SCALE);
        Qs[row][ch2 + 1] = f22h(v.z * ATT_SCALE, v.w * ATT_SCALE);
    }

    int krow = tid >> 3, kch2 = (tid & 7) * 2, kc4 = (tid & 7) * 4;
    float4 kr[2], va, vb;
    auto loadKV = [&](int k0) {
        #pragma unroll
        for (int j = 0; j < 2; j++) {
            int gk = k0 + krow + j * 32;
            kr[j] = (gk < QQ) ? *(const float4*)(kbase + (size_t)gk * CC + kc4)
                              : make_float4(0.f, 0.f, 0.f, 0.f);
        }
        int gva = k0 + 2 * krow, gvb = gva + 1;
        va = (gva < QQ) ? *(const float4*)(vbase + (size_t)gva * CC + kc4)
                        : make_float4(0.f, 0.f, 0.f, 0.f);
        vb = (gvb < QQ) ? *(const float4*)(vbase + (size_t)gvb * CC + kc4)
                        : make_float4(0.f, 0.f, 0.f, 0.f);
    };
    auto stageKV = [&](int buf) {
        #pragma unroll
        for (int j = 0; j < 2; j++) {
            int key = krow + j * 32;
            Ks[buf][kch2][key]     = f22h(kr[j].x, kr[j].y);
            Ks[buf][kch2 + 1][key] = f22h(kr[j].z, kr[j].w);
        }
        Vs[buf][krow][kc4 + 0] = f22h(va.x, vb.x);
        Vs[buf][krow][kc4 + 1] = f22h(va.y, vb.y);
        Vs[buf][krow][kc4 + 2] = f22h(va.z, vb.z);
        Vs[buf][krow][kc4 + 3] = f22h(va.w, vb.w);
    };

    float m0r = -1e30f, m1r = -1e30f;
    float l0 = 0.f, l1 = 0.f;
    float oacc[4][4] = {};

    loadKV(0);
    int buf = 0;
    for (int it = 0; it < NIT; it++) {
        stageKV(buf);
        __syncthreads();
        if (it + 1 < NIT) loadKV((it + 1) * 64);

        float sacc[8][4] = {};
        #pragma unroll
        for (int ko = 0; ko < 2; ko++) {
            int koff = ko * 8;
            uint32_t a[4];
            a[0] = Qs[wr0 + g][koff + tg];
            a[1] = Qs[wr0 + g + 8][koff + tg];
            a[2] = Qs[wr0 + g][koff + tg + 4];
            a[3] = Qs[wr0 + g + 8][koff + tg + 4];
            #pragma unroll
            for (int ni = 0; ni < 8; ni++) {
                uint32_t bf[2];
                int cn = ni * 8 + g;
                bf[0] = Ks[buf][koff + tg][cn];
                bf[1] = Ks[buf][koff + tg + 4][cn];
                mma16(sacc[ni], a, bf);
            }
        }

        int cbase = it * 64;
        float r0 = -1e30f, r1 = -1e30f;
        #pragma unroll
        for (int ni = 0; ni < 8; ni++) {
            #pragma unroll
            for (int e = 0; e < 4; e++) {
                int gk = cbase + ni * 8 + tg * 2 + (e & 1);
                float s = sacc[ni][e];
                if (gk >= QQ) s = -1e30f;
                sacc[ni][e] = s;
                if (e < 2) r0 = fmaxf(r0, s); else r1 = fmaxf(r1, s);
            }
        }
        r0 = fmaxf(r0, __shfl_xor_sync(0xffffffffu, r0, 1));
        r0 = fmaxf(r0, __shfl_xor_sync(0xffffffffu, r0, 2));
        r1 = fmaxf(r1, __shfl_xor_sync(0xffffffffu, r1, 1));
        r1 = fmaxf(r1, __shfl_xor_sync(0xffffffffu, r1, 2));

        float nm0 = fmaxf(m0r, r0), nm1 = fmaxf(m1r, r1);
        float sc0 = __expf(m0r - nm0), sc1 = __expf(m1r - nm1);
        m0r = nm0; m1r = nm1;

        float s0 = 0.f, s1 = 0.f;
        #pragma unroll
        for (int ni = 0; ni < 8; ni++) {
            float p0 = __expf(sacc[ni][0] - m0r);
            float p1 = __expf(sacc[ni][1] - m0r);
            float p2 = __expf(sacc[ni][2] - m1r);
            float p3 = __expf(sacc[ni][3] - m1r);
            Ps[wr0 + g][ni * 4 + tg]     = f22h(p0, p1);
            Ps[wr0 + g + 8][ni * 4 + tg] = f22h(p2, p3);
            s0 += p0 + p1;
            s1 += p2 + p3;
        }
        s0 += __shfl_xor_sync(0xffffffffu, s0, 1);
        s0 += __shfl_xor_sync(0xffffffffu, s0, 2);
        s1 += __shfl_xor_sync(0xffffffffu, s1, 1);
        s1 += __shfl_xor_sync(0xffffffffu, s1, 2);
        l0 = l0 * sc0 + s0;
        l1 = l1 * sc1 + s1;

        #pragma unroll
        for (int ni = 0; ni < 4; ni++) {
            oacc[ni][0] *= sc0; oacc[ni][1] *= sc0;
            oacc[ni][2] *= sc1; oacc[ni][3] *= sc1;
        }
        __syncwarp();

        #pragma unroll
        for (int kk2 = 0; kk2 < 32; kk2 += 8) {
            uint32_t a[4];
            a[0] = Ps[wr0 + g][kk2 + tg];
            a[1] = Ps[wr0 + g + 8][kk2 + tg];
            a[2] = Ps[wr0 + g][kk2 + tg + 4];
            a[3] = Ps[wr0 + g + 8][kk2 + tg + 4];
            #pragma unroll
            for (int ni = 0; ni < 4; ni++) {
                uint32_t bf[2];
                int cn = ni * 8 + g;
                bf[0] = Vs[buf][kk2 + tg][cn];
                bf[1] = Vs[buf][kk2 + tg + 4][cn];
                mma16(oacc[ni], a, bf);
            }
        }
        buf ^= 1;
    }

    float li0 = 1.f / l0, li1 = 1.f / l1;
    #pragma unroll
    for (int ni = 0; ni < 4; ni++) {
        #pragma unroll
        for (int e = 0; e < 4; e++) {
            int row = wr0 + g + ((e >> 1) << 3);
            int col = ni * 8 + tg * 2 + (e & 1);
            int q = q0 + row;
            if (q < QQ)
                attno[((size_t)b * QQ + q) * CC + h * HD + col] =
                    oacc[ni][e] * ((e < 2) ? li0 : li1);
        }
    }
}

// ---------------- host launcher ----------------
extern "C" void kernel_launch(void* const* d_in, const int* in_sizes, int n_in,
                              void* d_out, int out_size) {
    const float* f0   = (const float*)d_in[0];
    const float* f1   = (const float*)d_in[1];
    const float* refs = (const float*)d_in[2];
    const float* intr = (const float*)d_in[3];
    const float* extr = (const float*)d_in[4];
    const float* qry  = (const float*)d_in[5];
    const float* Wq   = (const float*)d_in[6];
    const float* bq   = (const float*)d_in[7];
    const float* Wk   = (const float*)d_in[8];
    const float* bk   = (const float*)d_in[9];
    const float* Wv   = (const float*)d_in[10];
    const float* bv   = (const float*)d_in[11];
    const float* Wo   = (const float*)d_in[12];
    const float* bo   = (const float*)d_in[13];
    float* out = (float*)d_out;

    __half *featT0, *featT1;
    float *sampled, *qp, *kp, *vp, *attno;
    cudaGetSymbolAddress((void**)&featT0, g_featT0);
    cudaGetSymbolAddress((void**)&featT1, g_featT1);
    cudaGetSymbolAddress((void**)&sampled, g_sampled);
    cudaGetSymbolAddress((void**)&qp, g_qp);
    cudaGetSymbolAddress((void**)&kp, g_kp);
    cudaGetSymbolAddress((void**)&vp, g_vp);
    cudaGetSymbolAddress((void**)&attno, g_attno);

    cudaFuncSetAttribute(gemm_qkv, cudaFuncAttributeMaxDynamicSharedMemorySize, GEMM_SMEM);
    cudaFuncSetAttribute(gemm_proj, cudaFuncAttributeMaxDynamicSharedMemorySize, GEMM_SMEM);
    cudaFuncSetAttribute(flash_kernel, cudaFuncAttributeMaxDynamicSharedMemorySize, FLASH_SMEM);

    dim3 tt(32, 8);
    transpose_kernel<<<dim3((H0 * W0) / 32, CC / 32, BB * VV), tt>>>(f0, featT0, H0 * W0);
    transpose_kernel<<<dim3((H1 * W1) / 32, CC / 32, BB * VV), tt>>>(f1, featT1, H1 * W1);
    sample_kernel<<<(BB * QQ) / 4, dim3(64, 4)>>>(refs, intr, extr);

    const int M = BB * QQ;  // 1800
    gemm_qkv<<<dim3(CC / 64, (M + 63) / 64, 3), 256, GEMM_SMEM>>>(
        qry, sampled, Wq, Wk, Wv, bq, bk, bv, qp, kp, vp);

    flash_kernel<<<dim3((QQ + 127) / 128, BB * NH), 256, FLASH_SMEM>>>(qp, kp, vp, attno);

    gemm_proj<<<dim3(CC / 64, (M + 63) / 64), 256, GEMM_SMEM>>>(attno, Wo, out, bo);
}

// round 10
// speedup vs baseline: 3.6525x; 1.1140x over previous
#include <cuda_runtime.h>
#include <cuda_fp16.h>
#include <math.h>
#include <stdint.h>

#define BB 2
#define VV 6
#define CC 256
#define QQ 900
#define KP 4
#define H0 64
#define W0 176
#define H1 32
#define W1 88
#define NH 8
#define HD 32
#define ATT_SCALE 0.17677669529663689f

// ---------------- scratch (device globals; no runtime allocation) ----------------
__device__ __half g_featT0[(size_t)BB*VV*H0*W0*CC];   // [B,V,H,W,C] fp16
__device__ __half g_featT1[(size_t)BB*VV*H1*W1*CC];
__device__ float  g_sampled[BB*QQ*CC];
__device__ float  g_qp[BB*QQ*CC];
__device__ float  g_kp[BB*QQ*CC];
__device__ float  g_vp[BB*QQ*CC];
__device__ float  g_attno[BB*QQ*CC];

// ---------------- feature transpose v2: [bv, C, HW] -> [bv, HW, C] fp32 -> fp16 ----------------
// 64 channels x 32 pixels per block; write phase stores half2 (128B/warp per instr).
__global__ void transpose_kernel(const float* __restrict__ in, __half* __restrict__ out, int HW) {
    __shared__ float tile[64][33];
    int bv = blockIdx.z;
    int c0 = blockIdx.y * 64, p0 = blockIdx.x * 32;
    const float* src = in  + (size_t)bv * CC * HW;
    __half*      dst = out + (size_t)bv * HW * CC;
    int tid = threadIdx.x;
    int tx = tid & 31, ty = tid >> 5;   // 32 x 8
    #pragma unroll
    for (int i = 0; i < 8; i++) {
        int c = ty + i * 8;             // 0..63
        tile[c][tx] = src[(size_t)(c0 + c) * HW + p0 + tx];
    }
    __syncthreads();
    #pragma unroll
    for (int i = 0; i < 4; i++) {
        int w = tid + i * 256;          // 0..1023
        int p = w >> 5;                 // 0..31 (constant per warp)
        int cw = w & 31;                // half2 word: c = 2*cw
        __half2 h = __floats2half2_rn(tile[2 * cw][p], tile[2 * cw + 1][p]);
        *(__half2*)(dst + (size_t)(p0 + p) * CC + c0 + 2 * cw) = h;
    }
}

// ---------------- sampling: proj fused into setup; 4 queries/block, fp16 features ----------------
__global__ void sample_kernel(const float* __restrict__ refs,
                              const float* __restrict__ intr,
                              const float* __restrict__ extr) {
    __shared__ float         s_w[4][48][4];
    __shared__ const __half* s_p[4][48][4];
    __shared__ int           s_valid[4][48];
    __shared__ float         s_cnt[4];
    int tid = threadIdx.y * 64 + threadIdx.x;
    int bq0 = blockIdx.x * 4;

    if (tid < 192) {
        int qy = tid / 48, t = tid % 48;
        int bq = bq0 + qy;
        int b = bq / QQ, q = bq % QQ;
        int level = t / 24, r = t % 24, v = r >> 2, k = r & 3;
        int bv = b * VV + v;
        const float kpx[4] = {0.f, 2.f, 0.f, -2.f};
        const float kpy[4] = {0.f, 0.f, 2.f, 0.f};
        const float* rp = refs + (b * QQ + q) * 3;
        float rx = rp[0] + kpx[k], ry = rp[1] + kpy[k], rz = rp[2];
        const float* E = extr + bv * 16;
        float c0 = E[0]*rx + E[1]*ry + E[2]*rz + E[3];
        float c1 = E[4]*rx + E[5]*ry + E[6]*rz + E[7];
        float c2 = E[8]*rx + E[9]*ry + E[10]*rz + E[11];
        const float* I = intr + bv * 9;
        float u  = I[0]*c0 + I[1]*c1 + I[2]*c2;
        float w_ = I[3]*c0 + I[4]*c1 + I[5]*c2;
        float z  = I[6]*c0 + I[7]*c1 + I[8]*c2;
        float zs = (fabsf(z) > 1e-6f) ? z : 1e-6f;
        float uz = u / zs, vz = w_ / zs;
        s_valid[qy][t] = (z > 0.f);
        int H = level ? H1 : H0, W = level ? W1 : W0;
        const __half* base = level ? g_featT1 : g_featT0;
        float gx = 2.f * uz / (float)(W - 1) - 1.f;
        float gy = 2.f * vz / (float)(H - 1) - 1.f;
        float x = (gx + 1.f) * 0.5f * (float)(W - 1);
        float y = (gy + 1.f) * 0.5f * (float)(H - 1);
        float x0f = floorf(x), y0f = floorf(y);
        float wx1 = x - x0f, wx0 = 1.f - wx1;
        float wy1 = y - y0f, wy0 = 1.f - wy1;
        #pragma unroll
        for (int c4 = 0; c4 < 4; c4++) {
            int dx = c4 & 1, dy = c4 >> 1;
            float xf = x0f + (float)dx, yf = y0f + (float)dy;
            bool inb = (xf >= 0.f) && (xf <= (float)(W - 1)) && (yf >= 0.f) && (yf <= (float)(H - 1));
            int xi = min(max((int)xf, 0), W - 1);
            int yi = min(max((int)yf, 0), H - 1);
            s_w[qy][t][c4] = inb ? (dx ? wx1 : wx0) * (dy ? wy1 : wy0) : 0.f;
            s_p[qy][t][c4] = base + (((size_t)bv * H + yi) * W + xi) * CC;
        }
    }
    __syncthreads();
    if (tid < 4) {
        float c = 0.f;
        for (int t = 0; t < 24; t++) c += s_valid[tid][t] ? 1.f : 0.f;
        s_cnt[tid] = 0.5f / fmaxf(c, 1.f);
    }
    __syncthreads();

    int qy = threadIdx.y, c = threadIdx.x * 4;
    float4 acc = make_float4(0.f, 0.f, 0.f, 0.f);
    #pragma unroll 4
    for (int t = 0; t < 48; t++) {
        if (!s_valid[qy][t]) continue;
        #pragma unroll
        for (int j = 0; j < 4; j++) {
            float w = s_w[qy][t][j];
            uint2 raw = *(const uint2*)(s_p[qy][t][j] + c);
            __half2 h0 = *reinterpret_cast<__half2*>(&raw.x);
            __half2 h1 = *reinterpret_cast<__half2*>(&raw.y);
            float2 f0 = __half22float2(h0);
            float2 f1 = __half22float2(h1);
            acc.x = fmaf(w, f0.x, acc.x);
            acc.y = fmaf(w, f0.y, acc.y);
            acc.z = fmaf(w, f1.x, acc.z);
            acc.w = fmaf(w, f1.y, acc.w);
        }
    }
    float sc = s_cnt[qy];
    int bq = bq0 + qy;
    *(float4*)(g_sampled + (size_t)bq * CC + c) =
        make_float4(acc.x * sc, acc.y * sc, acc.z * sc, acc.w * sc);
}

// ---------------- mma helpers ----------------
__device__ __forceinline__ uint32_t f22h(float x, float y) {
    __half2 h = __floats2half2_rn(x, y);
    return *reinterpret_cast<uint32_t*>(&h);
}

__device__ __forceinline__ void mma16(float* c, const uint32_t* a, const uint32_t* b) {
    asm volatile(
        "mma.sync.aligned.m16n8k16.row.col.f32.f16.f16.f32 "
        "{%0,%1,%2,%3},{%4,%5,%6,%7},{%8,%9},{%0,%1,%2,%3};\n"
        : "+f"(c[0]), "+f"(c[1]), "+f"(c[2]), "+f"(c[3])
        : "r"(a[0]), "r"(a[1]), "r"(a[2]), "r"(a[3]), "r"(b[0]), "r"(b[1]));
}

// ---------------- pipelined fp16 projection GEMM (64x64 tile, B [N,K] row-major) ----------------
#define GEMM_SMEM ((2*64*18 + 2*16*72) * 4)
__device__ __forceinline__ void gemm_body(
    const float* __restrict__ A, const float* __restrict__ B,
    float* __restrict__ C, const float* __restrict__ bias,
    int M, int N, int K, int lda, int ldb, int ldc, float alpha)
{
    extern __shared__ uint32_t gsm[];
    uint32_t (*As)[64][18] = (uint32_t(*)[64][18])gsm;
    uint32_t (*Bs)[16][72] = (uint32_t(*)[16][72])(gsm + 2*64*18);
    int tid = threadIdx.x;
    int warp = tid >> 5, lane = tid & 31;
    int g = lane >> 2, tg = lane & 3;
    int wm0 = (warp >> 1) * 16, wn0 = (warp & 1) * 32;
    int m0 = blockIdx.y * 64, n0 = blockIdx.x * 64;
    float acc[4][4] = {};

    int arow = tid >> 3, ac4 = (tid & 7) * 4, ac2 = (tid & 7) * 2;

    float4 aR[2], bR[2];
    auto loadA = [&](int k0) {
        #pragma unroll
        for (int i = 0; i < 2; i++) {
            int row = arow + i * 32;
            int gm = m0 + row, gk = k0 + ac4;
            aR[i] = (gm < M) ? *(const float4*)(A + (size_t)gm * lda + gk)
                             : make_float4(0.f, 0.f, 0.f, 0.f);
        }
    };
    auto loadB = [&](int k0) {
        #pragma unroll
        for (int i = 0; i < 2; i++) {
            int n = arow + i * 32;
            int gn = n0 + n, gk = k0 + ac4;
            bR[i] = (gn < N) ? *(const float4*)(B + (size_t)gn * ldb + gk)
                             : make_float4(0.f, 0.f, 0.f, 0.f);
        }
    };
    auto stage = [&](int buf) {
        #pragma unroll
        for (int i = 0; i < 2; i++) {
            int row = arow + i * 32;
            As[buf][row][ac2+0] = f22h(aR[i].x, aR[i].y);
            As[buf][row][ac2+1] = f22h(aR[i].z, aR[i].w);
        }
        #pragma unroll
        for (int i = 0; i < 2; i++) {
            int n = arow + i * 32;
            Bs[buf][ac2+0][n] = f22h(bR[i].x, bR[i].y);
            Bs[buf][ac2+1][n] = f22h(bR[i].z, bR[i].w);
        }
    };

    loadA(0); loadB(0);
    int nk = K >> 5;
    int buf = 0;
    for (int kt = 0; kt < nk; kt++) {
        stage(buf);
        __syncthreads();
        if (kt + 1 < nk) { loadA((kt + 1) * 32); loadB((kt + 1) * 32); }
        #pragma unroll
        for (int ko = 0; ko < 2; ko++) {
            int koff = ko * 8;
            uint32_t a[4], bfr[4][2];
            a[0] = As[buf][wm0 + g][koff + tg];
            a[1] = As[buf][wm0 + g + 8][koff + tg];
            a[2] = As[buf][wm0 + g][koff + tg + 4];
            a[3] = As[buf][wm0 + g + 8][koff + tg + 4];
            #pragma unroll
            for (int ni = 0; ni < 4; ni++) {
                int cn = wn0 + ni * 8 + g;
                bfr[ni][0] = Bs[buf][koff + tg][cn];
                bfr[ni][1] = Bs[buf][koff + tg + 4][cn];
            }
            #pragma unroll
            for (int ni = 0; ni < 4; ni++)
                mma16(acc[ni], a, bfr[ni]);
        }
        buf ^= 1;
    }

    #pragma unroll
    for (int ni = 0; ni < 4; ni++) {
        int r0 = m0 + wm0 + g;
        int cc0 = n0 + wn0 + ni * 8 + tg * 2;
        #pragma unroll
        for (int e = 0; e < 4; e++) {
            int r = r0 + (e >> 1) * 8;
            int cn = cc0 + (e & 1);
            if (r < M && cn < N) {
                float val = acc[ni][e] * alpha;
                if (bias) val += bias[cn];
                C[(size_t)r * ldc + cn] = val;
            }
        }
    }
}

__global__ void gemm_proj(const float* __restrict__ A, const float* __restrict__ B,
                          float* __restrict__ C, const float* __restrict__ bias) {
    gemm_body(A, B, C, bias, BB * QQ, CC, CC, CC, CC, CC, 1.f);
}

__global__ void gemm_qkv(const float* __restrict__ qry, const float* __restrict__ sampled,
                         const float* __restrict__ Wq, const float* __restrict__ Wk,
                         const float* __restrict__ Wv,
                         const float* __restrict__ bq, const float* __restrict__ bk,
                         const float* __restrict__ bv,
                         float* __restrict__ qp, float* __restrict__ kp, float* __restrict__ vp) {
    int z = blockIdx.z;
    const float* A = (z == 0) ? qry : sampled;
    const float* B = (z == 0) ? Wq : ((z == 1) ? Wk : Wv);
    const float* bi = (z == 0) ? bq : ((z == 1) ? bk : bv);
    float* C = (z == 0) ? qp : ((z == 1) ? kp : vp);
    gemm_body(A, B, C, bi, BB * QQ, CC, CC, CC, CC, CC, 1.f);
}

// ---------------- fused flash attention v3 (fp16 m16n8k16) ----------------
#define FLASH_SMEM ((128*18 + 2*16*68 + 2*32*36 + 128*34) * 4)
#define NIT ((QQ + 63) / 64)

__global__ void flash_kernel(const float* __restrict__ qp, const float* __restrict__ kp,
                             const float* __restrict__ vp, float* __restrict__ attno) {
    extern __shared__ uint32_t fsm[];
    uint32_t (*Qs)[18]     = (uint32_t(*)[18])fsm;
    uint32_t (*Ks)[16][68] = (uint32_t(*)[16][68])(fsm + 128*18);
    uint32_t (*Vs)[32][36] = (uint32_t(*)[32][36])(fsm + 128*18 + 2*16*68);
    uint32_t (*Ps)[34]     = (uint32_t(*)[34])(fsm + 128*18 + 2*16*68 + 2*32*36);

    int z = blockIdx.y;
    int b = z / NH, h = z % NH;
    int q0 = blockIdx.x * 128;
    int tid = threadIdx.x;
    int warp = tid >> 5, lane = tid & 31;
    int g = lane >> 2, tg = lane & 3;
    int wr0 = warp * 16;

    const float* qbase = qp + (size_t)b * QQ * CC + h * HD;
    const float* kbase = kp + (size_t)b * QQ * CC + h * HD;
    const float* vbase = vp + (size_t)b * QQ * CC + h * HD;

    #pragma unroll
    for (int i = 0; i < 4; i++) {
        int lin = tid + i * 256;
        int row = lin >> 3, ch2 = (lin & 7) * 2, c4 = (lin & 7) * 4;
        float4 v = make_float4(0.f, 0.f, 0.f, 0.f);
        if (q0 + row < QQ) v = *(const float4*)(qbase + (size_t)(q0 + row) * CC + c4);
        Qs[row][ch2]     = f22h(v.x * ATT_SCALE, v.y * ATT_SCALE);
        Qs[row][ch2 + 1] = f22h(v.z * ATT_SCALE, v.w * ATT_SCALE);
    }

    int krow = tid >> 3, kch2 = (tid & 7) * 2, kc4 = (tid & 7) * 4;
    float4 kr[2], va, vb;
    auto loadKV = [&](int k0) {
        #pragma unroll
        for (int j = 0; j < 2; j++) {
            int gk = k0 + krow + j * 32;
            kr[j] = (gk < QQ) ? *(const float4*)(kbase + (size_t)gk * CC + kc4)
                              : make_float4(0.f, 0.f, 0.f, 0.f);
        }
        int gva = k0 + 2 * krow, gvb = gva + 1;
        va = (gva < QQ) ? *(const float4*)(vbase + (size_t)gva * CC + kc4)
                        : make_float4(0.f, 0.f, 0.f, 0.f);
        vb = (gvb < QQ) ? *(const float4*)(vbase + (size_t)gvb * CC + kc4)
                        : make_float4(0.f, 0.f, 0.f, 0.f);
    };
    auto stageKV = [&](int buf) {
        #pragma unroll
        for (int j = 0; j < 2; j++) {
            int key = krow + j * 32;
            Ks[buf][kch2][key]     = f22h(kr[j].x, kr[j].y);
            Ks[buf][kch2 + 1][key] = f22h(kr[j].z, kr[j].w);
        }
        Vs[buf][krow][kc4 + 0] = f22h(va.x, vb.x);
        Vs[buf][krow][kc4 + 1] = f22h(va.y, vb.y);
        Vs[buf][krow][kc4 + 2] = f22h(va.z, vb.z);
        Vs[buf][krow][kc4 + 3] = f22h(va.w, vb.w);
    };

    float m0r = -1e30f, m1r = -1e30f;
    float l0 = 0.f, l1 = 0.f;
    float oacc[4][4] = {};

    loadKV(0);
    int buf = 0;
    for (int it = 0; it < NIT; it++) {
        stageKV(buf);
        __syncthreads();
        if (it + 1 < NIT) loadKV((it + 1) * 64);

        float sacc[8][4] = {};
        #pragma unroll
        for (int ko = 0; ko < 2; ko++) {
            int koff = ko * 8;
            uint32_t a[4];
            a[0] = Qs[wr0 + g][koff + tg];
            a[1] = Qs[wr0 + g + 8][koff + tg];
            a[2] = Qs[wr0 + g][koff + tg + 4];
            a[3] = Qs[wr0 + g + 8][koff + tg + 4];
            #pragma unroll
            for (int ni = 0; ni < 8; ni++) {
                uint32_t bf[2];
                int cn = ni * 8 + g;
                bf[0] = Ks[buf][koff + tg][cn];
                bf[1] = Ks[buf][koff + tg + 4][cn];
                mma16(sacc[ni], a, bf);
            }
        }

        int cbase = it * 64;
        float r0 = -1e30f, r1 = -1e30f;
        #pragma unroll
        for (int ni = 0; ni < 8; ni++) {
            #pragma unroll
            for (int e = 0; e < 4; e++) {
                int gk = cbase + ni * 8 + tg * 2 + (e & 1);
                float s = sacc[ni][e];
                if (gk >= QQ) s = -1e30f;
                sacc[ni][e] = s;
                if (e < 2) r0 = fmaxf(r0, s); else r1 = fmaxf(r1, s);
            }
        }
        r0 = fmaxf(r0, __shfl_xor_sync(0xffffffffu, r0, 1));
        r0 = fmaxf(r0, __shfl_xor_sync(0xffffffffu, r0, 2));
        r1 = fmaxf(r1, __shfl_xor_sync(0xffffffffu, r1, 1));
        r1 = fmaxf(r1, __shfl_xor_sync(0xffffffffu, r1, 2));

        float nm0 = fmaxf(m0r, r0), nm1 = fmaxf(m1r, r1);
        float sc0 = __expf(m0r - nm0), sc1 = __expf(m1r - nm1);
        m0r = nm0; m1r = nm1;

        float s0 = 0.f, s1 = 0.f;
        #pragma unroll
        for (int ni = 0; ni < 8; ni++) {
            float p0 = __expf(sacc[ni][0] - m0r);
            float p1 = __expf(sacc[ni][1] - m0r);
            float p2 = __expf(sacc[ni][2] - m1r);
            float p3 = __expf(sacc[ni][3] - m1r);
            Ps[wr0 + g][ni * 4 + tg]     = f22h(p0, p1);
            Ps[wr0 + g + 8][ni * 4 + tg] = f22h(p2, p3);
            s0 += p0 + p1;
            s1 += p2 + p3;
        }
        s0 += __shfl_xor_sync(0xffffffffu, s0, 1);
        s0 += __shfl_xor_sync(0xffffffffu, s0, 2);
        s1 += __shfl_xor_sync(0xffffffffu, s1, 1);
        s1 += __shfl_xor_sync(0xffffffffu, s1, 2);
        l0 = l0 * sc0 + s0;
        l1 = l1 * sc1 + s1;

        #pragma unroll
        for (int ni = 0; ni < 4; ni++) {
            oacc[ni][0] *= sc0; oacc[ni][1] *= sc0;
            oacc[ni][2] *= sc1; oacc[ni][3] *= sc1;
        }
        __syncwarp();

        #pragma unroll
        for (int kk2 = 0; kk2 < 32; kk2 += 8) {
            uint32_t a[4];
            a[0] = Ps[wr0 + g][kk2 + tg];
            a[1] = Ps[wr0 + g + 8][kk2 + tg];
            a[2] = Ps[wr0 + g][kk2 + tg + 4];
            a[3] = Ps[wr0 + g + 8][kk2 + tg + 4];
            #pragma unroll
            for (int ni = 0; ni < 4; ni++) {
                uint32_t bf[2];
                int cn = ni * 8 + g;
                bf[0] = Vs[buf][kk2 + tg][cn];
                bf[1] = Vs[buf][kk2 + tg + 4][cn];
                mma16(oacc[ni], a, bf);
            }
        }
        buf ^= 1;
    }

    float li0 = 1.f / l0, li1 = 1.f / l1;
    #pragma unroll
    for (int ni = 0; ni < 4; ni++) {
        #pragma unroll
        for (int e = 0; e < 4; e++) {
            int row = wr0 + g + ((e >> 1) << 3);
            int col = ni * 8 + tg * 2 + (e & 1);
            int q = q0 + row;
            if (q < QQ)
                attno[((size_t)b * QQ + q) * CC + h * HD + col] =
                    oacc[ni][e] * ((e < 2) ? li0 : li1);
        }
    }
}

// ---------------- host launcher ----------------
extern "C" void kernel_launch(void* const* d_in, const int* in_sizes, int n_in,
                              void* d_out, int out_size) {
    const float* f0   = (const float*)d_in[0];
    const float* f1   = (const float*)d_in[1];
    const float* refs = (const float*)d_in[2];
    const float* intr = (const float*)d_in[3];
    const float* extr = (const float*)d_in[4];
    const float* qry  = (const float*)d_in[5];
    const float* Wq   = (const float*)d_in[6];
    const float* bq   = (const float*)d_in[7];
    const float* Wk   = (const float*)d_in[8];
    const float* bk   = (const float*)d_in[9];
    const float* Wv   = (const float*)d_in[10];
    const float* bv   = (const float*)d_in[11];
    const float* Wo   = (const float*)d_in[12];
    const float* bo   = (const float*)d_in[13];
    float* out = (float*)d_out;

    __half *featT0, *featT1;
    float *sampled, *qp, *kp, *vp, *attno;
    cudaGetSymbolAddress((void**)&featT0, g_featT0);
    cudaGetSymbolAddress((void**)&featT1, g_featT1);
    cudaGetSymbolAddress((void**)&sampled, g_sampled);
    cudaGetSymbolAddress((void**)&qp, g_qp);
    cudaGetSymbolAddress((void**)&kp, g_kp);
    cudaGetSymbolAddress((void**)&vp, g_vp);
    cudaGetSymbolAddress((void**)&attno, g_attno);

    cudaFuncSetAttribute(gemm_qkv, cudaFuncAttributeMaxDynamicSharedMemorySize, GEMM_SMEM);
    cudaFuncSetAttribute(gemm_proj, cudaFuncAttributeMaxDynamicSharedMemorySize, GEMM_SMEM);
    cudaFuncSetAttribute(flash_kernel, cudaFuncAttributeMaxDynamicSharedMemorySize, FLASH_SMEM);

    transpose_kernel<<<dim3((H0 * W0) / 32, CC / 64, BB * VV), 256>>>(f0, featT0, H0 * W0);
    transpose_kernel<<<dim3((H1 * W1) / 32, CC / 64, BB * VV), 256>>>(f1, featT1, H1 * W1);
    sample_kernel<<<(BB * QQ) / 4, dim3(64, 4)>>>(refs, intr, extr);

    const int M = BB * QQ;  // 1800
    gemm_qkv<<<dim3(CC / 64, (M + 63) / 64, 3), 256, GEMM_SMEM>>>(
        qry, sampled, Wq, Wk, Wv, bq, bk, bv, qp, kp, vp);

    flash_kernel<<<dim3((QQ + 127) / 128, BB * NH), 256, FLASH_SMEM>>>(qp, kp, vp, attno);

    gemm_proj<<<dim3(CC / 64, (M + 63) / 64), 256, GEMM_SMEM>>>(attno, Wo, out, bo);
}

// round 11
// speedup vs baseline: 3.8067x; 1.0422x over previous
#include <cuda_runtime.h>
#include <cuda_fp16.h>
#include <math.h>
#include <stdint.h>

#define BB 2
#define VV 6
#define CC 256
#define QQ 900
#define KP 4
#define H0 64
#define W0 176
#define H1 32
#define W1 88
#define NH 8
#define HD 32
#define ATT_SCALE 0.17677669529663689f
#define HW0 (H0*W0)
#define HW1 (H1*W1)
#define PT0 (HW0/64)
#define PT1 (HW1/64)

// ---------------- scratch (device globals; no runtime allocation) ----------------
__device__ __half g_featT0[(size_t)BB*VV*HW0*CC];   // [B,V,H,W,C] fp16
__device__ __half g_featT1[(size_t)BB*VV*HW1*CC];
__device__ float  g_sampled[BB*QQ*CC];
__device__ __half g_qp[BB*QQ*CC];
__device__ __half g_kp[BB*QQ*CC];
__device__ __half g_vp[BB*QQ*CC];
__device__ float  g_attno[BB*QQ*CC];

__device__ __forceinline__ uint32_t f22h(float x, float y) {
    __half2 h = __floats2half2_rn(x, y);
    return *reinterpret_cast<uint32_t*>(&h);
}

// ---------------- feature transpose v3: both levels, one launch ----------------
// 64ch x 64px tiles; float4 reads, uint4 (8-ch) packed half stores.
__global__ void transpose_kernel(const float* __restrict__ f0, const float* __restrict__ f1) {
    __shared__ float tile[64][65];
    int bid = blockIdx.x;
    const int NT0 = PT0 * 4 * BB * VV;
    const float* src; __half* dst; int HW, pt, ct;
    if (bid < NT0) {
        int r = bid; int bv = r / (PT0 * 4); r %= PT0 * 4; pt = r >> 2; ct = r & 3;
        HW = HW0; src = f0 + (size_t)bv * CC * HW0; dst = g_featT0 + (size_t)bv * HW0 * CC;
    } else {
        int r = bid - NT0; int bv = r / (PT1 * 4); r %= PT1 * 4; pt = r >> 2; ct = r & 3;
        HW = HW1; src = f1 + (size_t)bv * CC * HW1; dst = g_featT1 + (size_t)bv * HW1 * CC;
    }
    int c0 = ct * 64, p0 = pt * 64;
    int tid = threadIdx.x;

    int rc = tid >> 4;             // 0..15
    int rp = (tid & 15) * 4;       // 0..60
    #pragma unroll
    for (int i = 0; i < 4; i++) {
        int c = rc + i * 16;
        float4 v = *(const float4*)(src + (size_t)(c0 + c) * HW + p0 + rp);
        tile[c][rp + 0] = v.x; tile[c][rp + 1] = v.y;
        tile[c][rp + 2] = v.z; tile[c][rp + 3] = v.w;
    }
    __syncthreads();

    int wp = tid >> 3;             // 0..31
    int wg = (tid & 7) * 8;        // channel group base
    #pragma unroll
    for (int i = 0; i < 2; i++) {
        int p = wp + i * 32;
        uint4 o;
        o.x = f22h(tile[wg + 0][p], tile[wg + 1][p]);
        o.y = f22h(tile[wg + 2][p], tile[wg + 3][p]);
        o.z = f22h(tile[wg + 4][p], tile[wg + 5][p]);
        o.w = f22h(tile[wg + 6][p], tile[wg + 7][p]);
        *(uint4*)(dst + (size_t)(p0 + p) * CC + c0 + wg) = o;
    }
}

// ---------------- sampling: proj fused into setup; 4 queries/block, fp16 features ----------------
__global__ void sample_kernel(const float* __restrict__ refs,
                              const float* __restrict__ intr,
                              const float* __restrict__ extr) {
    __shared__ float         s_w[4][48][4];
    __shared__ const __half* s_p[4][48][4];
    __shared__ int           s_valid[4][48];
    __shared__ float         s_cnt[4];
    int tid = threadIdx.y * 64 + threadIdx.x;
    int bq0 = blockIdx.x * 4;

    if (tid < 192) {
        int qy = tid / 48, t = tid % 48;
        int bq = bq0 + qy;
        int b = bq / QQ, q = bq % QQ;
        int level = t / 24, r = t % 24, v = r >> 2, k = r & 3;
        int bv = b * VV + v;
        const float kpx[4] = {0.f, 2.f, 0.f, -2.f};
        const float kpy[4] = {0.f, 0.f, 2.f, 0.f};
        const float* rp = refs + (b * QQ + q) * 3;
        float rx = rp[0] + kpx[k], ry = rp[1] + kpy[k], rz = rp[2];
        const float* E = extr + bv * 16;
        float c0 = E[0]*rx + E[1]*ry + E[2]*rz + E[3];
        float c1 = E[4]*rx + E[5]*ry + E[6]*rz + E[7];
        float c2 = E[8]*rx + E[9]*ry + E[10]*rz + E[11];
        const float* I = intr + bv * 9;
        float u  = I[0]*c0 + I[1]*c1 + I[2]*c2;
        float w_ = I[3]*c0 + I[4]*c1 + I[5]*c2;
        float z  = I[6]*c0 + I[7]*c1 + I[8]*c2;
        float zs = (fabsf(z) > 1e-6f) ? z : 1e-6f;
        float uz = u / zs, vz = w_ / zs;
        s_valid[qy][t] = (z > 0.f);
        int H = level ? H1 : H0, W = level ? W1 : W0;
        const __half* base = level ? g_featT1 : g_featT0;
        float gx = 2.f * uz / (float)(W - 1) - 1.f;
        float gy = 2.f * vz / (float)(H - 1) - 1.f;
        float x = (gx + 1.f) * 0.5f * (float)(W - 1);
        float y = (gy + 1.f) * 0.5f * (float)(H - 1);
        float x0f = floorf(x), y0f = floorf(y);
        float wx1 = x - x0f, wx0 = 1.f - wx1;
        float wy1 = y - y0f, wy0 = 1.f - wy1;
        #pragma unroll
        for (int c4 = 0; c4 < 4; c4++) {
            int dx = c4 & 1, dy = c4 >> 1;
            float xf = x0f + (float)dx, yf = y0f + (float)dy;
            bool inb = (xf >= 0.f) && (xf <= (float)(W - 1)) && (yf >= 0.f) && (yf <= (float)(H - 1));
            int xi = min(max((int)xf, 0), W - 1);
            int yi = min(max((int)yf, 0), H - 1);
            s_w[qy][t][c4] = inb ? (dx ? wx1 : wx0) * (dy ? wy1 : wy0) : 0.f;
            s_p[qy][t][c4] = base + (((size_t)bv * H + yi) * W + xi) * CC;
        }
    }
    __syncthreads();
    if (tid < 4) {
        float c = 0.f;
        for (int t = 0; t < 24; t++) c += s_valid[tid][t] ? 1.f : 0.f;
        s_cnt[tid] = 0.5f / fmaxf(c, 1.f);
    }
    __syncthreads();

    int qy = threadIdx.y, c = threadIdx.x * 4;
    float4 acc = make_float4(0.f, 0.f, 0.f, 0.f);
    #pragma unroll 4
    for (int t = 0; t < 48; t++) {
        if (!s_valid[qy][t]) continue;
        #pragma unroll
        for (int j = 0; j < 4; j++) {
            float w = s_w[qy][t][j];
            uint2 raw = *(const uint2*)(s_p[qy][t][j] + c);
            __half2 h0 = *reinterpret_cast<__half2*>(&raw.x);
            __half2 h1 = *reinterpret_cast<__half2*>(&raw.y);
            float2 f0 = __half22float2(h0);
            float2 f1 = __half22float2(h1);
            acc.x = fmaf(w, f0.x, acc.x);
            acc.y = fmaf(w, f0.y, acc.y);
            acc.z = fmaf(w, f1.x, acc.z);
            acc.w = fmaf(w, f1.y, acc.w);
        }
    }
    float sc = s_cnt[qy];
    int bq = bq0 + qy;
    *(float4*)(g_sampled + (size_t)bq * CC + c) =
        make_float4(acc.x * sc, acc.y * sc, acc.z * sc, acc.w * sc);
}

// ---------------- mma helper ----------------
__device__ __forceinline__ void mma16(float* c, const uint32_t* a, const uint32_t* b) {
    asm volatile(
        "mma.sync.aligned.m16n8k16.row.col.f32.f16.f16.f32 "
        "{%0,%1,%2,%3},{%4,%5,%6,%7},{%8,%9},{%0,%1,%2,%3};\n"
        : "+f"(c[0]), "+f"(c[1]), "+f"(c[2]), "+f"(c[3])
        : "r"(a[0]), "r"(a[1]), "r"(a[2]), "r"(a[3]), "r"(b[0]), "r"(b[1]));
}

// ---------------- pipelined fp16 projection GEMM (64x64 tile, B [N,K] row-major) ----------------
#define GEMM_SMEM ((2*64*18 + 2*16*72) * 4)
template<typename OutT>
__device__ __forceinline__ void gemm_body(
    const float* __restrict__ A, const float* __restrict__ B,
    OutT* __restrict__ C, const float* __restrict__ bias,
    int M, int N, int K, int lda, int ldb, int ldc, float alpha)
{
    extern __shared__ uint32_t gsm[];
    uint32_t (*As)[64][18] = (uint32_t(*)[64][18])gsm;
    uint32_t (*Bs)[16][72] = (uint32_t(*)[16][72])(gsm + 2*64*18);
    int tid = threadIdx.x;
    int warp = tid >> 5, lane = tid & 31;
    int g = lane >> 2, tg = lane & 3;
    int wm0 = (warp >> 1) * 16, wn0 = (warp & 1) * 32;
    int m0 = blockIdx.y * 64, n0 = blockIdx.x * 64;
    float acc[4][4] = {};

    int arow = tid >> 3, ac4 = (tid & 7) * 4, ac2 = (tid & 7) * 2;

    float4 aR[2], bR[2];
    auto loadA = [&](int k0) {
        #pragma unroll
        for (int i = 0; i < 2; i++) {
            int row = arow + i * 32;
            int gm = m0 + row, gk = k0 + ac4;
            aR[i] = (gm < M) ? *(const float4*)(A + (size_t)gm * lda + gk)
                             : make_float4(0.f, 0.f, 0.f, 0.f);
        }
    };
    auto loadB = [&](int k0) {
        #pragma unroll
        for (int i = 0; i < 2; i++) {
            int n = arow + i * 32;
            int gn = n0 + n, gk = k0 + ac4;
            bR[i] = (gn < N) ? *(const float4*)(B + (size_t)gn * ldb + gk)
                             : make_float4(0.f, 0.f, 0.f, 0.f);
        }
    };
    auto stage = [&](int buf) {
        #pragma unroll
        for (int i = 0; i < 2; i++) {
            int row = arow + i * 32;
            As[buf][row][ac2+0] = f22h(aR[i].x, aR[i].y);
            As[buf][row][ac2+1] = f22h(aR[i].z, aR[i].w);
        }
        #pragma unroll
        for (int i = 0; i < 2; i++) {
            int n = arow + i * 32;
            Bs[buf][ac2+0][n] = f22h(bR[i].x, bR[i].y);
            Bs[buf][ac2+1][n] = f22h(bR[i].z, bR[i].w);
        }
    };

    loadA(0); loadB(0);
    int nk = K >> 5;
    int buf = 0;
    for (int kt = 0; kt < nk; kt++) {
        stage(buf);
        __syncthreads();
        if (kt + 1 < nk) { loadA((kt + 1) * 32); loadB((kt + 1) * 32); }
        #pragma unroll
        for (int ko = 0; ko < 2; ko++) {
            int koff = ko * 8;
            uint32_t a[4], bfr[4][2];
            a[0] = As[buf][wm0 + g][koff + tg];
            a[1] = As[buf][wm0 + g + 8][koff + tg];
            a[2] = As[buf][wm0 + g][koff + tg + 4];
            a[3] = As[buf][wm0 + g + 8][koff + tg + 4];
            #pragma unroll
            for (int ni = 0; ni < 4; ni++) {
                int cn = wn0 + ni * 8 + g;
                bfr[ni][0] = Bs[buf][koff + tg][cn];
                bfr[ni][1] = Bs[buf][koff + tg + 4][cn];
            }
            #pragma unroll
            for (int ni = 0; ni < 4; ni++)
                mma16(acc[ni], a, bfr[ni]);
        }
        buf ^= 1;
    }

    #pragma unroll
    for (int ni = 0; ni < 4; ni++) {
        int r0 = m0 + wm0 + g;
        int cc0 = n0 + wn0 + ni * 8 + tg * 2;
        #pragma unroll
        for (int e = 0; e < 4; e++) {
            int r = r0 + (e >> 1) * 8;
            int cn = cc0 + (e & 1);
            if (r < M && cn < N) {
                float val = acc[ni][e];
                if (bias) val += bias[cn];
                val *= alpha;
                C[(size_t)r * ldc + cn] = (OutT)val;
            }
        }
    }
}

__global__ void gemm_proj(const float* __restrict__ A, const float* __restrict__ B,
                          float* __restrict__ C, const float* __restrict__ bias) {
    gemm_body<float>(A, B, C, bias, BB * QQ, CC, CC, CC, CC, CC, 1.f);
}

__global__ void gemm_qkv(const float* __restrict__ qry, const float* __restrict__ sampled,
                         const float* __restrict__ Wq, const float* __restrict__ Wk,
                         const float* __restrict__ Wv,
                         const float* __restrict__ bq, const float* __restrict__ bk,
                         const float* __restrict__ bv,
                         __half* __restrict__ qp, __half* __restrict__ kp, __half* __restrict__ vp) {
    int z = blockIdx.z;
    const float* A = (z == 0) ? qry : sampled;
    const float* B = (z == 0) ? Wq : ((z == 1) ? Wk : Wv);
    const float* bi = (z == 0) ? bq : ((z == 1) ? bk : bv);
    __half* C = (z == 0) ? qp : ((z == 1) ? kp : vp);
    float alpha = (z == 0) ? ATT_SCALE : 1.f;   // scores scale folded into q projection
    gemm_body<__half>(A, B, C, bi, BB * QQ, CC, CC, CC, CC, CC, alpha);
}

// ---------------- fused flash attention v4 (fp16 inputs, fp16 m16n8k16) ----------------
#define FLASH_SMEM ((128*18 + 2*16*68 + 2*32*36 + 128*34) * 4)
#define NIT ((QQ + 63) / 64)

__global__ void flash_kernel(const __half* __restrict__ qp, const __half* __restrict__ kp,
                             const __half* __restrict__ vp, float* __restrict__ attno) {
    extern __shared__ uint32_t fsm[];
    uint32_t (*Qs)[18]     = (uint32_t(*)[18])fsm;
    uint32_t (*Ks)[16][68] = (uint32_t(*)[16][68])(fsm + 128*18);
    uint32_t (*Vs)[32][36] = (uint32_t(*)[32][36])(fsm + 128*18 + 2*16*68);
    uint32_t (*Ps)[34]     = (uint32_t(*)[34])(fsm + 128*18 + 2*16*68 + 2*32*36);

    int z = blockIdx.y;
    int b = z / NH, h = z % NH;
    int q0 = blockIdx.x * 128;
    int tid = threadIdx.x;
    int warp = tid >> 5, lane = tid & 31;
    int g = lane >> 2, tg = lane & 3;
    int wr0 = warp * 16;

    const __half* qbase = qp + (size_t)b * QQ * CC + h * HD;
    const __half* kbase = kp + (size_t)b * QQ * CC + h * HD;
    const __half* vbase = vp + (size_t)b * QQ * CC + h * HD;

    // stage Q: direct half word copies (scale already folded in projection)
    #pragma unroll
    for (int i = 0; i < 4; i++) {
        int lin = tid + i * 256;
        int row = lin >> 3, ch2 = (lin & 7) * 2, c4 = (lin & 7) * 4;
        uint2 raw = make_uint2(0u, 0u);
        if (q0 + row < QQ) raw = *(const uint2*)(qbase + (size_t)(q0 + row) * CC + c4);
        Qs[row][ch2]     = raw.x;
        Qs[row][ch2 + 1] = raw.y;
    }

    int krow = tid >> 3, kch2 = (tid & 7) * 2, kc4 = (tid & 7) * 4;
    uint2 kr[2], va, vb;
    auto loadKV = [&](int k0) {
        #pragma unroll
        for (int j = 0; j < 2; j++) {
            int gk = k0 + krow + j * 32;
            kr[j] = (gk < QQ) ? *(const uint2*)(kbase + (size_t)gk * CC + kc4)
                              : make_uint2(0u, 0u);
        }
        int gva = k0 + 2 * krow, gvb = gva + 1;
        va = (gva < QQ) ? *(const uint2*)(vbase + (size_t)gva * CC + kc4) : make_uint2(0u, 0u);
        vb = (gvb < QQ) ? *(const uint2*)(vbase + (size_t)gvb * CC + kc4) : make_uint2(0u, 0u);
    };
    auto stageKV = [&](int buf) {
        #pragma unroll
        for (int j = 0; j < 2; j++) {
            int key = krow + j * 32;
            Ks[buf][kch2][key]     = kr[j].x;
            Ks[buf][kch2 + 1][key] = kr[j].y;
        }
        // pack (keyA, keyB) per channel via byte_perm
        Vs[buf][krow][kc4 + 0] = __byte_perm(va.x, vb.x, 0x5410);
        Vs[buf][krow][kc4 + 1] = __byte_perm(va.x, vb.x, 0x7632);
        Vs[buf][krow][kc4 + 2] = __byte_perm(va.y, vb.y, 0x5410);
        Vs[buf][krow][kc4 + 3] = __byte_perm(va.y, vb.y, 0x7632);
    };

    float m0r = -1e30f, m1r = -1e30f;
    float l0 = 0.f, l1 = 0.f;
    float oacc[4][4] = {};

    loadKV(0);
    int buf = 0;
    for (int it = 0; it < NIT; it++) {
        stageKV(buf);
        __syncthreads();
        if (it + 1 < NIT) loadKV((it + 1) * 64);

        float sacc[8][4] = {};
        #pragma unroll
        for (int ko = 0; ko < 2; ko++) {
            int koff = ko * 8;
            uint32_t a[4];
            a[0] = Qs[wr0 + g][koff + tg];
            a[1] = Qs[wr0 + g + 8][koff + tg];
            a[2] = Qs[wr0 + g][koff + tg + 4];
            a[3] = Qs[wr0 + g + 8][koff + tg + 4];
            #pragma unroll
            for (int ni = 0; ni < 8; ni++) {
                uint32_t bf[2];
                int cn = ni * 8 + g;
                bf[0] = Ks[buf][koff + tg][cn];
                bf[1] = Ks[buf][koff + tg + 4][cn];
                mma16(sacc[ni], a, bf);
            }
        }

        int cbase = it * 64;
        float r0 = -1e30f, r1 = -1e30f;
        #pragma unroll
        for (int ni = 0; ni < 8; ni++) {
            #pragma unroll
            for (int e = 0; e < 4; e++) {
                int gk = cbase + ni * 8 + tg * 2 + (e & 1);
                float s = sacc[ni][e];
                if (gk >= QQ) s = -1e30f;
                sacc[ni][e] = s;
                if (e < 2) r0 = fmaxf(r0, s); else r1 = fmaxf(r1, s);
            }
        }
        r0 = fmaxf(r0, __shfl_xor_sync(0xffffffffu, r0, 1));
        r0 = fmaxf(r0, __shfl_xor_sync(0xffffffffu, r0, 2));
        r1 = fmaxf(r1, __shfl_xor_sync(0xffffffffu, r1, 1));
        r1 = fmaxf(r1, __shfl_xor_sync(0xffffffffu, r1, 2));

        float nm0 = fmaxf(m0r, r0), nm1 = fmaxf(m1r, r1);
        float sc0 = __expf(m0r - nm0), sc1 = __expf(m1r - nm1);
        m0r = nm0; m1r = nm1;

        float s0 = 0.f, s1 = 0.f;
        #pragma unroll
        for (int ni = 0; ni < 8; ni++) {
            float p0 = __expf(sacc[ni][0] - m0r);
            float p1 = __expf(sacc[ni][1] - m0r);
            float p2 = __expf(sacc[ni][2] - m1r);
            float p3 = __expf(sacc[ni][3] - m1r);
            Ps[wr0 + g][ni * 4 + tg]     = f22h(p0, p1);
            Ps[wr0 + g + 8][ni * 4 + tg] = f22h(p2, p3);
            s0 += p0 + p1;
            s1 += p2 + p3;
        }
        s0 += __shfl_xor_sync(0xffffffffu, s0, 1);
        s0 += __shfl_xor_sync(0xffffffffu, s0, 2);
        s1 += __shfl_xor_sync(0xffffffffu, s1, 1);
        s1 += __shfl_xor_sync(0xffffffffu, s1, 2);
        l0 = l0 * sc0 + s0;
        l1 = l1 * sc1 + s1;

        #pragma unroll
        for (int ni = 0; ni < 4; ni++) {
            oacc[ni][0] *= sc0; oacc[ni][1] *= sc0;
            oacc[ni][2] *= sc1; oacc[ni][3] *= sc1;
        }
        __syncwarp();

        #pragma unroll
        for (int kk2 = 0; kk2 < 32; kk2 += 8) {
            uint32_t a[4];
            a[0] = Ps[wr0 + g][kk2 + tg];
            a[1] = Ps[wr0 + g + 8][kk2 + tg];
            a[2] = Ps[wr0 + g][kk2 + tg + 4];
            a[3] = Ps[wr0 + g + 8][kk2 + tg + 4];
            #pragma unroll
            for (int ni = 0; ni < 4; ni++) {
                uint32_t bf[2];
                int cn = ni * 8 + g;
                bf[0] = Vs[buf][kk2 + tg][cn];
                bf[1] = Vs[buf][kk2 + tg + 4][cn];
                mma16(oacc[ni], a, bf);
            }
        }
        buf ^= 1;
    }

    float li0 = 1.f / l0, li1 = 1.f / l1;
    #pragma unroll
    for (int ni = 0; ni < 4; ni++) {
        #pragma unroll
        for (int e = 0; e < 4; e++) {
            int row = wr0 + g + ((e >> 1) << 3);
            int col = ni * 8 + tg * 2 + (e & 1);
            int q = q0 + row;
            if (q < QQ)
                attno[((size_t)b * QQ + q) * CC + h * HD + col] =
                    oacc[ni][e] * ((e < 2) ? li0 : li1);
        }
    }
}

// ---------------- host launcher ----------------
extern "C" void kernel_launch(void* const* d_in, const int* in_sizes, int n_in,
                              void* d_out, int out_size) {
    const float* f0   = (const float*)d_in[0];
    const float* f1   = (const float*)d_in[1];
    const float* refs = (const float*)d_in[2];
    const float* intr = (const float*)d_in[3];
    const float* extr = (const float*)d_in[4];
    const float* qry  = (const float*)d_in[5];
    const float* Wq   = (const float*)d_in[6];
    const float* bq   = (const float*)d_in[7];
    const float* Wk   = (const float*)d_in[8];
    const float* bk   = (const float*)d_in[9];
    const float* Wv   = (const float*)d_in[10];
    const float* bv   = (const float*)d_in[11];
    const float* Wo   = (const float*)d_in[12];
    const float* bo   = (const float*)d_in[13];
    float* out = (float*)d_out;

    __half *qp, *kp, *vp;
    float *sampled, *attno;
    cudaGetSymbolAddress((void**)&sampled, g_sampled);
    cudaGetSymbolAddress((void**)&qp, g_qp);
    cudaGetSymbolAddress((void**)&kp, g_kp);
    cudaGetSymbolAddress((void**)&vp, g_vp);
    cudaGetSymbolAddress((void**)&attno, g_attno);

    cudaFuncSetAttribute(gemm_qkv, cudaFuncAttributeMaxDynamicSharedMemorySize, GEMM_SMEM);
    cudaFuncSetAttribute(gemm_proj, cudaFuncAttributeMaxDynamicSharedMemorySize, GEMM_SMEM);
    cudaFuncSetAttribute(flash_kernel, cudaFuncAttributeMaxDynamicSharedMemorySize, FLASH_SMEM);

    const int NTILES = (PT0 * 4 + PT1 * 4) * BB * VV;
    transpose_kernel<<<NTILES, 256>>>(f0, f1);
    sample_kernel<<<(BB * QQ) / 4, dim3(64, 4)>>>(refs, intr, extr);

    const int M = BB * QQ;  // 1800
    gemm_qkv<<<dim3(CC / 64, (M + 63) / 64, 3), 256, GEMM_SMEM>>>(
        qry, sampled, Wq, Wk, Wv, bq, bk, bv, qp, kp, vp);

    flash_kernel<<<dim3((QQ + 127) / 128, BB * NH), 256, FLASH_SMEM>>>(qp, kp, vp, attno);

    gemm_proj<<<dim3(CC / 64, (M + 63) / 64), 256, GEMM_SMEM>>>(attno, Wo, out, bo);
}